// round 1
// baseline (speedup 1.0000x reference)
#include <cuda_runtime.h>
#include <cuda_bf16.h>
#include <math.h>

#define NTOK 4096          // B*S = 2*2048
#define SEQ  2048
#define DIM  1024
#define NH   16
#define HD   64
#define DFF  4096

// ---------------- scratch (device globals; no allocs allowed) ----------------
__device__ float g_xn[NTOK * DIM];
__device__ float g_q[NTOK * DIM];
__device__ float g_k[NTOK * DIM];
__device__ float g_v[NTOK * DIM];
__device__ float g_attn[NTOK * DIM];
__device__ float g_h[NTOK * DIM];
__device__ float g_ff1[NTOK * DFF];

// ---------------- LayerNorm (optionally fused residual add) ----------------
__global__ __launch_bounds__(256)
void ln_kernel(const float* __restrict__ x, const float* __restrict__ res,
               const float* __restrict__ gamma, const float* __restrict__ beta,
               float* __restrict__ out)
{
    int row = blockIdx.x;
    int t = threadIdx.x;
    const float4* xr = (const float4*)(x + (size_t)row * DIM);
    float4 v = xr[t];
    if (res) {
        const float4* rr = (const float4*)(res + (size_t)row * DIM);
        float4 r = rr[t];
        v.x += r.x; v.y += r.y; v.z += r.z; v.w += r.w;
    }
    float s  = v.x + v.y + v.z + v.w;
    float s2 = v.x*v.x + v.y*v.y + v.z*v.z + v.w*v.w;
    #pragma unroll
    for (int o = 16; o > 0; o >>= 1) {
        s  += __shfl_down_sync(0xffffffffu, s,  o);
        s2 += __shfl_down_sync(0xffffffffu, s2, o);
    }
    __shared__ float ss[8], ss2[8];
    __shared__ float mean_s, rstd_s;
    if ((t & 31) == 0) { ss[t >> 5] = s; ss2[t >> 5] = s2; }
    __syncthreads();
    if (t == 0) {
        float a = 0.f, b = 0.f;
        #pragma unroll
        for (int i = 0; i < 8; i++) { a += ss[i]; b += ss2[i]; }
        float mean = a * (1.0f / DIM);
        float var  = b * (1.0f / DIM) - mean * mean;
        mean_s = mean;
        rstd_s = rsqrtf(var + 1e-5f);
    }
    __syncthreads();
    float mean = mean_s, rstd = rstd_s;
    float4 g = ((const float4*)gamma)[t];
    float4 bb = ((const float4*)beta)[t];
    float4 o4;
    o4.x = (v.x - mean) * rstd * g.x + bb.x;
    o4.y = (v.y - mean) * rstd * g.y + bb.y;
    o4.z = (v.z - mean) * rstd * g.z + bb.z;
    o4.w = (v.w - mean) * rstd * g.w + bb.w;
    ((float4*)(out + (size_t)row * DIM))[t] = o4;
}

// ---------------- SGEMM: C[M,N] = A[M,K] @ W[N,K]^T + bias, epilogues ----------------
// EPI: 0 = bias, 1 = bias+silu, 2 = bias + residual(res[m*N+n])
template<int EPI>
__global__ __launch_bounds__(256)
void gemm_tn(const float* __restrict__ A, const float* __restrict__ W,
             const float* __restrict__ bias, const float* __restrict__ res,
             float* __restrict__ C, int M, int N, int K)
{
    __shared__ float As[8][128];
    __shared__ float Bs[8][128];
    int tid = threadIdx.x;
    int bm = blockIdx.y * 128, bn = blockIdx.x * 128;
    int tx = tid & 15, ty = tid >> 4;

    float acc[8][8];
    #pragma unroll
    for (int i = 0; i < 8; i++)
        #pragma unroll
        for (int j = 0; j < 8; j++) acc[i][j] = 0.f;

    int lrow = tid >> 1;
    int lk = (tid & 1) * 4;
    const float* Aptr = A + (size_t)(bm + lrow) * K + lk;
    const float* Wptr = W + (size_t)(bn + lrow) * K + lk;

    for (int k0 = 0; k0 < K; k0 += 8) {
        float4 av = *(const float4*)(Aptr + k0);
        float4 wv = *(const float4*)(Wptr + k0);
        As[lk+0][lrow] = av.x; As[lk+1][lrow] = av.y;
        As[lk+2][lrow] = av.z; As[lk+3][lrow] = av.w;
        Bs[lk+0][lrow] = wv.x; Bs[lk+1][lrow] = wv.y;
        Bs[lk+2][lrow] = wv.z; Bs[lk+3][lrow] = wv.w;
        __syncthreads();
        #pragma unroll
        for (int kk = 0; kk < 8; kk++) {
            float a[8], b[8];
            *(float4*)(a)     = *(const float4*)&As[kk][ty*8];
            *(float4*)(a + 4) = *(const float4*)&As[kk][ty*8 + 4];
            *(float4*)(b)     = *(const float4*)&Bs[kk][tx*8];
            *(float4*)(b + 4) = *(const float4*)&Bs[kk][tx*8 + 4];
            #pragma unroll
            for (int i = 0; i < 8; i++)
                #pragma unroll
                for (int j = 0; j < 8; j++)
                    acc[i][j] += a[i] * b[j];
        }
        __syncthreads();
    }

    #pragma unroll
    for (int i = 0; i < 8; i++) {
        int m = bm + ty*8 + i;
        #pragma unroll
        for (int j = 0; j < 8; j++) {
            int n = bn + tx*8 + j;
            float c = acc[i][j] + bias[n];
            if (EPI == 1) {
                c = c / (1.0f + expf(-c));  // silu
            } else if (EPI == 2) {
                c += res[(size_t)m * N + n];
            }
            C[(size_t)m * N + n] = c;
        }
    }
}

// ---------------- Flash attention (fp32, non-causal) ----------------
// grid: (S/64, H, B); 256 threads; 4 threads per query row, each owns 16 dims.
__global__ __launch_bounds__(256)
void attn_kernel(const float* __restrict__ q, const float* __restrict__ k,
                 const float* __restrict__ v, float* __restrict__ out)
{
    __shared__ float sK[64][68];
    __shared__ float sV[64][68];

    int b = blockIdx.z, h = blockIdx.y;
    int q0 = blockIdx.x * 64;
    int tid = threadIdx.x;
    int qi = tid >> 2;
    int lane4 = tid & 3;

    const float* qrow = q + ((size_t)(b * SEQ + q0 + qi)) * DIM + h * HD + lane4 * 16;
    float qreg[16];
    #pragma unroll
    for (int i = 0; i < 4; i++)
        *(float4*)(qreg + 4*i) = *(const float4*)(qrow + 4*i);

    float acc[16];
    #pragma unroll
    for (int i = 0; i < 16; i++) acc[i] = 0.f;
    float m = -INFINITY, l = 0.f;

    int r = tid >> 2, c4 = tid & 3;
    const float* kbase = k + ((size_t)b * SEQ) * DIM + h * HD;
    const float* vbase = v + ((size_t)b * SEQ) * DIM + h * HD;

    for (int kt = 0; kt < SEQ / 64; kt++) {
        const float* krow = kbase + (size_t)(kt * 64 + r) * DIM;
        const float* vrow = vbase + (size_t)(kt * 64 + r) * DIM;
        #pragma unroll
        for (int i = 0; i < 4; i++) {
            int f4 = c4 + 4 * i;
            *(float4*)&sK[r][f4 * 4] = *(const float4*)(krow + f4 * 4);
            *(float4*)&sV[r][f4 * 4] = *(const float4*)(vrow + f4 * 4);
        }
        __syncthreads();

        #pragma unroll 4
        for (int kk = 0; kk < 64; kk++) {
            const float* kr = &sK[kk][lane4 * 16];
            float s = 0.f;
            #pragma unroll
            for (int i = 0; i < 4; i++) {
                float4 kv = *(const float4*)(kr + 4*i);
                s += qreg[4*i+0]*kv.x + qreg[4*i+1]*kv.y
                   + qreg[4*i+2]*kv.z + qreg[4*i+3]*kv.w;
            }
            s += __shfl_xor_sync(0xffffffffu, s, 1);
            s += __shfl_xor_sync(0xffffffffu, s, 2);
            s *= 0.125f;  // 1/sqrt(64)

            if (s > m) {
                float corr = __expf(m - s);
                m = s;
                l *= corr;
                #pragma unroll
                for (int i = 0; i < 16; i++) acc[i] *= corr;
            }
            float p = __expf(s - m);
            l += p;
            const float* vr = &sV[kk][lane4 * 16];
            #pragma unroll
            for (int i = 0; i < 4; i++) {
                float4 vv = *(const float4*)(vr + 4*i);
                acc[4*i+0] += p * vv.x;
                acc[4*i+1] += p * vv.y;
                acc[4*i+2] += p * vv.z;
                acc[4*i+3] += p * vv.w;
            }
        }
        __syncthreads();
    }

    float inv_l = 1.0f / l;
    float* orow = out + ((size_t)(b * SEQ + q0 + qi)) * DIM + h * HD + lane4 * 16;
    #pragma unroll
    for (int i = 0; i < 4; i++) {
        float4 o4;
        o4.x = acc[4*i+0] * inv_l;
        o4.y = acc[4*i+1] * inv_l;
        o4.z = acc[4*i+2] * inv_l;
        o4.w = acc[4*i+3] * inv_l;
        *(float4*)(orow + 4*i) = o4;
    }
}

// ---------------- launch ----------------
extern "C" void kernel_launch(void* const* d_in, const int* in_sizes, int n_in,
                              void* d_out, int out_size)
{
    (void)in_sizes; (void)n_in; (void)out_size;
    const float* x   = (const float*)d_in[0];
    const float* Wq  = (const float*)d_in[1];
    const float* bq  = (const float*)d_in[2];
    const float* Wk  = (const float*)d_in[3];
    const float* bk  = (const float*)d_in[4];
    const float* Wv  = (const float*)d_in[5];
    const float* bv  = (const float*)d_in[6];
    const float* g1  = (const float*)d_in[7];
    const float* b1  = (const float*)d_in[8];
    const float* g2  = (const float*)d_in[9];
    const float* b2  = (const float*)d_in[10];
    const float* W1  = (const float*)d_in[11];
    const float* bf1 = (const float*)d_in[12];
    const float* W2  = (const float*)d_in[13];
    const float* bf2 = (const float*)d_in[14];

    float *xn, *q, *k, *v, *attn, *h, *ff1;
    cudaGetSymbolAddress((void**)&xn,   g_xn);
    cudaGetSymbolAddress((void**)&q,    g_q);
    cudaGetSymbolAddress((void**)&k,    g_k);
    cudaGetSymbolAddress((void**)&v,    g_v);
    cudaGetSymbolAddress((void**)&attn, g_attn);
    cudaGetSymbolAddress((void**)&h,    g_h);
    cudaGetSymbolAddress((void**)&ff1,  g_ff1);

    // xn = LN(x)
    ln_kernel<<<NTOK, 256>>>(x, nullptr, g1, b1, xn);

    // q,k,v projections: [4096,1024] = xn @ W^T + b
    dim3 gQKV(DIM / 128, NTOK / 128);
    gemm_tn<0><<<gQKV, 256>>>(xn, Wq, bq, nullptr, q, NTOK, DIM, DIM);
    gemm_tn<0><<<gQKV, 256>>>(xn, Wk, bk, nullptr, k, NTOK, DIM, DIM);
    gemm_tn<0><<<gQKV, 256>>>(xn, Wv, bv, nullptr, v, NTOK, DIM, DIM);

    // attention (flash, fp32)
    attn_kernel<<<dim3(SEQ / 64, NH, 2), 256>>>(q, k, v, attn);

    // h = LN(attn + xn)
    ln_kernel<<<NTOK, 256>>>(attn, xn, g2, b2, h);

    // ff1 = silu(h @ W1^T + bf1): [4096, 4096]
    dim3 gF1(DFF / 128, NTOK / 128);
    gemm_tn<1><<<gF1, 256>>>(h, W1, bf1, nullptr, ff1, NTOK, DFF, DIM);

    // out = ff1 @ W2^T + bf2 + xn : [4096, 1024]
    gemm_tn<2><<<gQKV, 256>>>(ff1, W2, bf2, xn, (float*)d_out, NTOK, DIM, DFF);
}

// round 8
// speedup vs baseline: 4.9783x; 4.9783x over previous
#include <cuda_runtime.h>
#include <cuda_bf16.h>
#include <math.h>
#include <stdint.h>

#define NTOK 4096          // B*S
#define SEQ  2048
#define DIM  1024
#define NH   16
#define HD   64
#define DFF  4096

// ---------------- scratch (device globals; no allocs allowed) ----------------
__device__ float g_xn[NTOK * DIM];
__device__ float g_attn[NTOK * DIM];

__device__ __nv_bfloat16 g_xn_hi[NTOK * DIM],  g_xn_lo[NTOK * DIM];
__device__ __nv_bfloat16 g_q_hi[NTOK * DIM],   g_q_lo[NTOK * DIM];
__device__ __nv_bfloat16 g_k_hi[NTOK * DIM],   g_k_lo[NTOK * DIM];
__device__ __nv_bfloat16 g_v_hi[NTOK * DIM],   g_v_lo[NTOK * DIM];
__device__ __nv_bfloat16 g_h_hi[NTOK * DIM],   g_h_lo[NTOK * DIM];
__device__ __nv_bfloat16 g_ff1_hi[NTOK * DFF], g_ff1_lo[NTOK * DFF];
__device__ __nv_bfloat16 g_wq_hi[DIM * DIM],   g_wq_lo[DIM * DIM];
__device__ __nv_bfloat16 g_wk_hi[DIM * DIM],   g_wk_lo[DIM * DIM];
__device__ __nv_bfloat16 g_wv_hi[DIM * DIM],   g_wv_lo[DIM * DIM];
__device__ __nv_bfloat16 g_w1_hi[DFF * DIM],   g_w1_lo[DFF * DIM];
__device__ __nv_bfloat16 g_w2_hi[DIM * DFF],   g_w2_lo[DIM * DFF];

// ---------------- PTX helpers (ALL family-portable: sm_80-era ISA) ----------------
__device__ __forceinline__ uint32_t smem_u32(const void* p) {
    uint32_t a;
    asm("{ .reg .u64 t; cvta.to.shared.u64 t, %1; cvt.u32.u64 %0, t; }" : "=r"(a) : "l"(p));
    return a;
}
__device__ __forceinline__ void cp16(uint32_t dst, const void* src) {
    asm volatile("cp.async.cg.shared.global [%0], [%1], 16;" :: "r"(dst), "l"(src) : "memory");
}
__device__ __forceinline__ void cp_commit() {
    asm volatile("cp.async.commit_group;" ::: "memory");
}
template<int N> __device__ __forceinline__ void cp_wait() {
    asm volatile("cp.async.wait_group %0;" :: "n"(N) : "memory");
}
__device__ __forceinline__ void ldm_x4(uint32_t* r, uint32_t addr) {
    asm volatile("ldmatrix.sync.aligned.m8n8.x4.shared.b16 {%0,%1,%2,%3}, [%4];"
        : "=r"(r[0]), "=r"(r[1]), "=r"(r[2]), "=r"(r[3]) : "r"(addr));
}
__device__ __forceinline__ void ldm_x4t(uint32_t* r, uint32_t addr) {
    asm volatile("ldmatrix.sync.aligned.m8n8.x4.trans.shared.b16 {%0,%1,%2,%3}, [%4];"
        : "=r"(r[0]), "=r"(r[1]), "=r"(r[2]), "=r"(r[3]) : "r"(addr));
}
__device__ __forceinline__ void mma_bf16(float* d, const uint32_t* a, const uint32_t* b) {
    asm volatile(
        "mma.sync.aligned.m16n8k16.row.col.f32.bf16.bf16.f32 "
        "{%0,%1,%2,%3}, {%4,%5,%6,%7}, {%8,%9}, {%0,%1,%2,%3};"
        : "+f"(d[0]), "+f"(d[1]), "+f"(d[2]), "+f"(d[3])
        : "r"(a[0]), "r"(a[1]), "r"(a[2]), "r"(a[3]), "r"(b[0]), "r"(b[1]));
}
__device__ __forceinline__ uint32_t pk(float lo, float hi) {
    __nv_bfloat162 t = __floats2bfloat162_rn(lo, hi);
    return *(uint32_t*)&t;
}
__device__ __forceinline__ void split2(float v0, float v1, uint32_t& h, uint32_t& l) {
    __nv_bfloat16 h0 = __float2bfloat16(v0), h1 = __float2bfloat16(v1);
    h = pk(__bfloat162float(h0), __bfloat162float(h1));
    l = pk(v0 - __bfloat162float(h0), v1 - __bfloat162float(h1));
}
// 32-col bf16 tile (64B rows, 4x16B segs): conflict-free swizzle
__device__ __forceinline__ uint32_t off32(int r, int s) {
    return (uint32_t)(r * 64 + ((s ^ ((r >> 1) & 3)) << 4));
}
// 64-col bf16 tile (128B rows, 8x16B segs)
__device__ __forceinline__ uint32_t off64(int r, int s) {
    return (uint32_t)(r * 128 + ((s ^ (r & 7)) << 4));
}

// ---------------- split fp32 -> (hi, lo) bf16 ----------------
__global__ __launch_bounds__(256)
void split_kernel(const float* __restrict__ in, __nv_bfloat16* __restrict__ hi,
                  __nv_bfloat16* __restrict__ lo, int n4)
{
    int i = blockIdx.x * blockDim.x + threadIdx.x;
    if (i >= n4) return;
    float4 v = ((const float4*)in)[i];
    uint2 uh, ul;
    split2(v.x, v.y, uh.x, ul.x);
    split2(v.z, v.w, uh.y, ul.y);
    *(uint2*)(hi + (size_t)i * 4) = uh;
    *(uint2*)(lo + (size_t)i * 4) = ul;
}

// ---------------- LayerNorm (optional residual; fp32 out + bf16 splits) ----------------
__global__ __launch_bounds__(256)
void ln_kernel(const float* __restrict__ x, const float* __restrict__ res,
               const float* __restrict__ gamma, const float* __restrict__ beta,
               float* __restrict__ out, __nv_bfloat16* __restrict__ ohi,
               __nv_bfloat16* __restrict__ olo)
{
    int row = blockIdx.x;
    int t = threadIdx.x;
    const float4* xr = (const float4*)(x + (size_t)row * DIM);
    float4 v = xr[t];
    if (res) {
        const float4* rr = (const float4*)(res + (size_t)row * DIM);
        float4 r = rr[t];
        v.x += r.x; v.y += r.y; v.z += r.z; v.w += r.w;
    }
    float s  = v.x + v.y + v.z + v.w;
    float s2 = v.x*v.x + v.y*v.y + v.z*v.z + v.w*v.w;
    #pragma unroll
    for (int o = 16; o > 0; o >>= 1) {
        s  += __shfl_down_sync(0xffffffffu, s,  o);
        s2 += __shfl_down_sync(0xffffffffu, s2, o);
    }
    __shared__ float ss[8], ss2[8];
    __shared__ float mean_s, rstd_s;
    if ((t & 31) == 0) { ss[t >> 5] = s; ss2[t >> 5] = s2; }
    __syncthreads();
    if (t == 0) {
        float a = 0.f, b = 0.f;
        #pragma unroll
        for (int i = 0; i < 8; i++) { a += ss[i]; b += ss2[i]; }
        float mean = a * (1.0f / DIM);
        float var  = b * (1.0f / DIM) - mean * mean;
        mean_s = mean;
        rstd_s = rsqrtf(var + 1e-5f);
    }
    __syncthreads();
    float mean = mean_s, rstd = rstd_s;
    float4 g = ((const float4*)gamma)[t];
    float4 bb = ((const float4*)beta)[t];
    float4 o4;
    o4.x = (v.x - mean) * rstd * g.x + bb.x;
    o4.y = (v.y - mean) * rstd * g.y + bb.y;
    o4.z = (v.z - mean) * rstd * g.z + bb.z;
    o4.w = (v.w - mean) * rstd * g.w + bb.w;
    size_t idx = (size_t)row * DIM + t * 4;
    if (out) *(float4*)(out + idx) = o4;
    if (ohi) {
        uint2 uh, ul;
        split2(o4.x, o4.y, uh.x, ul.x);
        split2(o4.z, o4.w, uh.y, ul.y);
        *(uint2*)(ohi + idx) = uh;
        *(uint2*)(olo + idx) = ul;
    }
}

// ---------------- mma.sync split-bf16 GEMM: C[M,N] = A[M,K] @ W[N,K]^T ----------------
// CTA 128x128, 8 warps (warp tile 32x64), K-chunk 32, cp.async double buffer.
// EPI: 1 = bias+silu -> bf16 hi/lo ; 2 = bias+res -> fp32 ; 3 = (bias)*scale -> bf16 hi/lo
static constexpr int G_STAGE = 32768;   // Ah(8K) Al(8K) Bh(8K) Bl(8K)
static constexpr int G_SMEM = 2 * G_STAGE;

template<int EPI>
__global__ void __launch_bounds__(256, 1)
gemm_mma(const __nv_bfloat16* __restrict__ Ah, const __nv_bfloat16* __restrict__ Al,
         const __nv_bfloat16* __restrict__ Bh, const __nv_bfloat16* __restrict__ Bl,
         const float* __restrict__ bias, const float* __restrict__ res,
         float* __restrict__ C, __nv_bfloat16* __restrict__ Chi,
         __nv_bfloat16* __restrict__ Clo, int N, int K, float scale)
{
    extern __shared__ char sm[];
    const int tid = threadIdx.x;
    const int wid = tid >> 5, lane = tid & 31;
    const int bm = blockIdx.y * 128, bn = blockIdx.x * 128;
    const int wm = (wid & 3) * 32, wn = (wid >> 2) * 64;
    const uint32_t sb = smem_u32(sm);

    float acc[2][8][4];
    #pragma unroll
    for (int i = 0; i < 2; i++)
        #pragma unroll
        for (int j = 0; j < 8; j++)
            #pragma unroll
            for (int d = 0; d < 4; d++) acc[i][j][d] = 0.f;

    const int r_ld = tid >> 1;           // 0..127
    const int s_ld = (tid & 1) * 2;      // seg base 0 or 2
    const __nv_bfloat16* gA[2] = {Ah, Al};
    const __nv_bfloat16* gB[2] = {Bh, Bl};

    auto issue = [&](int c) {
        uint32_t st = sb + (uint32_t)(c & 1) * G_STAGE;
        int k0 = c * 32;
        #pragma unroll
        for (int t = 0; t < 2; t++) {
            const __nv_bfloat16* A = gA[t];
            const __nv_bfloat16* B = gB[t];
            uint32_t dA = st + t * 8192;
            uint32_t dB = st + 16384 + t * 8192;
            #pragma unroll
            for (int j = 0; j < 2; j++) {
                int s = s_ld + j;
                uint32_t o = off32(r_ld, s);
                cp16(dA + o, A + (size_t)(bm + r_ld) * K + k0 + s * 8);
                cp16(dB + o, B + (size_t)(bn + r_ld) * K + k0 + s * 8);
            }
        }
        cp_commit();
    };

    const int NC = K / 32;
    issue(0);
    issue(1);

    for (int c = 0; c < NC; c++) {
        if (c + 1 < NC) cp_wait<1>(); else cp_wait<0>();
        __syncthreads();
        uint32_t st = sb + (uint32_t)(c & 1) * G_STAGE;
        #pragma unroll
        for (int ks = 0; ks < 2; ks++) {
            uint32_t a_h[8], a_l[8];
            #pragma unroll
            for (int mt = 0; mt < 2; mt++) {
                int row = wm + mt * 16 + (lane & 7) + ((lane >> 3) & 1) * 8;
                int seg = ks * 2 + (lane >> 4);
                uint32_t oa = off32(row, seg);
                ldm_x4(a_h + mt * 4, st + oa);
                ldm_x4(a_l + mt * 4, st + 8192 + oa);
            }
            #pragma unroll
            for (int ntp = 0; ntp < 4; ntp++) {
                int row = wn + ntp * 16 + (lane & 7) + ((lane >> 4) & 1) * 8;
                int seg = ks * 2 + ((lane >> 3) & 1);
                uint32_t ob = off32(row, seg);
                uint32_t bh4[4], bl4[4];
                ldm_x4(bh4, st + 16384 + ob);
                ldm_x4(bl4, st + 24576 + ob);
                #pragma unroll
                for (int half = 0; half < 2; half++) {
                    int nt = ntp * 2 + half;
                    #pragma unroll
                    for (int mt = 0; mt < 2; mt++) {
                        mma_bf16(acc[mt][nt], a_h + mt * 4, bh4 + half * 2);
                        mma_bf16(acc[mt][nt], a_h + mt * 4, bl4 + half * 2);
                        mma_bf16(acc[mt][nt], a_l + mt * 4, bh4 + half * 2);
                    }
                }
            }
        }
        __syncthreads();
        if (c + 2 < NC) issue(c + 2);
    }

    // epilogue (direct reg->global)
    #pragma unroll
    for (int mt = 0; mt < 2; mt++) {
        int r0 = bm + wm + mt * 16 + (lane >> 2);
        #pragma unroll
        for (int nt = 0; nt < 8; nt++) {
            int col = bn + wn + nt * 8 + (lane & 3) * 2;
            float b0 = bias[col], b1 = bias[col + 1];
            float* a = acc[mt][nt];
            if (EPI == 3) {
                uint32_t h0, l0, h1, l1;
                split2((a[0] + b0) * scale, (a[1] + b1) * scale, h0, l0);
                split2((a[2] + b0) * scale, (a[3] + b1) * scale, h1, l1);
                *(uint32_t*)(Chi + (size_t)r0 * N + col) = h0;
                *(uint32_t*)(Clo + (size_t)r0 * N + col) = l0;
                *(uint32_t*)(Chi + (size_t)(r0 + 8) * N + col) = h1;
                *(uint32_t*)(Clo + (size_t)(r0 + 8) * N + col) = l1;
            } else if (EPI == 1) {
                float v0 = a[0] + b0, v1 = a[1] + b1, v2 = a[2] + b0, v3 = a[3] + b1;
                v0 = v0 / (1.f + __expf(-v0));
                v1 = v1 / (1.f + __expf(-v1));
                v2 = v2 / (1.f + __expf(-v2));
                v3 = v3 / (1.f + __expf(-v3));
                uint32_t h0, l0, h1, l1;
                split2(v0, v1, h0, l0);
                split2(v2, v3, h1, l1);
                *(uint32_t*)(Chi + (size_t)r0 * N + col) = h0;
                *(uint32_t*)(Clo + (size_t)r0 * N + col) = l0;
                *(uint32_t*)(Chi + (size_t)(r0 + 8) * N + col) = h1;
                *(uint32_t*)(Clo + (size_t)(r0 + 8) * N + col) = l1;
            } else {
                float2 p0, p1;
                float2 rr0 = *(const float2*)(res + (size_t)r0 * N + col);
                float2 rr1 = *(const float2*)(res + (size_t)(r0 + 8) * N + col);
                p0.x = a[0] + b0 + rr0.x; p0.y = a[1] + b1 + rr0.y;
                p1.x = a[2] + b0 + rr1.x; p1.y = a[3] + b1 + rr1.y;
                *(float2*)(C + (size_t)r0 * N + col) = p0;
                *(float2*)(C + (size_t)(r0 + 8) * N + col) = p1;
            }
        }
    }
}

// ---------------- Flash attention via mma.sync ----------------
// grid: (SEQ/128, NH, B); 256 thr (8 warps, 16 q-rows each). Q scaled by 1/8 upstream.
// smem: Qhi 16K @0, Qlo 16K @16384; KV stages @32768, stride 24576: Kh, Kl(+8192), Vh(+16384)
static constexpr int A_SMEM = 32768 + 2 * 24576;   // 81920

__global__ void __launch_bounds__(256, 1)
attn_mma(const __nv_bfloat16* __restrict__ qh, const __nv_bfloat16* __restrict__ ql,
         const __nv_bfloat16* __restrict__ kh, const __nv_bfloat16* __restrict__ kl,
         const __nv_bfloat16* __restrict__ vh, float* __restrict__ out)
{
    extern __shared__ char sm[];
    const int tid = threadIdx.x;
    const int wid = tid >> 5, lane = tid & 31;
    const int h = blockIdx.y, b = blockIdx.z;
    const int tok0 = b * SEQ + blockIdx.x * 128;
    const size_t qbase = (size_t)tok0 * DIM + h * HD;
    const size_t kvbase = (size_t)b * SEQ * DIM + h * HD;
    const uint32_t sb = smem_u32(sm);

    // issue Q (group 0)
    {
        int r = tid >> 1;
        #pragma unroll
        for (int j = 0; j < 4; j++) {
            int s = (tid & 1) * 4 + j;
            uint32_t o = off64(r, s);
            const size_t go = qbase + (size_t)r * DIM + s * 8;
            cp16(sb + o, qh + go);
            cp16(sb + 16384 + o, ql + go);
        }
        cp_commit();
    }
    auto issueKV = [&](int kb) {
        uint32_t st = sb + 32768 + (uint32_t)(kb & 1) * 24576;
        int r = tid >> 2;
        size_t rowoff = kvbase + (size_t)(kb * 64 + r) * DIM;
        #pragma unroll
        for (int j = 0; j < 2; j++) {
            int s = (tid & 3) * 2 + j;
            uint32_t o = off64(r, s);
            cp16(st + o, kh + rowoff + s * 8);
            cp16(st + 8192 + o, kl + rowoff + s * 8);
            cp16(st + 16384 + o, vh + rowoff + s * 8);
        }
        cp_commit();
    };
    issueKV(0);   // group 1
    issueKV(1);   // group 2

    cp_wait<1>(); // Q + KV0 done
    __syncthreads();

    // Q fragments (registers, reused all blocks)
    uint32_t qf[2][4][4];
    {
        int row = wid * 16 + (lane & 7) + ((lane >> 3) & 1) * 8;
        #pragma unroll
        for (int ks = 0; ks < 4; ks++) {
            int seg = ks * 2 + (lane >> 4);
            uint32_t o = off64(row, seg);
            ldm_x4(qf[0][ks], sb + o);
            ldm_x4(qf[1][ks], sb + 16384 + o);
        }
    }

    float o_acc[8][4];
    #pragma unroll
    for (int i = 0; i < 8; i++)
        #pragma unroll
        for (int d = 0; d < 4; d++) o_acc[i][d] = 0.f;
    float runA = -INFINITY, runB = -INFINITY, lA = 0.f, lB = 0.f;

    const int NKB = SEQ / 64;
    for (int kb = 0; kb < NKB; kb++) {
        uint32_t st = sb + 32768 + (uint32_t)(kb & 1) * 24576;
        // ---- scores S[16,64] ----
        float s[8][4];
        #pragma unroll
        for (int i = 0; i < 8; i++)
            #pragma unroll
            for (int d = 0; d < 4; d++) s[i][d] = 0.f;
        #pragma unroll
        for (int ks = 0; ks < 4; ks++) {
            #pragma unroll
            for (int ntp = 0; ntp < 4; ntp++) {
                int row = ntp * 16 + (lane & 7) + ((lane >> 4) & 1) * 8;
                int seg = ks * 2 + ((lane >> 3) & 1);
                uint32_t ob = off64(row, seg);
                uint32_t bh4[4], bl4[4];
                ldm_x4(bh4, st + ob);
                ldm_x4(bl4, st + 8192 + ob);
                #pragma unroll
                for (int half = 0; half < 2; half++) {
                    int nt = ntp * 2 + half;
                    mma_bf16(s[nt], qf[0][ks], bh4 + half * 2);
                    mma_bf16(s[nt], qf[1][ks], bh4 + half * 2);
                    mma_bf16(s[nt], qf[0][ks], bl4 + half * 2);
                }
            }
        }
        // ---- online softmax (rows: A = lane>>2, B = +8) ----
        float mA = -INFINITY, mB = -INFINITY;
        #pragma unroll
        for (int nt = 0; nt < 8; nt++) {
            mA = fmaxf(mA, fmaxf(s[nt][0], s[nt][1]));
            mB = fmaxf(mB, fmaxf(s[nt][2], s[nt][3]));
        }
        mA = fmaxf(mA, __shfl_xor_sync(0xffffffffu, mA, 1));
        mA = fmaxf(mA, __shfl_xor_sync(0xffffffffu, mA, 2));
        mB = fmaxf(mB, __shfl_xor_sync(0xffffffffu, mB, 1));
        mB = fmaxf(mB, __shfl_xor_sync(0xffffffffu, mB, 2));
        float nA = fmaxf(runA, mA), nB = fmaxf(runB, mB);
        float cA = __expf(runA - nA), cB = __expf(runB - nB);
        runA = nA; runB = nB;
        lA *= cA; lB *= cB;
        #pragma unroll
        for (int nt = 0; nt < 8; nt++) {
            o_acc[nt][0] *= cA; o_acc[nt][1] *= cA;
            o_acc[nt][2] *= cB; o_acc[nt][3] *= cB;
        }
        float sumA = 0.f, sumB = 0.f;
        #pragma unroll
        for (int nt = 0; nt < 8; nt++) {
            s[nt][0] = __expf(s[nt][0] - nA); sumA += s[nt][0];
            s[nt][1] = __expf(s[nt][1] - nA); sumA += s[nt][1];
            s[nt][2] = __expf(s[nt][2] - nB); sumB += s[nt][2];
            s[nt][3] = __expf(s[nt][3] - nB); sumB += s[nt][3];
        }
        lA += sumA; lB += sumB;
        // ---- P (bf16 A-frags, pure register repack) ----
        uint32_t pf[4][4];
        #pragma unroll
        for (int j = 0; j < 4; j++) {
            pf[j][0] = pk(s[2*j][0],   s[2*j][1]);
            pf[j][1] = pk(s[2*j][2],   s[2*j][3]);
            pf[j][2] = pk(s[2*j+1][0], s[2*j+1][1]);
            pf[j][3] = pk(s[2*j+1][2], s[2*j+1][3]);
        }
        // ---- O += P @ V ----
        #pragma unroll
        for (int ks = 0; ks < 4; ks++) {
            #pragma unroll
            for (int ntp = 0; ntp < 4; ntp++) {
                int row = ks * 16 + (lane & 7) + ((lane >> 3) & 1) * 8;
                int seg = ntp * 2 + (lane >> 4);
                uint32_t vb[4];
                ldm_x4t(vb, st + 16384 + off64(row, seg));
                mma_bf16(o_acc[ntp * 2 + 0], pf[ks], vb + 0);
                mma_bf16(o_acc[ntp * 2 + 1], pf[ks], vb + 2);
            }
        }
        __syncthreads();
        if (kb + 2 < NKB) issueKV(kb + 2);
        if (kb + 1 < NKB) {
            if (kb + 2 < NKB) cp_wait<1>(); else cp_wait<0>();
            __syncthreads();
        }
    }

    // finalize: row sums live in quads
    lA += __shfl_xor_sync(0xffffffffu, lA, 1);
    lA += __shfl_xor_sync(0xffffffffu, lA, 2);
    lB += __shfl_xor_sync(0xffffffffu, lB, 1);
    lB += __shfl_xor_sync(0xffffffffu, lB, 2);
    float iA = 1.f / lA, iB = 1.f / lB;
    int rowA = tok0 + wid * 16 + (lane >> 2);
    #pragma unroll
    for (int nt = 0; nt < 8; nt++) {
        int col = h * HD + nt * 8 + (lane & 3) * 2;
        float2 p0 = {o_acc[nt][0] * iA, o_acc[nt][1] * iA};
        float2 p1 = {o_acc[nt][2] * iB, o_acc[nt][3] * iB};
        *(float2*)(out + (size_t)rowA * DIM + col) = p0;
        *(float2*)(out + (size_t)(rowA + 8) * DIM + col) = p1;
    }
}

// ---------------- launch ----------------
extern "C" void kernel_launch(void* const* d_in, const int* in_sizes, int n_in,
                              void* d_out, int out_size)
{
    (void)in_sizes; (void)n_in; (void)out_size;
    const float* x   = (const float*)d_in[0];
    const float* Wq  = (const float*)d_in[1];
    const float* bq  = (const float*)d_in[2];
    const float* Wk  = (const float*)d_in[3];
    const float* bk  = (const float*)d_in[4];
    const float* Wv  = (const float*)d_in[5];
    const float* bv  = (const float*)d_in[6];
    const float* g1  = (const float*)d_in[7];
    const float* b1  = (const float*)d_in[8];
    const float* g2  = (const float*)d_in[9];
    const float* b2  = (const float*)d_in[10];
    const float* W1  = (const float*)d_in[11];
    const float* bf1 = (const float*)d_in[12];
    const float* W2  = (const float*)d_in[13];
    const float* bf2 = (const float*)d_in[14];

    float *xn, *attn;
    cudaGetSymbolAddress((void**)&xn,   g_xn);
    cudaGetSymbolAddress((void**)&attn, g_attn);

    __nv_bfloat16 *xnh, *xnl, *qhp, *qlp, *khp, *klp, *vhp, *vlp, *hh, *hl, *f1h, *f1l;
    __nv_bfloat16 *wqh, *wql, *wkh, *wkl, *wvh, *wvl, *w1h, *w1l, *w2h, *w2l;
    cudaGetSymbolAddress((void**)&xnh, g_xn_hi);  cudaGetSymbolAddress((void**)&xnl, g_xn_lo);
    cudaGetSymbolAddress((void**)&qhp, g_q_hi);   cudaGetSymbolAddress((void**)&qlp, g_q_lo);
    cudaGetSymbolAddress((void**)&khp, g_k_hi);   cudaGetSymbolAddress((void**)&klp, g_k_lo);
    cudaGetSymbolAddress((void**)&vhp, g_v_hi);   cudaGetSymbolAddress((void**)&vlp, g_v_lo);
    cudaGetSymbolAddress((void**)&hh,  g_h_hi);   cudaGetSymbolAddress((void**)&hl,  g_h_lo);
    cudaGetSymbolAddress((void**)&f1h, g_ff1_hi); cudaGetSymbolAddress((void**)&f1l, g_ff1_lo);
    cudaGetSymbolAddress((void**)&wqh, g_wq_hi);  cudaGetSymbolAddress((void**)&wql, g_wq_lo);
    cudaGetSymbolAddress((void**)&wkh, g_wk_hi);  cudaGetSymbolAddress((void**)&wkl, g_wk_lo);
    cudaGetSymbolAddress((void**)&wvh, g_wv_hi);  cudaGetSymbolAddress((void**)&wvl, g_wv_lo);
    cudaGetSymbolAddress((void**)&w1h, g_w1_hi);  cudaGetSymbolAddress((void**)&w1l, g_w1_lo);
    cudaGetSymbolAddress((void**)&w2h, g_w2_hi);  cudaGetSymbolAddress((void**)&w2l, g_w2_lo);

    cudaFuncSetAttribute(gemm_mma<1>, cudaFuncAttributeMaxDynamicSharedMemorySize, G_SMEM);
    cudaFuncSetAttribute(gemm_mma<2>, cudaFuncAttributeMaxDynamicSharedMemorySize, G_SMEM);
    cudaFuncSetAttribute(gemm_mma<3>, cudaFuncAttributeMaxDynamicSharedMemorySize, G_SMEM);
    cudaFuncSetAttribute(attn_mma,    cudaFuncAttributeMaxDynamicSharedMemorySize, A_SMEM);

    // weight splits
    split_kernel<<<(DIM*DIM/4 + 255)/256, 256>>>(Wq, wqh, wql, DIM*DIM/4);
    split_kernel<<<(DIM*DIM/4 + 255)/256, 256>>>(Wk, wkh, wkl, DIM*DIM/4);
    split_kernel<<<(DIM*DIM/4 + 255)/256, 256>>>(Wv, wvh, wvl, DIM*DIM/4);
    split_kernel<<<(DFF*DIM/4 + 255)/256, 256>>>(W1, w1h, w1l, DFF*DIM/4);
    split_kernel<<<(DIM*DFF/4 + 255)/256, 256>>>(W2, w2h, w2l, DIM*DFF/4);

    // xn = LN(x) : fp32 + splits
    ln_kernel<<<NTOK, 256>>>(x, nullptr, g1, b1, xn, xnh, xnl);

    // QKV projections -> bf16 hi/lo (Q pre-scaled by 1/sqrt(64))
    dim3 gP(DIM / 128, NTOK / 128);
    gemm_mma<3><<<gP, 256, G_SMEM>>>(xnh, xnl, wqh, wql, bq, nullptr, nullptr, qhp, qlp, DIM, DIM, 0.125f);
    gemm_mma<3><<<gP, 256, G_SMEM>>>(xnh, xnl, wkh, wkl, bk, nullptr, nullptr, khp, klp, DIM, DIM, 1.0f);
    gemm_mma<3><<<gP, 256, G_SMEM>>>(xnh, xnl, wvh, wvl, bv, nullptr, nullptr, vhp, vlp, DIM, DIM, 1.0f);

    // attention (tensor-core flash)
    attn_mma<<<dim3(SEQ / 128, NH, 2), 256, A_SMEM>>>(qhp, qlp, khp, klp, vhp, attn);

    // h = LN(attn + xn) -> splits
    ln_kernel<<<NTOK, 256>>>(attn, xn, g2, b2, nullptr, hh, hl);

    // ff1 = silu(h @ W1^T + bf1) -> bf16 splits
    dim3 gF1(DFF / 128, NTOK / 128);
    gemm_mma<1><<<gF1, 256, G_SMEM>>>(hh, hl, w1h, w1l, bf1, nullptr, nullptr, f1h, f1l, DFF, DIM, 1.0f);

    // out = ff1 @ W2^T + bf2 + xn
    dim3 gF2(DIM / 128, NTOK / 128);
    gemm_mma<2><<<gF2, 256, G_SMEM>>>(f1h, f1l, w2h, w2l, bf2, xn, (float*)d_out, nullptr, nullptr, DIM, DFF, 1.0f);
}

// round 9
// speedup vs baseline: 5.4801x; 1.1008x over previous
#include <cuda_runtime.h>
#include <cuda_bf16.h>
#include <math.h>
#include <stdint.h>

#define NTOK 4096          // B*S
#define SEQ  2048
#define DIM  1024
#define NH   16
#define HD   64
#define DFF  4096

// ---------------- scratch (device globals; no allocs allowed) ----------------
__device__ float g_xn[NTOK * DIM];
__device__ float g_attn[NTOK * DIM];

__device__ __nv_bfloat16 g_xn_hi[NTOK * DIM],  g_xn_lo[NTOK * DIM];
__device__ __nv_bfloat16 g_q_hi[NTOK * DIM],   g_q_lo[NTOK * DIM];
__device__ __nv_bfloat16 g_k_hi[NTOK * DIM],   g_k_lo[NTOK * DIM];
__device__ __nv_bfloat16 g_v_hi[NTOK * DIM],   g_v_lo[NTOK * DIM];
__device__ __nv_bfloat16 g_h_hi[NTOK * DIM],   g_h_lo[NTOK * DIM];
__device__ __nv_bfloat16 g_ff1_hi[NTOK * DFF], g_ff1_lo[NTOK * DFF];
__device__ __nv_bfloat16 g_wq_hi[DIM * DIM],   g_wq_lo[DIM * DIM];
__device__ __nv_bfloat16 g_wk_hi[DIM * DIM],   g_wk_lo[DIM * DIM];
__device__ __nv_bfloat16 g_wv_hi[DIM * DIM],   g_wv_lo[DIM * DIM];
__device__ __nv_bfloat16 g_w1_hi[DFF * DIM],   g_w1_lo[DFF * DIM];
__device__ __nv_bfloat16 g_w2_hi[DIM * DFF],   g_w2_lo[DIM * DFF];

// ---------------- PTX helpers (family-portable sm_80-era ISA) ----------------
__device__ __forceinline__ uint32_t smem_u32(const void* p) {
    uint32_t a;
    asm("{ .reg .u64 t; cvta.to.shared.u64 t, %1; cvt.u32.u64 %0, t; }" : "=r"(a) : "l"(p));
    return a;
}
__device__ __forceinline__ void cp16(uint32_t dst, const void* src) {
    asm volatile("cp.async.cg.shared.global [%0], [%1], 16;" :: "r"(dst), "l"(src) : "memory");
}
__device__ __forceinline__ void cp_commit() {
    asm volatile("cp.async.commit_group;" ::: "memory");
}
template<int N> __device__ __forceinline__ void cp_wait() {
    asm volatile("cp.async.wait_group %0;" :: "n"(N) : "memory");
}
__device__ __forceinline__ void ldm_x4(uint32_t* r, uint32_t addr) {
    asm volatile("ldmatrix.sync.aligned.m8n8.x4.shared.b16 {%0,%1,%2,%3}, [%4];"
        : "=r"(r[0]), "=r"(r[1]), "=r"(r[2]), "=r"(r[3]) : "r"(addr));
}
__device__ __forceinline__ void ldm_x4t(uint32_t* r, uint32_t addr) {
    asm volatile("ldmatrix.sync.aligned.m8n8.x4.trans.shared.b16 {%0,%1,%2,%3}, [%4];"
        : "=r"(r[0]), "=r"(r[1]), "=r"(r[2]), "=r"(r[3]) : "r"(addr));
}
__device__ __forceinline__ void mma_bf16(float* d, const uint32_t* a, const uint32_t* b) {
    asm volatile(
        "mma.sync.aligned.m16n8k16.row.col.f32.bf16.bf16.f32 "
        "{%0,%1,%2,%3}, {%4,%5,%6,%7}, {%8,%9}, {%0,%1,%2,%3};"
        : "+f"(d[0]), "+f"(d[1]), "+f"(d[2]), "+f"(d[3])
        : "r"(a[0]), "r"(a[1]), "r"(a[2]), "r"(a[3]), "r"(b[0]), "r"(b[1]));
}
__device__ __forceinline__ uint32_t pk(float lo, float hi) {
    __nv_bfloat162 t = __floats2bfloat162_rn(lo, hi);
    return *(uint32_t*)&t;
}
__device__ __forceinline__ void split2(float v0, float v1, uint32_t& h, uint32_t& l) {
    __nv_bfloat16 h0 = __float2bfloat16(v0), h1 = __float2bfloat16(v1);
    h = pk(__bfloat162float(h0), __bfloat162float(h1));
    l = pk(v0 - __bfloat162float(h0), v1 - __bfloat162float(h1));
}
// 32-col bf16 tile (64B rows, 4x16B segs)
__device__ __forceinline__ uint32_t off32(int r, int s) {
    return (uint32_t)(r * 64 + ((s ^ ((r >> 1) & 3)) << 4));
}
// 64-col bf16 tile (128B rows, 8x16B segs)
__device__ __forceinline__ uint32_t off64(int r, int s) {
    return (uint32_t)(r * 128 + ((s ^ (r & 7)) << 4));
}

// ---------------- split fp32 -> (hi, lo) bf16 ----------------
__global__ __launch_bounds__(256)
void split_kernel(const float* __restrict__ in, __nv_bfloat16* __restrict__ hi,
                  __nv_bfloat16* __restrict__ lo, int n4)
{
    int i = blockIdx.x * blockDim.x + threadIdx.x;
    if (i >= n4) return;
    float4 v = ((const float4*)in)[i];
    uint2 uh, ul;
    split2(v.x, v.y, uh.x, ul.x);
    split2(v.z, v.w, uh.y, ul.y);
    *(uint2*)(hi + (size_t)i * 4) = uh;
    *(uint2*)(lo + (size_t)i * 4) = ul;
}

// ---------------- LayerNorm (optional residual; fp32 out + bf16 splits) ----------------
__global__ __launch_bounds__(256)
void ln_kernel(const float* __restrict__ x, const float* __restrict__ res,
               const float* __restrict__ gamma, const float* __restrict__ beta,
               float* __restrict__ out, __nv_bfloat16* __restrict__ ohi,
               __nv_bfloat16* __restrict__ olo)
{
    int row = blockIdx.x;
    int t = threadIdx.x;
    const float4* xr = (const float4*)(x + (size_t)row * DIM);
    float4 v = xr[t];
    if (res) {
        const float4* rr = (const float4*)(res + (size_t)row * DIM);
        float4 r = rr[t];
        v.x += r.x; v.y += r.y; v.z += r.z; v.w += r.w;
    }
    float s  = v.x + v.y + v.z + v.w;
    float s2 = v.x*v.x + v.y*v.y + v.z*v.z + v.w*v.w;
    #pragma unroll
    for (int o = 16; o > 0; o >>= 1) {
        s  += __shfl_down_sync(0xffffffffu, s,  o);
        s2 += __shfl_down_sync(0xffffffffu, s2, o);
    }
    __shared__ float ss[8], ss2[8];
    __shared__ float mean_s, rstd_s;
    if ((t & 31) == 0) { ss[t >> 5] = s; ss2[t >> 5] = s2; }
    __syncthreads();
    if (t == 0) {
        float a = 0.f, b = 0.f;
        #pragma unroll
        for (int i = 0; i < 8; i++) { a += ss[i]; b += ss2[i]; }
        float mean = a * (1.0f / DIM);
        float var  = b * (1.0f / DIM) - mean * mean;
        mean_s = mean;
        rstd_s = rsqrtf(var + 1e-5f);
    }
    __syncthreads();
    float mean = mean_s, rstd = rstd_s;
    float4 g = ((const float4*)gamma)[t];
    float4 bb = ((const float4*)beta)[t];
    float4 o4;
    o4.x = (v.x - mean) * rstd * g.x + bb.x;
    o4.y = (v.y - mean) * rstd * g.y + bb.y;
    o4.z = (v.z - mean) * rstd * g.z + bb.z;
    o4.w = (v.w - mean) * rstd * g.w + bb.w;
    size_t idx = (size_t)row * DIM + t * 4;
    if (out) *(float4*)(out + idx) = o4;
    if (ohi) {
        uint2 uh, ul;
        split2(o4.x, o4.y, uh.x, ul.x);
        split2(o4.z, o4.w, uh.y, ul.y);
        *(uint2*)(ohi + idx) = uh;
        *(uint2*)(olo + idx) = ul;
    }
}

// ---------------- mma.sync split-bf16 GEMM: C[M,N] = A[M,K] @ W[N,K]^T ----------------
// CTA 128x128, 8 warps (warp tile 32x64), K-chunk 32, 3-stage cp.async, 2 CTAs/SM.
// EPI: 1 = bias+silu -> bf16 hi/lo ; 2 = bias+res -> fp32 ; 3 = (bias)*scale -> bf16 hi/lo
static constexpr int G_STAGE = 32768;   // Ah(8K) Al(8K) Bh(8K) Bl(8K)
static constexpr int G_SMEM = 3 * G_STAGE;

template<int EPI>
__global__ void __launch_bounds__(256, 2)
gemm_mma(const __nv_bfloat16* __restrict__ Ah, const __nv_bfloat16* __restrict__ Al,
         const __nv_bfloat16* __restrict__ Bh, const __nv_bfloat16* __restrict__ Bl,
         const float* __restrict__ bias, const float* __restrict__ res,
         float* __restrict__ C, __nv_bfloat16* __restrict__ Chi,
         __nv_bfloat16* __restrict__ Clo, int N, int K, float scale)
{
    extern __shared__ char sm[];
    const int tid = threadIdx.x;
    const int wid = tid >> 5, lane = tid & 31;
    const int bm = blockIdx.y * 128, bn = blockIdx.x * 128;
    const int wm = (wid & 3) * 32, wn = (wid >> 2) * 64;
    const uint32_t sb = smem_u32(sm);

    float acc[2][8][4];
    #pragma unroll
    for (int i = 0; i < 2; i++)
        #pragma unroll
        for (int j = 0; j < 8; j++)
            #pragma unroll
            for (int d = 0; d < 4; d++) acc[i][j][d] = 0.f;

    const int r_ld = tid >> 1;           // 0..127
    const int s_ld = (tid & 1) * 2;      // seg base 0 or 2
    const __nv_bfloat16* gA[2] = {Ah, Al};
    const __nv_bfloat16* gB[2] = {Bh, Bl};

    auto issue = [&](int c) {
        uint32_t st = sb + (uint32_t)(c % 3) * G_STAGE;
        int k0 = c * 32;
        #pragma unroll
        for (int t = 0; t < 2; t++) {
            const __nv_bfloat16* A = gA[t];
            const __nv_bfloat16* B = gB[t];
            uint32_t dA = st + t * 8192;
            uint32_t dB = st + 16384 + t * 8192;
            #pragma unroll
            for (int j = 0; j < 2; j++) {
                int s = s_ld + j;
                uint32_t o = off32(r_ld, s);
                cp16(dA + o, A + (size_t)(bm + r_ld) * K + k0 + s * 8);
                cp16(dB + o, B + (size_t)(bn + r_ld) * K + k0 + s * 8);
            }
        }
        cp_commit();
    };

    const int NC = K / 32;
    issue(0);
    issue(1);
    issue(2);

    for (int c = 0; c < NC; c++) {
        if (c + 2 < NC) cp_wait<2>(); else if (c + 1 < NC) cp_wait<1>(); else cp_wait<0>();
        __syncthreads();
        uint32_t st = sb + (uint32_t)(c % 3) * G_STAGE;
        #pragma unroll
        for (int ks = 0; ks < 2; ks++) {
            uint32_t a_h[8], a_l[8];
            #pragma unroll
            for (int mt = 0; mt < 2; mt++) {
                int row = wm + mt * 16 + (lane & 7) + ((lane >> 3) & 1) * 8;
                int seg = ks * 2 + (lane >> 4);
                uint32_t oa = off32(row, seg);
                ldm_x4(a_h + mt * 4, st + oa);
                ldm_x4(a_l + mt * 4, st + 8192 + oa);
            }
            #pragma unroll
            for (int ntp = 0; ntp < 4; ntp++) {
                int row = wn + ntp * 16 + (lane & 7) + ((lane >> 4) & 1) * 8;
                int seg = ks * 2 + ((lane >> 3) & 1);
                uint32_t ob = off32(row, seg);
                uint32_t bh4[4], bl4[4];
                ldm_x4(bh4, st + 16384 + ob);
                ldm_x4(bl4, st + 24576 + ob);
                #pragma unroll
                for (int half = 0; half < 2; half++) {
                    int nt = ntp * 2 + half;
                    #pragma unroll
                    for (int mt = 0; mt < 2; mt++) {
                        mma_bf16(acc[mt][nt], a_h + mt * 4, bh4 + half * 2);
                        mma_bf16(acc[mt][nt], a_h + mt * 4, bl4 + half * 2);
                        mma_bf16(acc[mt][nt], a_l + mt * 4, bh4 + half * 2);
                    }
                }
            }
        }
        __syncthreads();
        if (c + 3 < NC) issue(c + 3);
    }

    // epilogue (direct reg->global)
    #pragma unroll
    for (int mt = 0; mt < 2; mt++) {
        int r0 = bm + wm + mt * 16 + (lane >> 2);
        #pragma unroll
        for (int nt = 0; nt < 8; nt++) {
            int col = bn + wn + nt * 8 + (lane & 3) * 2;
            float b0 = bias[col], b1 = bias[col + 1];
            float* a = acc[mt][nt];
            if (EPI == 3) {
                uint32_t h0, l0, h1, l1;
                split2((a[0] + b0) * scale, (a[1] + b1) * scale, h0, l0);
                split2((a[2] + b0) * scale, (a[3] + b1) * scale, h1, l1);
                *(uint32_t*)(Chi + (size_t)r0 * N + col) = h0;
                *(uint32_t*)(Clo + (size_t)r0 * N + col) = l0;
                *(uint32_t*)(Chi + (size_t)(r0 + 8) * N + col) = h1;
                *(uint32_t*)(Clo + (size_t)(r0 + 8) * N + col) = l1;
            } else if (EPI == 1) {
                float v0 = a[0] + b0, v1 = a[1] + b1, v2 = a[2] + b0, v3 = a[3] + b1;
                v0 = v0 / (1.f + __expf(-v0));
                v1 = v1 / (1.f + __expf(-v1));
                v2 = v2 / (1.f + __expf(-v2));
                v3 = v3 / (1.f + __expf(-v3));
                uint32_t h0, l0, h1, l1;
                split2(v0, v1, h0, l0);
                split2(v2, v3, h1, l1);
                *(uint32_t*)(Chi + (size_t)r0 * N + col) = h0;
                *(uint32_t*)(Clo + (size_t)r0 * N + col) = l0;
                *(uint32_t*)(Chi + (size_t)(r0 + 8) * N + col) = h1;
                *(uint32_t*)(Clo + (size_t)(r0 + 8) * N + col) = l1;
            } else {
                float2 p0, p1;
                float2 rr0 = *(const float2*)(res + (size_t)r0 * N + col);
                float2 rr1 = *(const float2*)(res + (size_t)(r0 + 8) * N + col);
                p0.x = a[0] + b0 + rr0.x; p0.y = a[1] + b1 + rr0.y;
                p1.x = a[2] + b0 + rr1.x; p1.y = a[3] + b1 + rr1.y;
                *(float2*)(C + (size_t)r0 * N + col) = p0;
                *(float2*)(C + (size_t)(r0 + 8) * N + col) = p1;
            }
        }
    }
}

// ---------------- Flash attention via mma.sync ----------------
// grid: (SEQ/64, NH, B); 128 thr (4 warps, 16 q-rows each), 2 CTAs/SM.
// smem: Qhi 8K @0, Qlo 8K @8192; KV 3 stages @16384, stride 24576: Kh, Kl(+8192), Vh(+16384)
static constexpr int A_SMEM = 16384 + 3 * 24576;   // 90112

__global__ void __launch_bounds__(128, 2)
attn_mma(const __nv_bfloat16* __restrict__ qh, const __nv_bfloat16* __restrict__ ql,
         const __nv_bfloat16* __restrict__ kh, const __nv_bfloat16* __restrict__ kl,
         const __nv_bfloat16* __restrict__ vh, float* __restrict__ out)
{
    extern __shared__ char sm[];
    const int tid = threadIdx.x;
    const int wid = tid >> 5, lane = tid & 31;
    const int h = blockIdx.y, b = blockIdx.z;
    const int tok0 = b * SEQ + blockIdx.x * 64;
    const size_t qbase = (size_t)tok0 * DIM + h * HD;
    const size_t kvbase = (size_t)b * SEQ * DIM + h * HD;
    const uint32_t sb = smem_u32(sm);

    // issue Q (group 0): 64 rows x 128B, hi+lo
    {
        int r = tid >> 1;
        #pragma unroll
        for (int j = 0; j < 4; j++) {
            int s = (tid & 1) * 4 + j;
            uint32_t o = off64(r, s);
            const size_t go = qbase + (size_t)r * DIM + s * 8;
            cp16(sb + o, qh + go);
            cp16(sb + 8192 + o, ql + go);
        }
        cp_commit();
    }
    auto issueKV = [&](int kb) {
        uint32_t st = sb + 16384 + (uint32_t)(kb % 3) * 24576;
        int r = tid >> 1;
        size_t rowoff = kvbase + (size_t)(kb * 64 + r) * DIM;
        #pragma unroll
        for (int j = 0; j < 4; j++) {
            int s = (tid & 1) * 4 + j;
            uint32_t o = off64(r, s);
            cp16(st + o, kh + rowoff + s * 8);
            cp16(st + 8192 + o, kl + rowoff + s * 8);
            cp16(st + 16384 + o, vh + rowoff + s * 8);
        }
        cp_commit();
    };
    issueKV(0);   // group 1
    issueKV(1);   // group 2
    issueKV(2);   // group 3

    cp_wait<2>(); // Q + KV0 done
    __syncthreads();

    // Q fragments (registers, reused all blocks)
    uint32_t qf[2][4][4];
    {
        int row = wid * 16 + (lane & 7) + ((lane >> 3) & 1) * 8;
        #pragma unroll
        for (int ks = 0; ks < 4; ks++) {
            int seg = ks * 2 + (lane >> 4);
            uint32_t o = off64(row, seg);
            ldm_x4(qf[0][ks], sb + o);
            ldm_x4(qf[1][ks], sb + 8192 + o);
        }
    }

    float o_acc[8][4];
    #pragma unroll
    for (int i = 0; i < 8; i++)
        #pragma unroll
        for (int d = 0; d < 4; d++) o_acc[i][d] = 0.f;
    float runA = -INFINITY, runB = -INFINITY, lA = 0.f, lB = 0.f;

    const int NKB = SEQ / 64;
    for (int kb = 0; kb < NKB; kb++) {
        uint32_t st = sb + 16384 + (uint32_t)(kb % 3) * 24576;
        // ---- scores S[16,64] ----
        float s[8][4];
        #pragma unroll
        for (int i = 0; i < 8; i++)
            #pragma unroll
            for (int d = 0; d < 4; d++) s[i][d] = 0.f;
        #pragma unroll
        for (int ks = 0; ks < 4; ks++) {
            #pragma unroll
            for (int ntp = 0; ntp < 4; ntp++) {
                int row = ntp * 16 + (lane & 7) + ((lane >> 4) & 1) * 8;
                int seg = ks * 2 + ((lane >> 3) & 1);
                uint32_t ob = off64(row, seg);
                uint32_t bh4[4], bl4[4];
                ldm_x4(bh4, st + ob);
                ldm_x4(bl4, st + 8192 + ob);
                #pragma unroll
                for (int half = 0; half < 2; half++) {
                    int nt = ntp * 2 + half;
                    mma_bf16(s[nt], qf[0][ks], bh4 + half * 2);
                    mma_bf16(s[nt], qf[1][ks], bh4 + half * 2);
                    mma_bf16(s[nt], qf[0][ks], bl4 + half * 2);
                }
            }
        }
        // ---- online softmax (rows: A = lane>>2, B = +8) ----
        float mA = -INFINITY, mB = -INFINITY;
        #pragma unroll
        for (int nt = 0; nt < 8; nt++) {
            mA = fmaxf(mA, fmaxf(s[nt][0], s[nt][1]));
            mB = fmaxf(mB, fmaxf(s[nt][2], s[nt][3]));
        }
        mA = fmaxf(mA, __shfl_xor_sync(0xffffffffu, mA, 1));
        mA = fmaxf(mA, __shfl_xor_sync(0xffffffffu, mA, 2));
        mB = fmaxf(mB, __shfl_xor_sync(0xffffffffu, mB, 1));
        mB = fmaxf(mB, __shfl_xor_sync(0xffffffffu, mB, 2));
        float nA = fmaxf(runA, mA), nB = fmaxf(runB, mB);
        float cA = __expf(runA - nA), cB = __expf(runB - nB);
        runA = nA; runB = nB;
        lA *= cA; lB *= cB;
        #pragma unroll
        for (int nt = 0; nt < 8; nt++) {
            o_acc[nt][0] *= cA; o_acc[nt][1] *= cA;
            o_acc[nt][2] *= cB; o_acc[nt][3] *= cB;
        }
        float sumA = 0.f, sumB = 0.f;
        #pragma unroll
        for (int nt = 0; nt < 8; nt++) {
            s[nt][0] = __expf(s[nt][0] - nA); sumA += s[nt][0];
            s[nt][1] = __expf(s[nt][1] - nA); sumA += s[nt][1];
            s[nt][2] = __expf(s[nt][2] - nB); sumB += s[nt][2];
            s[nt][3] = __expf(s[nt][3] - nB); sumB += s[nt][3];
        }
        lA += sumA; lB += sumB;
        // ---- P (bf16 A-frags, pure register repack) ----
        uint32_t pf[4][4];
        #pragma unroll
        for (int j = 0; j < 4; j++) {
            pf[j][0] = pk(s[2*j][0],   s[2*j][1]);
            pf[j][1] = pk(s[2*j][2],   s[2*j][3]);
            pf[j][2] = pk(s[2*j+1][0], s[2*j+1][1]);
            pf[j][3] = pk(s[2*j+1][2], s[2*j+1][3]);
        }
        // ---- O += P @ V ----
        #pragma unroll
        for (int ks = 0; ks < 4; ks++) {
            #pragma unroll
            for (int ntp = 0; ntp < 4; ntp++) {
                int row = ks * 16 + (lane & 7) + ((lane >> 3) & 1) * 8;
                int seg = ntp * 2 + (lane >> 4);
                uint32_t vb[4];
                ldm_x4t(vb, st + 16384 + off64(row, seg));
                mma_bf16(o_acc[ntp * 2 + 0], pf[ks], vb + 0);
                mma_bf16(o_acc[ntp * 2 + 1], pf[ks], vb + 2);
            }
        }
        __syncthreads();
        if (kb + 3 < NKB) issueKV(kb + 3);
        if (kb + 1 < NKB) {
            if (kb + 3 < NKB) cp_wait<2>();
            else if (kb + 2 < NKB) cp_wait<1>();
            else cp_wait<0>();
            __syncthreads();
        }
    }

    // finalize: row sums live in quads
    lA += __shfl_xor_sync(0xffffffffu, lA, 1);
    lA += __shfl_xor_sync(0xffffffffu, lA, 2);
    lB += __shfl_xor_sync(0xffffffffu, lB, 1);
    lB += __shfl_xor_sync(0xffffffffu, lB, 2);
    float iA = 1.f / lA, iB = 1.f / lB;
    int rowA = tok0 + wid * 16 + (lane >> 2);
    #pragma unroll
    for (int nt = 0; nt < 8; nt++) {
        int col = h * HD + nt * 8 + (lane & 3) * 2;
        float2 p0 = {o_acc[nt][0] * iA, o_acc[nt][1] * iA};
        float2 p1 = {o_acc[nt][2] * iB, o_acc[nt][3] * iB};
        *(float2*)(out + (size_t)rowA * DIM + col) = p0;
        *(float2*)(out + (size_t)(rowA + 8) * DIM + col) = p1;
    }
}

// ---------------- launch ----------------
extern "C" void kernel_launch(void* const* d_in, const int* in_sizes, int n_in,
                              void* d_out, int out_size)
{
    (void)in_sizes; (void)n_in; (void)out_size;
    const float* x   = (const float*)d_in[0];
    const float* Wq  = (const float*)d_in[1];
    const float* bq  = (const float*)d_in[2];
    const float* Wk  = (const float*)d_in[3];
    const float* bk  = (const float*)d_in[4];
    const float* Wv  = (const float*)d_in[5];
    const float* bv  = (const float*)d_in[6];
    const float* g1  = (const float*)d_in[7];
    const float* b1  = (const float*)d_in[8];
    const float* g2  = (const float*)d_in[9];
    const float* b2  = (const float*)d_in[10];
    const float* W1  = (const float*)d_in[11];
    const float* bf1 = (const float*)d_in[12];
    const float* W2  = (const float*)d_in[13];
    const float* bf2 = (const float*)d_in[14];

    float *xn, *attn;
    cudaGetSymbolAddress((void**)&xn,   g_xn);
    cudaGetSymbolAddress((void**)&attn, g_attn);

    __nv_bfloat16 *xnh, *xnl, *qhp, *qlp, *khp, *klp, *vhp, *vlp, *hh, *hl, *f1h, *f1l;
    __nv_bfloat16 *wqh, *wql, *wkh, *wkl, *wvh, *wvl, *w1h, *w1l, *w2h, *w2l;
    cudaGetSymbolAddress((void**)&xnh, g_xn_hi);  cudaGetSymbolAddress((void**)&xnl, g_xn_lo);
    cudaGetSymbolAddress((void**)&qhp, g_q_hi);   cudaGetSymbolAddress((void**)&qlp, g_q_lo);
    cudaGetSymbolAddress((void**)&khp, g_k_hi);   cudaGetSymbolAddress((void**)&klp, g_k_lo);
    cudaGetSymbolAddress((void**)&vhp, g_v_hi);   cudaGetSymbolAddress((void**)&vlp, g_v_lo);
    cudaGetSymbolAddress((void**)&hh,  g_h_hi);   cudaGetSymbolAddress((void**)&hl,  g_h_lo);
    cudaGetSymbolAddress((void**)&f1h, g_ff1_hi); cudaGetSymbolAddress((void**)&f1l, g_ff1_lo);
    cudaGetSymbolAddress((void**)&wqh, g_wq_hi);  cudaGetSymbolAddress((void**)&wql, g_wq_lo);
    cudaGetSymbolAddress((void**)&wkh, g_wk_hi);  cudaGetSymbolAddress((void**)&wkl, g_wk_lo);
    cudaGetSymbolAddress((void**)&wvh, g_wv_hi);  cudaGetSymbolAddress((void**)&wvl, g_wv_lo);
    cudaGetSymbolAddress((void**)&w1h, g_w1_hi);  cudaGetSymbolAddress((void**)&w1l, g_w1_lo);
    cudaGetSymbolAddress((void**)&w2h, g_w2_hi);  cudaGetSymbolAddress((void**)&w2l, g_w2_lo);

    cudaFuncSetAttribute(gemm_mma<1>, cudaFuncAttributeMaxDynamicSharedMemorySize, G_SMEM);
    cudaFuncSetAttribute(gemm_mma<2>, cudaFuncAttributeMaxDynamicSharedMemorySize, G_SMEM);
    cudaFuncSetAttribute(gemm_mma<3>, cudaFuncAttributeMaxDynamicSharedMemorySize, G_SMEM);
    cudaFuncSetAttribute(attn_mma,    cudaFuncAttributeMaxDynamicSharedMemorySize, A_SMEM);

    // weight splits
    split_kernel<<<(DIM*DIM/4 + 255)/256, 256>>>(Wq, wqh, wql, DIM*DIM/4);
    split_kernel<<<(DIM*DIM/4 + 255)/256, 256>>>(Wk, wkh, wkl, DIM*DIM/4);
    split_kernel<<<(DIM*DIM/4 + 255)/256, 256>>>(Wv, wvh, wvl, DIM*DIM/4);
    split_kernel<<<(DFF*DIM/4 + 255)/256, 256>>>(W1, w1h, w1l, DFF*DIM/4);
    split_kernel<<<(DIM*DFF/4 + 255)/256, 256>>>(W2, w2h, w2l, DIM*DFF/4);

    // xn = LN(x) : fp32 + splits
    ln_kernel<<<NTOK, 256>>>(x, nullptr, g1, b1, xn, xnh, xnl);

    // QKV projections -> bf16 hi/lo (Q pre-scaled by 1/sqrt(64))
    dim3 gP(DIM / 128, NTOK / 128);
    gemm_mma<3><<<gP, 256, G_SMEM>>>(xnh, xnl, wqh, wql, bq, nullptr, nullptr, qhp, qlp, DIM, DIM, 0.125f);
    gemm_mma<3><<<gP, 256, G_SMEM>>>(xnh, xnl, wkh, wkl, bk, nullptr, nullptr, khp, klp, DIM, DIM, 1.0f);
    gemm_mma<3><<<gP, 256, G_SMEM>>>(xnh, xnl, wvh, wvl, bv, nullptr, nullptr, vhp, vlp, DIM, DIM, 1.0f);

    // attention (tensor-core flash, 64-q tiles, 2 CTAs/SM)
    attn_mma<<<dim3(SEQ / 64, NH, 2), 128, A_SMEM>>>(qhp, qlp, khp, klp, vhp, attn);

    // h = LN(attn + xn) -> splits
    ln_kernel<<<NTOK, 256>>>(attn, xn, g2, b2, nullptr, hh, hl);

    // ff1 = silu(h @ W1^T + bf1) -> bf16 splits
    dim3 gF1(DFF / 128, NTOK / 128);
    gemm_mma<1><<<gF1, 256, G_SMEM>>>(hh, hl, w1h, w1l, bf1, nullptr, nullptr, f1h, f1l, DFF, DIM, 1.0f);

    // out = ff1 @ W2^T + bf2 + xn
    dim3 gF2(DIM / 128, NTOK / 128);
    gemm_mma<2><<<gF2, 256, G_SMEM>>>(f1h, f1l, w2h, w2l, bf2, xn, (float*)d_out, nullptr, nullptr, DIM, DFF, 1.0f);
}

// round 10
// speedup vs baseline: 5.5175x; 1.0068x over previous
#include <cuda_runtime.h>
#include <cuda_bf16.h>
#include <math.h>
#include <stdint.h>

#define NTOK 4096          // B*S
#define SEQ  2048
#define DIM  1024
#define NH   16
#define HD   64
#define DFF  4096
#define NQKV 3072

// ---------------- scratch (device globals; no allocs allowed) ----------------
__device__ float g_xn[NTOK * DIM];
__device__ float g_attn[NTOK * DIM];
__device__ float g_bqkv[NQKV];

__device__ __nv_bfloat16 g_xn_hi[NTOK * DIM],   g_xn_lo[NTOK * DIM];
__device__ __nv_bfloat16 g_qkv_hi[NTOK * NQKV], g_qkv_lo[NTOK * NQKV];
__device__ __nv_bfloat16 g_h_hi[NTOK * DIM],    g_h_lo[NTOK * DIM];
__device__ __nv_bfloat16 g_ff1_hi[NTOK * DFF],  g_ff1_lo[NTOK * DFF];
__device__ __nv_bfloat16 g_wqkv_hi[NQKV * DIM], g_wqkv_lo[NQKV * DIM];
__device__ __nv_bfloat16 g_w1_hi[DFF * DIM],    g_w1_lo[DFF * DIM];
__device__ __nv_bfloat16 g_w2_hi[DIM * DFF],    g_w2_lo[DIM * DFF];

// ---------------- PTX helpers (family-portable sm_80-era ISA) ----------------
__device__ __forceinline__ uint32_t smem_u32(const void* p) {
    uint32_t a;
    asm("{ .reg .u64 t; cvta.to.shared.u64 t, %1; cvt.u32.u64 %0, t; }" : "=r"(a) : "l"(p));
    return a;
}
__device__ __forceinline__ void cp16(uint32_t dst, const void* src) {
    asm volatile("cp.async.cg.shared.global [%0], [%1], 16;" :: "r"(dst), "l"(src) : "memory");
}
__device__ __forceinline__ void cp_commit() {
    asm volatile("cp.async.commit_group;" ::: "memory");
}
template<int N> __device__ __forceinline__ void cp_wait() {
    asm volatile("cp.async.wait_group %0;" :: "n"(N) : "memory");
}
__device__ __forceinline__ void ldm_x4(uint32_t* r, uint32_t addr) {
    asm volatile("ldmatrix.sync.aligned.m8n8.x4.shared.b16 {%0,%1,%2,%3}, [%4];"
        : "=r"(r[0]), "=r"(r[1]), "=r"(r[2]), "=r"(r[3]) : "r"(addr));
}
__device__ __forceinline__ void ldm_x4t(uint32_t* r, uint32_t addr) {
    asm volatile("ldmatrix.sync.aligned.m8n8.x4.trans.shared.b16 {%0,%1,%2,%3}, [%4];"
        : "=r"(r[0]), "=r"(r[1]), "=r"(r[2]), "=r"(r[3]) : "r"(addr));
}
__device__ __forceinline__ void mma_bf16(float* d, const uint32_t* a, const uint32_t* b) {
    asm volatile(
        "mma.sync.aligned.m16n8k16.row.col.f32.bf16.bf16.f32 "
        "{%0,%1,%2,%3}, {%4,%5,%6,%7}, {%8,%9}, {%0,%1,%2,%3};"
        : "+f"(d[0]), "+f"(d[1]), "+f"(d[2]), "+f"(d[3])
        : "r"(a[0]), "r"(a[1]), "r"(a[2]), "r"(a[3]), "r"(b[0]), "r"(b[1]));
}
__device__ __forceinline__ uint32_t pk(float lo, float hi) {
    __nv_bfloat162 t = __floats2bfloat162_rn(lo, hi);
    return *(uint32_t*)&t;
}
__device__ __forceinline__ void split2(float v0, float v1, uint32_t& h, uint32_t& l) {
    __nv_bfloat16 h0 = __float2bfloat16(v0), h1 = __float2bfloat16(v1);
    h = pk(__bfloat162float(h0), __bfloat162float(h1));
    l = pk(v0 - __bfloat162float(h0), v1 - __bfloat162float(h1));
}
// 32-col bf16 tile (64B rows, 4x16B segs)
__device__ __forceinline__ uint32_t off32(int r, int s) {
    return (uint32_t)(r * 64 + ((s ^ ((r >> 1) & 3)) << 4));
}
// 64-col bf16 tile (128B rows, 8x16B segs)
__device__ __forceinline__ uint32_t off64(int r, int s) {
    return (uint32_t)(r * 128 + ((s ^ (r & 7)) << 4));
}

// ---------------- merged weight split (+ QKV bias concat, Q pre-scaled) ----------------
static constexpr int WS_QKV = NQKV * DIM / 4;              // 786432
static constexpr int WS_W1  = DFF * DIM / 4;               // 1048576
static constexpr int WS_W2  = DIM * DFF / 4;               // 1048576
static constexpr int WS_B   = NQKV / 4;                    // 768
static constexpr int WS_TOT = WS_QKV + WS_W1 + WS_W2 + WS_B;

__global__ __launch_bounds__(256)
void wsplit_all(const float* __restrict__ Wq, const float* __restrict__ Wk,
                const float* __restrict__ Wv, const float* __restrict__ W1,
                const float* __restrict__ W2, const float* __restrict__ bq,
                const float* __restrict__ bk, const float* __restrict__ bv,
                __nv_bfloat16* __restrict__ qkvh, __nv_bfloat16* __restrict__ qkvl,
                __nv_bfloat16* __restrict__ w1h, __nv_bfloat16* __restrict__ w1l,
                __nv_bfloat16* __restrict__ w2h, __nv_bfloat16* __restrict__ w2l,
                float* __restrict__ bqkv)
{
    int i = blockIdx.x * 256 + threadIdx.x;
    if (i >= WS_TOT) return;
    if (i < WS_QKV) {
        int e = i * 4;
        int r = e >> 10;
        float sc = 1.0f;
        const float* src;
        if (r < 1024)      { src = Wq + e;                sc = 0.125f; }
        else if (r < 2048) { src = Wk + (e - 1024*1024); }
        else               { src = Wv + (e - 2048*1024); }
        float4 v = *(const float4*)src;
        v.x *= sc; v.y *= sc; v.z *= sc; v.w *= sc;
        uint2 uh, ul;
        split2(v.x, v.y, uh.x, ul.x);
        split2(v.z, v.w, uh.y, ul.y);
        *(uint2*)(qkvh + e) = uh;
        *(uint2*)(qkvl + e) = ul;
    } else if (i < WS_QKV + WS_W1) {
        int e = (i - WS_QKV) * 4;
        float4 v = *(const float4*)(W1 + e);
        uint2 uh, ul;
        split2(v.x, v.y, uh.x, ul.x);
        split2(v.z, v.w, uh.y, ul.y);
        *(uint2*)(w1h + e) = uh;
        *(uint2*)(w1l + e) = ul;
    } else if (i < WS_QKV + WS_W1 + WS_W2) {
        int e = (i - WS_QKV - WS_W1) * 4;
        float4 v = *(const float4*)(W2 + e);
        uint2 uh, ul;
        split2(v.x, v.y, uh.x, ul.x);
        split2(v.z, v.w, uh.y, ul.y);
        *(uint2*)(w2h + e) = uh;
        *(uint2*)(w2l + e) = ul;
    } else {
        int e = (i - WS_QKV - WS_W1 - WS_W2) * 4;
        #pragma unroll
        for (int j = 0; j < 4; j++) {
            int c = e + j;
            float b = (c < 1024) ? 0.125f * bq[c]
                    : (c < 2048) ? bk[c - 1024] : bv[c - 2048];
            bqkv[c] = b;
        }
    }
}

// ---------------- LayerNorm (optional residual; fp32 out + bf16 splits) ----------------
__global__ __launch_bounds__(256)
void ln_kernel(const float* __restrict__ x, const float* __restrict__ res,
               const float* __restrict__ gamma, const float* __restrict__ beta,
               float* __restrict__ out, __nv_bfloat16* __restrict__ ohi,
               __nv_bfloat16* __restrict__ olo)
{
    int row = blockIdx.x;
    int t = threadIdx.x;
    const float4* xr = (const float4*)(x + (size_t)row * DIM);
    float4 v = xr[t];
    if (res) {
        const float4* rr = (const float4*)(res + (size_t)row * DIM);
        float4 r = rr[t];
        v.x += r.x; v.y += r.y; v.z += r.z; v.w += r.w;
    }
    float s  = v.x + v.y + v.z + v.w;
    float s2 = v.x*v.x + v.y*v.y + v.z*v.z + v.w*v.w;
    #pragma unroll
    for (int o = 16; o > 0; o >>= 1) {
        s  += __shfl_down_sync(0xffffffffu, s,  o);
        s2 += __shfl_down_sync(0xffffffffu, s2, o);
    }
    __shared__ float ss[8], ss2[8];
    __shared__ float mean_s, rstd_s;
    if ((t & 31) == 0) { ss[t >> 5] = s; ss2[t >> 5] = s2; }
    __syncthreads();
    if (t == 0) {
        float a = 0.f, b = 0.f;
        #pragma unroll
        for (int i = 0; i < 8; i++) { a += ss[i]; b += ss2[i]; }
        float mean = a * (1.0f / DIM);
        float var  = b * (1.0f / DIM) - mean * mean;
        mean_s = mean;
        rstd_s = rsqrtf(var + 1e-5f);
    }
    __syncthreads();
    float mean = mean_s, rstd = rstd_s;
    float4 g = ((const float4*)gamma)[t];
    float4 bb = ((const float4*)beta)[t];
    float4 o4;
    o4.x = (v.x - mean) * rstd * g.x + bb.x;
    o4.y = (v.y - mean) * rstd * g.y + bb.y;
    o4.z = (v.z - mean) * rstd * g.z + bb.z;
    o4.w = (v.w - mean) * rstd * g.w + bb.w;
    size_t idx = (size_t)row * DIM + t * 4;
    if (out) *(float4*)(out + idx) = o4;
    if (ohi) {
        uint2 uh, ul;
        split2(o4.x, o4.y, uh.x, ul.x);
        split2(o4.z, o4.w, uh.y, ul.y);
        *(uint2*)(ohi + idx) = uh;
        *(uint2*)(olo + idx) = ul;
    }
}

// ---------------- mma.sync split-bf16 GEMM: C[M,N] = A[M,K] @ W[N,K]^T ----------------
// CTA 128x128, 8 warps (warp tile 32x64), K-chunk 32, 3-stage cp.async, 2 CTAs/SM.
// EPI: 1 = bias+silu -> bf16 hi/lo ; 2 = bias+res -> fp32 ; 3 = bias -> bf16 hi/lo
static constexpr int G_STAGE = 32768;   // Ah(8K) Al(8K) Bh(8K) Bl(8K)
static constexpr int G_SMEM = 3 * G_STAGE;

template<int EPI>
__global__ void __launch_bounds__(256, 2)
gemm_mma(const __nv_bfloat16* __restrict__ Ah, const __nv_bfloat16* __restrict__ Al,
         const __nv_bfloat16* __restrict__ Bh, const __nv_bfloat16* __restrict__ Bl,
         const float* __restrict__ bias, const float* __restrict__ res,
         float* __restrict__ C, __nv_bfloat16* __restrict__ Chi,
         __nv_bfloat16* __restrict__ Clo, int N, int K)
{
    extern __shared__ char sm[];
    const int tid = threadIdx.x;
    const int wid = tid >> 5, lane = tid & 31;
    const int bm = blockIdx.y * 128, bn = blockIdx.x * 128;
    const int wm = (wid & 3) * 32, wn = (wid >> 2) * 64;
    const uint32_t sb = smem_u32(sm);

    float acc[2][8][4];
    #pragma unroll
    for (int i = 0; i < 2; i++)
        #pragma unroll
        for (int j = 0; j < 8; j++)
            #pragma unroll
            for (int d = 0; d < 4; d++) acc[i][j][d] = 0.f;

    const int r_ld = tid >> 1;           // 0..127
    const int s_ld = (tid & 1) * 2;      // seg base 0 or 2
    const __nv_bfloat16* gA[2] = {Ah, Al};
    const __nv_bfloat16* gB[2] = {Bh, Bl};

    auto issue = [&](int c) {
        uint32_t st = sb + (uint32_t)(c % 3) * G_STAGE;
        int k0 = c * 32;
        #pragma unroll
        for (int t = 0; t < 2; t++) {
            const __nv_bfloat16* A = gA[t];
            const __nv_bfloat16* B = gB[t];
            uint32_t dA = st + t * 8192;
            uint32_t dB = st + 16384 + t * 8192;
            #pragma unroll
            for (int j = 0; j < 2; j++) {
                int s = s_ld + j;
                uint32_t o = off32(r_ld, s);
                cp16(dA + o, A + (size_t)(bm + r_ld) * K + k0 + s * 8);
                cp16(dB + o, B + (size_t)(bn + r_ld) * K + k0 + s * 8);
            }
        }
        cp_commit();
    };

    const int NC = K / 32;
    issue(0);
    issue(1);
    issue(2);

    for (int c = 0; c < NC; c++) {
        if (c + 2 < NC) cp_wait<2>(); else if (c + 1 < NC) cp_wait<1>(); else cp_wait<0>();
        __syncthreads();
        uint32_t st = sb + (uint32_t)(c % 3) * G_STAGE;
        #pragma unroll
        for (int ks = 0; ks < 2; ks++) {
            uint32_t a_h[8], a_l[8];
            #pragma unroll
            for (int mt = 0; mt < 2; mt++) {
                int row = wm + mt * 16 + (lane & 7) + ((lane >> 3) & 1) * 8;
                int seg = ks * 2 + (lane >> 4);
                uint32_t oa = off32(row, seg);
                ldm_x4(a_h + mt * 4, st + oa);
                ldm_x4(a_l + mt * 4, st + 8192 + oa);
            }
            #pragma unroll
            for (int ntp = 0; ntp < 4; ntp++) {
                int row = wn + ntp * 16 + (lane & 7) + ((lane >> 4) & 1) * 8;
                int seg = ks * 2 + ((lane >> 3) & 1);
                uint32_t ob = off32(row, seg);
                uint32_t bh4[4], bl4[4];
                ldm_x4(bh4, st + 16384 + ob);
                ldm_x4(bl4, st + 24576 + ob);
                // pass 1: Ah*Bh  (4 independent accs between same-acc reuse)
                #pragma unroll
                for (int half = 0; half < 2; half++)
                    #pragma unroll
                    for (int mt = 0; mt < 2; mt++)
                        mma_bf16(acc[mt][ntp * 2 + half], a_h + mt * 4, bh4 + half * 2);
                // pass 2: Ah*Bl
                #pragma unroll
                for (int half = 0; half < 2; half++)
                    #pragma unroll
                    for (int mt = 0; mt < 2; mt++)
                        mma_bf16(acc[mt][ntp * 2 + half], a_h + mt * 4, bl4 + half * 2);
                // pass 3: Al*Bh
                #pragma unroll
                for (int half = 0; half < 2; half++)
                    #pragma unroll
                    for (int mt = 0; mt < 2; mt++)
                        mma_bf16(acc[mt][ntp * 2 + half], a_l + mt * 4, bh4 + half * 2);
            }
        }
        __syncthreads();
        if (c + 3 < NC) issue(c + 3);
    }

    // epilogue (direct reg->global)
    #pragma unroll
    for (int mt = 0; mt < 2; mt++) {
        int r0 = bm + wm + mt * 16 + (lane >> 2);
        #pragma unroll
        for (int nt = 0; nt < 8; nt++) {
            int col = bn + wn + nt * 8 + (lane & 3) * 2;
            float b0 = bias[col], b1 = bias[col + 1];
            float* a = acc[mt][nt];
            if (EPI == 3) {
                uint32_t h0, l0, h1, l1;
                split2(a[0] + b0, a[1] + b1, h0, l0);
                split2(a[2] + b0, a[3] + b1, h1, l1);
                *(uint32_t*)(Chi + (size_t)r0 * N + col) = h0;
                *(uint32_t*)(Clo + (size_t)r0 * N + col) = l0;
                *(uint32_t*)(Chi + (size_t)(r0 + 8) * N + col) = h1;
                *(uint32_t*)(Clo + (size_t)(r0 + 8) * N + col) = l1;
            } else if (EPI == 1) {
                float v0 = a[0] + b0, v1 = a[1] + b1, v2 = a[2] + b0, v3 = a[3] + b1;
                v0 = v0 / (1.f + __expf(-v0));
                v1 = v1 / (1.f + __expf(-v1));
                v2 = v2 / (1.f + __expf(-v2));
                v3 = v3 / (1.f + __expf(-v3));
                uint32_t h0, l0, h1, l1;
                split2(v0, v1, h0, l0);
                split2(v2, v3, h1, l1);
                *(uint32_t*)(Chi + (size_t)r0 * N + col) = h0;
                *(uint32_t*)(Clo + (size_t)r0 * N + col) = l0;
                *(uint32_t*)(Chi + (size_t)(r0 + 8) * N + col) = h1;
                *(uint32_t*)(Clo + (size_t)(r0 + 8) * N + col) = l1;
            } else {
                float2 p0, p1;
                float2 rr0 = *(const float2*)(res + (size_t)r0 * N + col);
                float2 rr1 = *(const float2*)(res + (size_t)(r0 + 8) * N + col);
                p0.x = a[0] + b0 + rr0.x; p0.y = a[1] + b1 + rr0.y;
                p1.x = a[2] + b0 + rr1.x; p1.y = a[3] + b1 + rr1.y;
                *(float2*)(C + (size_t)r0 * N + col) = p0;
                *(float2*)(C + (size_t)(r0 + 8) * N + col) = p1;
            }
        }
    }
}

// ---------------- Flash attention via mma.sync (reads fused QKV buffer) ----------------
// grid: (SEQ/64, NH, B); 128 thr (4 warps, 16 q-rows each), 2 CTAs/SM.
// smem: Qhi 8K @0, Qlo 8K @8192; KV 3 stages @16384, stride 24576: Kh, Kl(+8192), Vh(+16384)
static constexpr int A_SMEM = 16384 + 3 * 24576;   // 90112

__global__ void __launch_bounds__(128, 2)
attn_mma(const __nv_bfloat16* __restrict__ qkvh, const __nv_bfloat16* __restrict__ qkvl,
         float* __restrict__ out)
{
    extern __shared__ char sm[];
    const int tid = threadIdx.x;
    const int wid = tid >> 5, lane = tid & 31;
    const int h = blockIdx.y, b = blockIdx.z;
    const int tok0 = b * SEQ + blockIdx.x * 64;
    const uint32_t sb = smem_u32(sm);

    // issue Q (group 0): 64 rows x 128B, hi+lo ; Q at col h*64, row-stride NQKV
    {
        int r = tid >> 1;
        size_t qrow = (size_t)(tok0 + r) * NQKV + h * HD;
        #pragma unroll
        for (int j = 0; j < 4; j++) {
            int s = (tid & 1) * 4 + j;
            uint32_t o = off64(r, s);
            cp16(sb + o, qkvh + qrow + s * 8);
            cp16(sb + 8192 + o, qkvl + qrow + s * 8);
        }
        cp_commit();
    }
    auto issueKV = [&](int kb) {
        uint32_t st = sb + 16384 + (uint32_t)(kb % 3) * 24576;
        int r = tid >> 1;
        size_t kvrow = (size_t)(b * SEQ + kb * 64 + r) * NQKV + h * HD;
        #pragma unroll
        for (int j = 0; j < 4; j++) {
            int s = (tid & 1) * 4 + j;
            uint32_t o = off64(r, s);
            cp16(st + o, qkvh + kvrow + 1024 + s * 8);          // K hi
            cp16(st + 8192 + o, qkvl + kvrow + 1024 + s * 8);   // K lo
            cp16(st + 16384 + o, qkvh + kvrow + 2048 + s * 8);  // V hi
        }
        cp_commit();
    };
    issueKV(0);
    issueKV(1);
    issueKV(2);

    cp_wait<2>(); // Q + KV0 done
    __syncthreads();

    // Q fragments (registers, reused all blocks)
    uint32_t qf[2][4][4];
    {
        int row = wid * 16 + (lane & 7) + ((lane >> 3) & 1) * 8;
        #pragma unroll
        for (int ks = 0; ks < 4; ks++) {
            int seg = ks * 2 + (lane >> 4);
            uint32_t o = off64(row, seg);
            ldm_x4(qf[0][ks], sb + o);
            ldm_x4(qf[1][ks], sb + 8192 + o);
        }
    }

    float o_acc[8][4];
    #pragma unroll
    for (int i = 0; i < 8; i++)
        #pragma unroll
        for (int d = 0; d < 4; d++) o_acc[i][d] = 0.f;
    float runA = -INFINITY, runB = -INFINITY, lA = 0.f, lB = 0.f;

    const int NKB = SEQ / 64;
    for (int kb = 0; kb < NKB; kb++) {
        uint32_t st = sb + 16384 + (uint32_t)(kb % 3) * 24576;
        // ---- scores S[16,64] ----
        float s[8][4];
        #pragma unroll
        for (int i = 0; i < 8; i++)
            #pragma unroll
            for (int d = 0; d < 4; d++) s[i][d] = 0.f;
        #pragma unroll
        for (int ks = 0; ks < 4; ks++) {
            #pragma unroll
            for (int ntp = 0; ntp < 4; ntp++) {
                int row = ntp * 16 + (lane & 7) + ((lane >> 4) & 1) * 8;
                int seg = ks * 2 + ((lane >> 3) & 1);
                uint32_t ob = off64(row, seg);
                uint32_t bh4[4], bl4[4];
                ldm_x4(bh4, st + ob);
                ldm_x4(bl4, st + 8192 + ob);
                #pragma unroll
                for (int half = 0; half < 2; half++)
                    mma_bf16(s[ntp * 2 + half], qf[0][ks], bh4 + half * 2);
                #pragma unroll
                for (int half = 0; half < 2; half++)
                    mma_bf16(s[ntp * 2 + half], qf[1][ks], bh4 + half * 2);
                #pragma unroll
                for (int half = 0; half < 2; half++)
                    mma_bf16(s[ntp * 2 + half], qf[0][ks], bl4 + half * 2);
            }
        }
        // ---- online softmax (rows: A = lane>>2, B = +8) ----
        float mA = -INFINITY, mB = -INFINITY;
        #pragma unroll
        for (int nt = 0; nt < 8; nt++) {
            mA = fmaxf(mA, fmaxf(s[nt][0], s[nt][1]));
            mB = fmaxf(mB, fmaxf(s[nt][2], s[nt][3]));
        }
        mA = fmaxf(mA, __shfl_xor_sync(0xffffffffu, mA, 1));
        mA = fmaxf(mA, __shfl_xor_sync(0xffffffffu, mA, 2));
        mB = fmaxf(mB, __shfl_xor_sync(0xffffffffu, mB, 1));
        mB = fmaxf(mB, __shfl_xor_sync(0xffffffffu, mB, 2));
        float nA = fmaxf(runA, mA), nB = fmaxf(runB, mB);
        float cA = __expf(runA - nA), cB = __expf(runB - nB);
        runA = nA; runB = nB;
        lA *= cA; lB *= cB;
        #pragma unroll
        for (int nt = 0; nt < 8; nt++) {
            o_acc[nt][0] *= cA; o_acc[nt][1] *= cA;
            o_acc[nt][2] *= cB; o_acc[nt][3] *= cB;
        }
        float sumA = 0.f, sumB = 0.f;
        #pragma unroll
        for (int nt = 0; nt < 8; nt++) {
            s[nt][0] = __expf(s[nt][0] - nA); sumA += s[nt][0];
            s[nt][1] = __expf(s[nt][1] - nA); sumA += s[nt][1];
            s[nt][2] = __expf(s[nt][2] - nB); sumB += s[nt][2];
            s[nt][3] = __expf(s[nt][3] - nB); sumB += s[nt][3];
        }
        lA += sumA; lB += sumB;
        // ---- P (bf16 A-frags, pure register repack) ----
        uint32_t pf[4][4];
        #pragma unroll
        for (int j = 0; j < 4; j++) {
            pf[j][0] = pk(s[2*j][0],   s[2*j][1]);
            pf[j][1] = pk(s[2*j][2],   s[2*j][3]);
            pf[j][2] = pk(s[2*j+1][0], s[2*j+1][1]);
            pf[j][3] = pk(s[2*j+1][2], s[2*j+1][3]);
        }
        // ---- O += P @ V ----
        #pragma unroll
        for (int ks = 0; ks < 4; ks++) {
            #pragma unroll
            for (int ntp = 0; ntp < 4; ntp++) {
                int row = ks * 16 + (lane & 7) + ((lane >> 3) & 1) * 8;
                int seg = ntp * 2 + (lane >> 4);
                uint32_t vb[4];
                ldm_x4t(vb, st + 16384 + off64(row, seg));
                mma_bf16(o_acc[ntp * 2 + 0], pf[ks], vb + 0);
                mma_bf16(o_acc[ntp * 2 + 1], pf[ks], vb + 2);
            }
        }
        __syncthreads();
        if (kb + 3 < NKB) issueKV(kb + 3);
        if (kb + 1 < NKB) {
            if (kb + 3 < NKB) cp_wait<2>();
            else if (kb + 2 < NKB) cp_wait<1>();
            else cp_wait<0>();
            __syncthreads();
        }
    }

    // finalize: row sums live in quads
    lA += __shfl_xor_sync(0xffffffffu, lA, 1);
    lA += __shfl_xor_sync(0xffffffffu, lA, 2);
    lB += __shfl_xor_sync(0xffffffffu, lB, 1);
    lB += __shfl_xor_sync(0xffffffffu, lB, 2);
    float iA = 1.f / lA, iB = 1.f / lB;
    int rowA = tok0 + wid * 16 + (lane >> 2);
    #pragma unroll
    for (int nt = 0; nt < 8; nt++) {
        int col = h * HD + nt * 8 + (lane & 3) * 2;
        float2 p0 = {o_acc[nt][0] * iA, o_acc[nt][1] * iA};
        float2 p1 = {o_acc[nt][2] * iB, o_acc[nt][3] * iB};
        *(float2*)(out + (size_t)rowA * DIM + col) = p0;
        *(float2*)(out + (size_t)(rowA + 8) * DIM + col) = p1;
    }
}

// ---------------- launch ----------------
extern "C" void kernel_launch(void* const* d_in, const int* in_sizes, int n_in,
                              void* d_out, int out_size)
{
    (void)in_sizes; (void)n_in; (void)out_size;
    const float* x   = (const float*)d_in[0];
    const float* Wq  = (const float*)d_in[1];
    const float* bq  = (const float*)d_in[2];
    const float* Wk  = (const float*)d_in[3];
    const float* bk  = (const float*)d_in[4];
    const float* Wv  = (const float*)d_in[5];
    const float* bv  = (const float*)d_in[6];
    const float* g1  = (const float*)d_in[7];
    const float* b1  = (const float*)d_in[8];
    const float* g2  = (const float*)d_in[9];
    const float* b2  = (const float*)d_in[10];
    const float* W1  = (const float*)d_in[11];
    const float* bf1 = (const float*)d_in[12];
    const float* W2  = (const float*)d_in[13];
    const float* bf2 = (const float*)d_in[14];

    float *xn, *attn, *bqkv;
    cudaGetSymbolAddress((void**)&xn,   g_xn);
    cudaGetSymbolAddress((void**)&attn, g_attn);
    cudaGetSymbolAddress((void**)&bqkv, g_bqkv);

    __nv_bfloat16 *xnh, *xnl, *qkvh, *qkvl, *hh, *hl, *f1h, *f1l;
    __nv_bfloat16 *wqkvh, *wqkvl, *w1h, *w1l, *w2h, *w2l;
    cudaGetSymbolAddress((void**)&xnh,   g_xn_hi);   cudaGetSymbolAddress((void**)&xnl,   g_xn_lo);
    cudaGetSymbolAddress((void**)&qkvh,  g_qkv_hi);  cudaGetSymbolAddress((void**)&qkvl,  g_qkv_lo);
    cudaGetSymbolAddress((void**)&hh,    g_h_hi);    cudaGetSymbolAddress((void**)&hl,    g_h_lo);
    cudaGetSymbolAddress((void**)&f1h,   g_ff1_hi);  cudaGetSymbolAddress((void**)&f1l,   g_ff1_lo);
    cudaGetSymbolAddress((void**)&wqkvh, g_wqkv_hi); cudaGetSymbolAddress((void**)&wqkvl, g_wqkv_lo);
    cudaGetSymbolAddress((void**)&w1h,   g_w1_hi);   cudaGetSymbolAddress((void**)&w1l,   g_w1_lo);
    cudaGetSymbolAddress((void**)&w2h,   g_w2_hi);   cudaGetSymbolAddress((void**)&w2l,   g_w2_lo);

    cudaFuncSetAttribute(gemm_mma<1>, cudaFuncAttributeMaxDynamicSharedMemorySize, G_SMEM);
    cudaFuncSetAttribute(gemm_mma<2>, cudaFuncAttributeMaxDynamicSharedMemorySize, G_SMEM);
    cudaFuncSetAttribute(gemm_mma<3>, cudaFuncAttributeMaxDynamicSharedMemorySize, G_SMEM);
    cudaFuncSetAttribute(attn_mma,    cudaFuncAttributeMaxDynamicSharedMemorySize, A_SMEM);

    // launch 0: merged weight splits (+ bias concat, Q pre-scaled by 1/8)
    wsplit_all<<<(WS_TOT + 255)/256, 256>>>(Wq, Wk, Wv, W1, W2, bq, bk, bv,
                                            wqkvh, wqkvl, w1h, w1l, w2h, w2l, bqkv);

    // launch 1: xn = LN(x) : fp32 + splits
    ln_kernel<<<NTOK, 256>>>(x, nullptr, g1, b1, xn, xnh, xnl);

    // launch 2: fused QKV projection -> bf16 hi/lo [NTOK, 3072]
    dim3 gQKV(NQKV / 128, NTOK / 128);
    gemm_mma<3><<<gQKV, 256, G_SMEM>>>(xnh, xnl, wqkvh, wqkvl, bqkv, nullptr,
                                       nullptr, qkvh, qkvl, NQKV, DIM);

    // launch 3 (profiled): attention (tensor-core flash)
    attn_mma<<<dim3(SEQ / 64, NH, 2), 128, A_SMEM>>>(qkvh, qkvl, attn);

    // launch 4: h = LN(attn + xn) -> splits
    ln_kernel<<<NTOK, 256>>>(attn, xn, g2, b2, nullptr, hh, hl);

    // launch 5: ff1 = silu(h @ W1^T + bf1) -> bf16 splits
    dim3 gF1(DFF / 128, NTOK / 128);
    gemm_mma<1><<<gF1, 256, G_SMEM>>>(hh, hl, w1h, w1l, bf1, nullptr,
                                      nullptr, f1h, f1l, DFF, DIM);

    // launch 6: out = ff1 @ W2^T + bf2 + xn
    dim3 gF2(DIM / 128, NTOK / 128);
    gemm_mma<2><<<gF2, 256, G_SMEM>>>(f1h, f1l, w2h, w2l, bf2, xn,
                                      (float*)d_out, nullptr, nullptr, DIM, DFF);
}

// round 11
// speedup vs baseline: 5.6894x; 1.0312x over previous
#include <cuda_runtime.h>
#include <cuda_bf16.h>
#include <math.h>
#include <stdint.h>

#define NTOK 4096          // B*S
#define SEQ  2048
#define DIM  1024
#define NH   16
#define HD   64
#define DFF  4096
#define NQKV 3072

#define QSCALE (0.125f * 1.44269504088896f)   // 1/sqrt(64) * log2(e)

// ---------------- scratch (device globals; no allocs allowed) ----------------
__device__ float g_xn[NTOK * DIM];
__device__ float g_attn[NTOK * DIM];
__device__ float g_bqkv[NQKV];

__device__ __nv_bfloat16 g_xn_hi[NTOK * DIM],   g_xn_lo[NTOK * DIM];
__device__ __nv_bfloat16 g_qkv_hi[NTOK * NQKV], g_qkv_lo[NTOK * NQKV];
__device__ __nv_bfloat16 g_h_hi[NTOK * DIM],    g_h_lo[NTOK * DIM];
__device__ __nv_bfloat16 g_ff1_hi[NTOK * DFF],  g_ff1_lo[NTOK * DFF];
__device__ __nv_bfloat16 g_wqkv_hi[NQKV * DIM], g_wqkv_lo[NQKV * DIM];
__device__ __nv_bfloat16 g_w1_hi[DFF * DIM],    g_w1_lo[DFF * DIM];
__device__ __nv_bfloat16 g_w2_hi[DIM * DFF],    g_w2_lo[DIM * DFF];

// ---------------- PTX helpers (family-portable sm_80-era ISA) ----------------
__device__ __forceinline__ uint32_t smem_u32(const void* p) {
    uint32_t a;
    asm("{ .reg .u64 t; cvta.to.shared.u64 t, %1; cvt.u32.u64 %0, t; }" : "=r"(a) : "l"(p));
    return a;
}
__device__ __forceinline__ void cp16(uint32_t dst, const void* src) {
    asm volatile("cp.async.cg.shared.global [%0], [%1], 16;" :: "r"(dst), "l"(src) : "memory");
}
__device__ __forceinline__ void cp_commit() {
    asm volatile("cp.async.commit_group;" ::: "memory");
}
template<int N> __device__ __forceinline__ void cp_wait() {
    asm volatile("cp.async.wait_group %0;" :: "n"(N) : "memory");
}
__device__ __forceinline__ void ldm_x4(uint32_t* r, uint32_t addr) {
    asm volatile("ldmatrix.sync.aligned.m8n8.x4.shared.b16 {%0,%1,%2,%3}, [%4];"
        : "=r"(r[0]), "=r"(r[1]), "=r"(r[2]), "=r"(r[3]) : "r"(addr));
}
__device__ __forceinline__ void ldm_x4t(uint32_t* r, uint32_t addr) {
    asm volatile("ldmatrix.sync.aligned.m8n8.x4.trans.shared.b16 {%0,%1,%2,%3}, [%4];"
        : "=r"(r[0]), "=r"(r[1]), "=r"(r[2]), "=r"(r[3]) : "r"(addr));
}
__device__ __forceinline__ void mma_bf16(float* d, const uint32_t* a, const uint32_t* b) {
    asm volatile(
        "mma.sync.aligned.m16n8k16.row.col.f32.bf16.bf16.f32 "
        "{%0,%1,%2,%3}, {%4,%5,%6,%7}, {%8,%9}, {%0,%1,%2,%3};"
        : "+f"(d[0]), "+f"(d[1]), "+f"(d[2]), "+f"(d[3])
        : "r"(a[0]), "r"(a[1]), "r"(a[2]), "r"(a[3]), "r"(b[0]), "r"(b[1]));
}
__device__ __forceinline__ uint32_t pk(float lo, float hi) {
    __nv_bfloat162 t = __floats2bfloat162_rn(lo, hi);
    return *(uint32_t*)&t;
}
__device__ __forceinline__ void split2(float v0, float v1, uint32_t& h, uint32_t& l) {
    __nv_bfloat16 h0 = __float2bfloat16(v0), h1 = __float2bfloat16(v1);
    h = pk(__bfloat162float(h0), __bfloat162float(h1));
    l = pk(v0 - __bfloat162float(h0), v1 - __bfloat162float(h1));
}
// 32-col bf16 tile (64B rows, 4x16B segs)
__device__ __forceinline__ uint32_t off32(int r, int s) {
    return (uint32_t)(r * 64 + ((s ^ ((r >> 1) & 3)) << 4));
}
// 64-col bf16 tile (128B rows, 8x16B segs)
__device__ __forceinline__ uint32_t off64(int r, int s) {
    return (uint32_t)(r * 128 + ((s ^ (r & 7)) << 4));
}

// ---------------- merged weight split (+ QKV bias concat, Q pre-scaled) ----------------
static constexpr int WS_QKV = NQKV * DIM / 4;
static constexpr int WS_W1  = DFF * DIM / 4;
static constexpr int WS_W2  = DIM * DFF / 4;
static constexpr int WS_B   = NQKV / 4;
static constexpr int WS_TOT = WS_QKV + WS_W1 + WS_W2 + WS_B;

__global__ __launch_bounds__(256)
void wsplit_all(const float* __restrict__ Wq, const float* __restrict__ Wk,
                const float* __restrict__ Wv, const float* __restrict__ W1,
                const float* __restrict__ W2, const float* __restrict__ bq,
                const float* __restrict__ bk, const float* __restrict__ bv,
                __nv_bfloat16* __restrict__ qkvh, __nv_bfloat16* __restrict__ qkvl,
                __nv_bfloat16* __restrict__ w1h, __nv_bfloat16* __restrict__ w1l,
                __nv_bfloat16* __restrict__ w2h, __nv_bfloat16* __restrict__ w2l,
                float* __restrict__ bqkv)
{
    int i = blockIdx.x * 256 + threadIdx.x;
    if (i >= WS_TOT) return;
    if (i < WS_QKV) {
        int e = i * 4;
        int r = e >> 10;
        float sc = 1.0f;
        const float* src;
        if (r < 1024)      { src = Wq + e;                sc = QSCALE; }
        else if (r < 2048) { src = Wk + (e - 1024*1024); }
        else               { src = Wv + (e - 2048*1024); }
        float4 v = *(const float4*)src;
        v.x *= sc; v.y *= sc; v.z *= sc; v.w *= sc;
        uint2 uh, ul;
        split2(v.x, v.y, uh.x, ul.x);
        split2(v.z, v.w, uh.y, ul.y);
        *(uint2*)(qkvh + e) = uh;
        *(uint2*)(qkvl + e) = ul;
    } else if (i < WS_QKV + WS_W1) {
        int e = (i - WS_QKV) * 4;
        float4 v = *(const float4*)(W1 + e);
        uint2 uh, ul;
        split2(v.x, v.y, uh.x, ul.x);
        split2(v.z, v.w, uh.y, ul.y);
        *(uint2*)(w1h + e) = uh;
        *(uint2*)(w1l + e) = ul;
    } else if (i < WS_QKV + WS_W1 + WS_W2) {
        int e = (i - WS_QKV - WS_W1) * 4;
        float4 v = *(const float4*)(W2 + e);
        uint2 uh, ul;
        split2(v.x, v.y, uh.x, ul.x);
        split2(v.z, v.w, uh.y, ul.y);
        *(uint2*)(w2h + e) = uh;
        *(uint2*)(w2l + e) = ul;
    } else {
        int e = (i - WS_QKV - WS_W1 - WS_W2) * 4;
        #pragma unroll
        for (int j = 0; j < 4; j++) {
            int c = e + j;
            float b = (c < 1024) ? QSCALE * bq[c]
                    : (c < 2048) ? bk[c - 1024] : bv[c - 2048];
            bqkv[c] = b;
        }
    }
}

// ---------------- LayerNorm (optional residual; fp32 out + bf16 splits) ----------------
__global__ __launch_bounds__(256)
void ln_kernel(const float* __restrict__ x, const float* __restrict__ res,
               const float* __restrict__ gamma, const float* __restrict__ beta,
               float* __restrict__ out, __nv_bfloat16* __restrict__ ohi,
               __nv_bfloat16* __restrict__ olo)
{
    int row = blockIdx.x;
    int t = threadIdx.x;
    const float4* xr = (const float4*)(x + (size_t)row * DIM);
    float4 v = xr[t];
    if (res) {
        const float4* rr = (const float4*)(res + (size_t)row * DIM);
        float4 r = rr[t];
        v.x += r.x; v.y += r.y; v.z += r.z; v.w += r.w;
    }
    float s  = v.x + v.y + v.z + v.w;
    float s2 = v.x*v.x + v.y*v.y + v.z*v.z + v.w*v.w;
    #pragma unroll
    for (int o = 16; o > 0; o >>= 1) {
        s  += __shfl_down_sync(0xffffffffu, s,  o);
        s2 += __shfl_down_sync(0xffffffffu, s2, o);
    }
    __shared__ float ss[8], ss2[8];
    __shared__ float mean_s, rstd_s;
    if ((t & 31) == 0) { ss[t >> 5] = s; ss2[t >> 5] = s2; }
    __syncthreads();
    if (t == 0) {
        float a = 0.f, b = 0.f;
        #pragma unroll
        for (int i = 0; i < 8; i++) { a += ss[i]; b += ss2[i]; }
        float mean = a * (1.0f / DIM);
        float var  = b * (1.0f / DIM) - mean * mean;
        mean_s = mean;
        rstd_s = rsqrtf(var + 1e-5f);
    }
    __syncthreads();
    float mean = mean_s, rstd = rstd_s;
    float4 g = ((const float4*)gamma)[t];
    float4 bb = ((const float4*)beta)[t];
    float4 o4;
    o4.x = (v.x - mean) * rstd * g.x + bb.x;
    o4.y = (v.y - mean) * rstd * g.y + bb.y;
    o4.z = (v.z - mean) * rstd * g.z + bb.z;
    o4.w = (v.w - mean) * rstd * g.w + bb.w;
    size_t idx = (size_t)row * DIM + t * 4;
    if (out) *(float4*)(out + idx) = o4;
    if (ohi) {
        uint2 uh, ul;
        split2(o4.x, o4.y, uh.x, ul.x);
        split2(o4.z, o4.w, uh.y, ul.y);
        *(uint2*)(ohi + idx) = uh;
        *(uint2*)(olo + idx) = ul;
    }
}

// ---------------- mma.sync split-bf16 GEMM: C[M,N] = A[M,K] @ W[N,K]^T ----------------
// CTA 128x128, 8 warps (warp tile 32x64), K-chunk 32, 3-stage cp.async, 2 CTAs/SM.
// Inner loop pass-structured: same-accumulator reuse distance = 8 MMAs.
// EPI: 1 = bias+silu -> bf16 hi/lo ; 2 = bias+res -> fp32 ; 3 = bias -> bf16 hi/lo
static constexpr int G_STAGE = 32768;   // Ah(8K) Al(8K) Bh(8K) Bl(8K)
static constexpr int G_SMEM = 3 * G_STAGE;

template<int EPI>
__global__ void __launch_bounds__(256, 2)
gemm_mma(const __nv_bfloat16* __restrict__ Ah, const __nv_bfloat16* __restrict__ Al,
         const __nv_bfloat16* __restrict__ Bh, const __nv_bfloat16* __restrict__ Bl,
         const float* __restrict__ bias, const float* __restrict__ res,
         float* __restrict__ C, __nv_bfloat16* __restrict__ Chi,
         __nv_bfloat16* __restrict__ Clo, int N, int K)
{
    extern __shared__ char sm[];
    const int tid = threadIdx.x;
    const int wid = tid >> 5, lane = tid & 31;
    const int bm = blockIdx.y * 128, bn = blockIdx.x * 128;
    const int wm = (wid & 3) * 32, wn = (wid >> 2) * 64;
    const uint32_t sb = smem_u32(sm);

    float acc[2][8][4];
    #pragma unroll
    for (int i = 0; i < 2; i++)
        #pragma unroll
        for (int j = 0; j < 8; j++)
            #pragma unroll
            for (int d = 0; d < 4; d++) acc[i][j][d] = 0.f;

    const int r_ld = tid >> 1;
    const int s_ld = (tid & 1) * 2;
    const __nv_bfloat16* gA[2] = {Ah, Al};
    const __nv_bfloat16* gB[2] = {Bh, Bl};

    auto issue = [&](int c) {
        uint32_t st = sb + (uint32_t)(c % 3) * G_STAGE;
        int k0 = c * 32;
        #pragma unroll
        for (int t = 0; t < 2; t++) {
            const __nv_bfloat16* A = gA[t];
            const __nv_bfloat16* B = gB[t];
            uint32_t dA = st + t * 8192;
            uint32_t dB = st + 16384 + t * 8192;
            #pragma unroll
            for (int j = 0; j < 2; j++) {
                int s = s_ld + j;
                uint32_t o = off32(r_ld, s);
                cp16(dA + o, A + (size_t)(bm + r_ld) * K + k0 + s * 8);
                cp16(dB + o, B + (size_t)(bn + r_ld) * K + k0 + s * 8);
            }
        }
        cp_commit();
    };

    const int NC = K / 32;
    issue(0);
    issue(1);
    issue(2);

    for (int c = 0; c < NC; c++) {
        if (c + 2 < NC) cp_wait<2>(); else if (c + 1 < NC) cp_wait<1>(); else cp_wait<0>();
        __syncthreads();
        uint32_t st = sb + (uint32_t)(c % 3) * G_STAGE;
        #pragma unroll
        for (int ks = 0; ks < 2; ks++) {
            uint32_t a_h[8], a_l[8];
            #pragma unroll
            for (int mt = 0; mt < 2; mt++) {
                int row = wm + mt * 16 + (lane & 7) + ((lane >> 3) & 1) * 8;
                int seg = ks * 2 + (lane >> 4);
                uint32_t oa = off32(row, seg);
                ldm_x4(a_h + mt * 4, st + oa);
                ldm_x4(a_l + mt * 4, st + 8192 + oa);
            }
            #pragma unroll
            for (int np = 0; np < 2; np++) {      // pair of ntp
                uint32_t bh[8], bl[8];
                #pragma unroll
                for (int p = 0; p < 2; p++) {
                    int ntp = np * 2 + p;
                    int row = wn + ntp * 16 + (lane & 7) + ((lane >> 4) & 1) * 8;
                    int seg = ks * 2 + ((lane >> 3) & 1);
                    uint32_t ob = off32(row, seg);
                    ldm_x4(bh + p * 4, st + 16384 + ob);
                    ldm_x4(bl + p * 4, st + 24576 + ob);
                }
                // pass 1 (hh): 8 distinct accumulators
                #pragma unroll
                for (int p = 0; p < 2; p++)
                    #pragma unroll
                    for (int half = 0; half < 2; half++)
                        #pragma unroll
                        for (int mt = 0; mt < 2; mt++)
                            mma_bf16(acc[mt][(np*2+p)*2+half], a_h + mt*4, bh + p*4 + half*2);
                // pass 2 (hl)
                #pragma unroll
                for (int p = 0; p < 2; p++)
                    #pragma unroll
                    for (int half = 0; half < 2; half++)
                        #pragma unroll
                        for (int mt = 0; mt < 2; mt++)
                            mma_bf16(acc[mt][(np*2+p)*2+half], a_h + mt*4, bl + p*4 + half*2);
                // pass 3 (lh)
                #pragma unroll
                for (int p = 0; p < 2; p++)
                    #pragma unroll
                    for (int half = 0; half < 2; half++)
                        #pragma unroll
                        for (int mt = 0; mt < 2; mt++)
                            mma_bf16(acc[mt][(np*2+p)*2+half], a_l + mt*4, bh + p*4 + half*2);
            }
        }
        __syncthreads();
        if (c + 3 < NC) issue(c + 3);
    }

    // epilogue (direct reg->global)
    #pragma unroll
    for (int mt = 0; mt < 2; mt++) {
        int r0 = bm + wm + mt * 16 + (lane >> 2);
        #pragma unroll
        for (int nt = 0; nt < 8; nt++) {
            int col = bn + wn + nt * 8 + (lane & 3) * 2;
            float b0 = bias[col], b1 = bias[col + 1];
            float* a = acc[mt][nt];
            if (EPI == 3) {
                uint32_t h0, l0, h1, l1;
                split2(a[0] + b0, a[1] + b1, h0, l0);
                split2(a[2] + b0, a[3] + b1, h1, l1);
                *(uint32_t*)(Chi + (size_t)r0 * N + col) = h0;
                *(uint32_t*)(Clo + (size_t)r0 * N + col) = l0;
                *(uint32_t*)(Chi + (size_t)(r0 + 8) * N + col) = h1;
                *(uint32_t*)(Clo + (size_t)(r0 + 8) * N + col) = l1;
            } else if (EPI == 1) {
                float v0 = a[0] + b0, v1 = a[1] + b1, v2 = a[2] + b0, v3 = a[3] + b1;
                v0 = v0 / (1.f + __expf(-v0));
                v1 = v1 / (1.f + __expf(-v1));
                v2 = v2 / (1.f + __expf(-v2));
                v3 = v3 / (1.f + __expf(-v3));
                uint32_t h0, l0, h1, l1;
                split2(v0, v1, h0, l0);
                split2(v2, v3, h1, l1);
                *(uint32_t*)(Chi + (size_t)r0 * N + col) = h0;
                *(uint32_t*)(Clo + (size_t)r0 * N + col) = l0;
                *(uint32_t*)(Chi + (size_t)(r0 + 8) * N + col) = h1;
                *(uint32_t*)(Clo + (size_t)(r0 + 8) * N + col) = l1;
            } else {
                float2 p0, p1;
                float2 rr0 = *(const float2*)(res + (size_t)r0 * N + col);
                float2 rr1 = *(const float2*)(res + (size_t)(r0 + 8) * N + col);
                p0.x = a[0] + b0 + rr0.x; p0.y = a[1] + b1 + rr0.y;
                p1.x = a[2] + b0 + rr1.x; p1.y = a[3] + b1 + rr1.y;
                *(float2*)(C + (size_t)r0 * N + col) = p0;
                *(float2*)(C + (size_t)(r0 + 8) * N + col) = p1;
            }
        }
    }
}

// ---------------- Flash attention via mma.sync (reads fused QKV buffer) ----------------
// grid: (SEQ/64, NH, B); 128 thr (4 warps, 16 q-rows each), 3 CTAs/SM.
// Scores are in log2 units (Q pre-scaled by 1/8*log2e) -> exp2f softmax.
// smem: Qhi 8K @0, Qlo 8K @8192; KV 2 stages @16384, stride 24576: Kh, Kl(+8192), Vh(+16384)
static constexpr int A_SMEM = 16384 + 2 * 24576;   // 65536

__global__ void __launch_bounds__(128, 3)
attn_mma(const __nv_bfloat16* __restrict__ qkvh, const __nv_bfloat16* __restrict__ qkvl,
         float* __restrict__ out)
{
    extern __shared__ char sm[];
    const int tid = threadIdx.x;
    const int wid = tid >> 5, lane = tid & 31;
    const int h = blockIdx.y, b = blockIdx.z;
    const int tok0 = b * SEQ + blockIdx.x * 64;
    const uint32_t sb = smem_u32(sm);

    // issue Q (group 0): 64 rows x 128B, hi+lo ; Q at col h*64, row-stride NQKV
    {
        int r = tid >> 1;
        size_t qrow = (size_t)(tok0 + r) * NQKV + h * HD;
        #pragma unroll
        for (int j = 0; j < 4; j++) {
            int s = (tid & 1) * 4 + j;
            uint32_t o = off64(r, s);
            cp16(sb + o, qkvh + qrow + s * 8);
            cp16(sb + 8192 + o, qkvl + qrow + s * 8);
        }
        cp_commit();
    }
    auto issueKV = [&](int kb) {
        uint32_t st = sb + 16384 + (uint32_t)(kb & 1) * 24576;
        int r = tid >> 1;
        size_t kvrow = (size_t)(b * SEQ + kb * 64 + r) * NQKV + h * HD;
        #pragma unroll
        for (int j = 0; j < 4; j++) {
            int s = (tid & 1) * 4 + j;
            uint32_t o = off64(r, s);
            cp16(st + o, qkvh + kvrow + 1024 + s * 8);          // K hi
            cp16(st + 8192 + o, qkvl + kvrow + 1024 + s * 8);   // K lo
            cp16(st + 16384 + o, qkvh + kvrow + 2048 + s * 8);  // V hi
        }
        cp_commit();
    };
    issueKV(0);
    issueKV(1);

    cp_wait<1>(); // Q + KV0 done
    __syncthreads();

    // Q fragments (registers, reused all blocks)
    uint32_t qf[2][4][4];
    {
        int row = wid * 16 + (lane & 7) + ((lane >> 3) & 1) * 8;
        #pragma unroll
        for (int ks = 0; ks < 4; ks++) {
            int seg = ks * 2 + (lane >> 4);
            uint32_t o = off64(row, seg);
            ldm_x4(qf[0][ks], sb + o);
            ldm_x4(qf[1][ks], sb + 8192 + o);
        }
    }

    float o_acc[8][4];
    #pragma unroll
    for (int i = 0; i < 8; i++)
        #pragma unroll
        for (int d = 0; d < 4; d++) o_acc[i][d] = 0.f;
    float runA = -INFINITY, runB = -INFINITY, lA = 0.f, lB = 0.f;

    const int NKB = SEQ / 64;
    for (int kb = 0; kb < NKB; kb++) {
        if (kb > 0) {
            if (kb + 1 < NKB) cp_wait<1>(); else cp_wait<0>();
            __syncthreads();
        }
        uint32_t st = sb + 16384 + (uint32_t)(kb & 1) * 24576;
        // ---- scores S[16,64] (log2 units) ----
        float s[8][4];
        #pragma unroll
        for (int i = 0; i < 8; i++)
            #pragma unroll
            for (int d = 0; d < 4; d++) s[i][d] = 0.f;
        #pragma unroll
        for (int ks = 0; ks < 4; ks++) {
            #pragma unroll
            for (int np = 0; np < 2; np++) {
                uint32_t bh[8], bl[8];
                #pragma unroll
                for (int p = 0; p < 2; p++) {
                    int ntp = np * 2 + p;
                    int row = ntp * 16 + (lane & 7) + ((lane >> 4) & 1) * 8;
                    int seg = ks * 2 + ((lane >> 3) & 1);
                    uint32_t ob = off64(row, seg);
                    ldm_x4(bh + p * 4, st + ob);
                    ldm_x4(bl + p * 4, st + 8192 + ob);
                }
                #pragma unroll
                for (int p = 0; p < 2; p++)
                    #pragma unroll
                    for (int half = 0; half < 2; half++)
                        mma_bf16(s[(np*2+p)*2+half], qf[0][ks], bh + p*4 + half*2);
                #pragma unroll
                for (int p = 0; p < 2; p++)
                    #pragma unroll
                    for (int half = 0; half < 2; half++)
                        mma_bf16(s[(np*2+p)*2+half], qf[1][ks], bh + p*4 + half*2);
                #pragma unroll
                for (int p = 0; p < 2; p++)
                    #pragma unroll
                    for (int half = 0; half < 2; half++)
                        mma_bf16(s[(np*2+p)*2+half], qf[0][ks], bl + p*4 + half*2);
            }
        }
        // ---- online softmax in base 2 (rows: A = lane>>2, B = +8) ----
        float mA = -INFINITY, mB = -INFINITY;
        #pragma unroll
        for (int nt = 0; nt < 8; nt++) {
            mA = fmaxf(mA, fmaxf(s[nt][0], s[nt][1]));
            mB = fmaxf(mB, fmaxf(s[nt][2], s[nt][3]));
        }
        mA = fmaxf(mA, __shfl_xor_sync(0xffffffffu, mA, 1));
        mA = fmaxf(mA, __shfl_xor_sync(0xffffffffu, mA, 2));
        mB = fmaxf(mB, __shfl_xor_sync(0xffffffffu, mB, 1));
        mB = fmaxf(mB, __shfl_xor_sync(0xffffffffu, mB, 2));
        float nA = fmaxf(runA, mA), nB = fmaxf(runB, mB);
        float cA = exp2f(runA - nA), cB = exp2f(runB - nB);
        runA = nA; runB = nB;
        lA *= cA; lB *= cB;
        #pragma unroll
        for (int nt = 0; nt < 8; nt++) {
            o_acc[nt][0] *= cA; o_acc[nt][1] *= cA;
            o_acc[nt][2] *= cB; o_acc[nt][3] *= cB;
        }
        float sumA = 0.f, sumB = 0.f;
        #pragma unroll
        for (int nt = 0; nt < 8; nt++) {
            s[nt][0] = exp2f(s[nt][0] - nA); sumA += s[nt][0];
            s[nt][1] = exp2f(s[nt][1] - nA); sumA += s[nt][1];
            s[nt][2] = exp2f(s[nt][2] - nB); sumB += s[nt][2];
            s[nt][3] = exp2f(s[nt][3] - nB); sumB += s[nt][3];
        }
        lA += sumA; lB += sumB;
        // ---- P (bf16 A-frags, pure register repack) ----
        uint32_t pf[4][4];
        #pragma unroll
        for (int j = 0; j < 4; j++) {
            pf[j][0] = pk(s[2*j][0],   s[2*j][1]);
            pf[j][1] = pk(s[2*j][2],   s[2*j][3]);
            pf[j][2] = pk(s[2*j+1][0], s[2*j+1][1]);
            pf[j][3] = pk(s[2*j+1][2], s[2*j+1][3]);
        }
        // ---- O += P @ V ----
        #pragma unroll
        for (int ks = 0; ks < 4; ks++) {
            #pragma unroll
            for (int ntp = 0; ntp < 4; ntp++) {
                int row = ks * 16 + (lane & 7) + ((lane >> 3) & 1) * 8;
                int seg = ntp * 2 + (lane >> 4);
                uint32_t vb[4];
                ldm_x4t(vb, st + 16384 + off64(row, seg));
                mma_bf16(o_acc[ntp * 2 + 0], pf[ks], vb + 0);
                mma_bf16(o_acc[ntp * 2 + 1], pf[ks], vb + 2);
            }
        }
        __syncthreads();
        if (kb + 2 < NKB) issueKV(kb + 2);
    }

    // finalize: row sums live in quads
    lA += __shfl_xor_sync(0xffffffffu, lA, 1);
    lA += __shfl_xor_sync(0xffffffffu, lA, 2);
    lB += __shfl_xor_sync(0xffffffffu, lB, 1);
    lB += __shfl_xor_sync(0xffffffffu, lB, 2);
    float iA = 1.f / lA, iB = 1.f / lB;
    int rowA = tok0 + wid * 16 + (lane >> 2);
    #pragma unroll
    for (int nt = 0; nt < 8; nt++) {
        int col = h * HD + nt * 8 + (lane & 3) * 2;
        float2 p0 = {o_acc[nt][0] * iA, o_acc[nt][1] * iA};
        float2 p1 = {o_acc[nt][2] * iB, o_acc[nt][3] * iB};
        *(float2*)(out + (size_t)rowA * DIM + col) = p0;
        *(float2*)(out + (size_t)(rowA + 8) * DIM + col) = p1;
    }
}

// ---------------- launch ----------------
extern "C" void kernel_launch(void* const* d_in, const int* in_sizes, int n_in,
                              void* d_out, int out_size)
{
    (void)in_sizes; (void)n_in; (void)out_size;
    const float* x   = (const float*)d_in[0];
    const float* Wq  = (const float*)d_in[1];
    const float* bq  = (const float*)d_in[2];
    const float* Wk  = (const float*)d_in[3];
    const float* bk  = (const float*)d_in[4];
    const float* Wv  = (const float*)d_in[5];
    const float* bv  = (const float*)d_in[6];
    const float* g1  = (const float*)d_in[7];
    const float* b1  = (const float*)d_in[8];
    const float* g2  = (const float*)d_in[9];
    const float* b2  = (const float*)d_in[10];
    const float* W1  = (const float*)d_in[11];
    const float* bf1 = (const float*)d_in[12];
    const float* W2  = (const float*)d_in[13];
    const float* bf2 = (const float*)d_in[14];

    float *xn, *attn, *bqkv;
    cudaGetSymbolAddress((void**)&xn,   g_xn);
    cudaGetSymbolAddress((void**)&attn, g_attn);
    cudaGetSymbolAddress((void**)&bqkv, g_bqkv);

    __nv_bfloat16 *xnh, *xnl, *qkvh, *qkvl, *hh, *hl, *f1h, *f1l;
    __nv_bfloat16 *wqkvh, *wqkvl, *w1h, *w1l, *w2h, *w2l;
    cudaGetSymbolAddress((void**)&xnh,   g_xn_hi);   cudaGetSymbolAddress((void**)&xnl,   g_xn_lo);
    cudaGetSymbolAddress((void**)&qkvh,  g_qkv_hi);  cudaGetSymbolAddress((void**)&qkvl,  g_qkv_lo);
    cudaGetSymbolAddress((void**)&hh,    g_h_hi);    cudaGetSymbolAddress((void**)&hl,    g_h_lo);
    cudaGetSymbolAddress((void**)&f1h,   g_ff1_hi);  cudaGetSymbolAddress((void**)&f1l,   g_ff1_lo);
    cudaGetSymbolAddress((void**)&wqkvh, g_wqkv_hi); cudaGetSymbolAddress((void**)&wqkvl, g_wqkv_lo);
    cudaGetSymbolAddress((void**)&w1h,   g_w1_hi);   cudaGetSymbolAddress((void**)&w1l,   g_w1_lo);
    cudaGetSymbolAddress((void**)&w2h,   g_w2_hi);   cudaGetSymbolAddress((void**)&w2l,   g_w2_lo);

    cudaFuncSetAttribute(gemm_mma<1>, cudaFuncAttributeMaxDynamicSharedMemorySize, G_SMEM);
    cudaFuncSetAttribute(gemm_mma<2>, cudaFuncAttributeMaxDynamicSharedMemorySize, G_SMEM);
    cudaFuncSetAttribute(gemm_mma<3>, cudaFuncAttributeMaxDynamicSharedMemorySize, G_SMEM);
    cudaFuncSetAttribute(attn_mma,    cudaFuncAttributeMaxDynamicSharedMemorySize, A_SMEM);

    // launch 0: merged weight splits (+ bias concat, Q pre-scaled by 1/8*log2e)
    wsplit_all<<<(WS_TOT + 255)/256, 256>>>(Wq, Wk, Wv, W1, W2, bq, bk, bv,
                                            wqkvh, wqkvl, w1h, w1l, w2h, w2l, bqkv);

    // launch 1: xn = LN(x) : fp32 + splits
    ln_kernel<<<NTOK, 256>>>(x, nullptr, g1, b1, xn, xnh, xnl);

    // launch 2: fused QKV projection -> bf16 hi/lo [NTOK, 3072]
    dim3 gQKV(NQKV / 128, NTOK / 128);
    gemm_mma<3><<<gQKV, 256, G_SMEM>>>(xnh, xnl, wqkvh, wqkvl, bqkv, nullptr,
                                       nullptr, qkvh, qkvl, NQKV, DIM);

    // launch 3: attention (tensor-core flash, 3 CTAs/SM, exp2 softmax)
    attn_mma<<<dim3(SEQ / 64, NH, 2), 128, A_SMEM>>>(qkvh, qkvl, attn);

    // launch 4: h = LN(attn + xn) -> splits
    ln_kernel<<<NTOK, 256>>>(attn, xn, g2, b2, nullptr, hh, hl);

    // launch 5: ff1 = silu(h @ W1^T + bf1) -> bf16 splits
    dim3 gF1(DFF / 128, NTOK / 128);
    gemm_mma<1><<<gF1, 256, G_SMEM>>>(hh, hl, w1h, w1l, bf1, nullptr,
                                      nullptr, f1h, f1l, DFF, DIM);

    // launch 6: out = ff1 @ W2^T + bf2 + xn
    dim3 gF2(DIM / 128, NTOK / 128);
    gemm_mma<2><<<gF2, 256, G_SMEM>>>(f1h, f1l, w2h, w2l, bf2, xn,
                                      (float*)d_out, nullptr, nullptr, DIM, DFF);
}

// round 12
// speedup vs baseline: 5.9528x; 1.0463x over previous
#include <cuda_runtime.h>
#include <cuda_bf16.h>
#include <math.h>
#include <stdint.h>

#define NTOK 4096          // B*S
#define SEQ  2048
#define DIM  1024
#define NH   16
#define HD   64
#define DFF  4096
#define NQKV 3072

#define QSCALE (0.125f * 1.44269504088896f)   // 1/sqrt(64) * log2(e)

// ---------------- scratch (device globals; no allocs allowed) ----------------
__device__ float g_xn[NTOK * DIM];
__device__ float g_attn[NTOK * DIM];
__device__ float g_bqkv[NQKV];

__device__ __nv_bfloat16 g_xn_hi[NTOK * DIM],   g_xn_lo[NTOK * DIM];
__device__ __nv_bfloat16 g_qkv_hi[NTOK * NQKV];
__device__ __nv_bfloat16 g_h_hi[NTOK * DIM],    g_h_lo[NTOK * DIM];
__device__ __nv_bfloat16 g_ff1_hi[NTOK * DFF],  g_ff1_lo[NTOK * DFF];
__device__ __nv_bfloat16 g_wqkv_hi[NQKV * DIM];
__device__ __nv_bfloat16 g_w1_hi[DFF * DIM],    g_w1_lo[DFF * DIM];
__device__ __nv_bfloat16 g_w2_hi[DIM * DFF],    g_w2_lo[DIM * DFF];

// ---------------- PTX helpers (family-portable sm_80-era ISA) ----------------
__device__ __forceinline__ uint32_t smem_u32(const void* p) {
    uint32_t a;
    asm("{ .reg .u64 t; cvta.to.shared.u64 t, %1; cvt.u32.u64 %0, t; }" : "=r"(a) : "l"(p));
    return a;
}
__device__ __forceinline__ void cp16(uint32_t dst, const void* src) {
    asm volatile("cp.async.cg.shared.global [%0], [%1], 16;" :: "r"(dst), "l"(src) : "memory");
}
__device__ __forceinline__ void cp_commit() {
    asm volatile("cp.async.commit_group;" ::: "memory");
}
template<int N> __device__ __forceinline__ void cp_wait() {
    asm volatile("cp.async.wait_group %0;" :: "n"(N) : "memory");
}
__device__ __forceinline__ void ldm_x4(uint32_t* r, uint32_t addr) {
    asm volatile("ldmatrix.sync.aligned.m8n8.x4.shared.b16 {%0,%1,%2,%3}, [%4];"
        : "=r"(r[0]), "=r"(r[1]), "=r"(r[2]), "=r"(r[3]) : "r"(addr));
}
__device__ __forceinline__ void ldm_x4t(uint32_t* r, uint32_t addr) {
    asm volatile("ldmatrix.sync.aligned.m8n8.x4.trans.shared.b16 {%0,%1,%2,%3}, [%4];"
        : "=r"(r[0]), "=r"(r[1]), "=r"(r[2]), "=r"(r[3]) : "r"(addr));
}
__device__ __forceinline__ void mma_bf16(float* d, const uint32_t* a, const uint32_t* b) {
    asm volatile(
        "mma.sync.aligned.m16n8k16.row.col.f32.bf16.bf16.f32 "
        "{%0,%1,%2,%3}, {%4,%5,%6,%7}, {%8,%9}, {%0,%1,%2,%3};"
        : "+f"(d[0]), "+f"(d[1]), "+f"(d[2]), "+f"(d[3])
        : "r"(a[0]), "r"(a[1]), "r"(a[2]), "r"(a[3]), "r"(b[0]), "r"(b[1]));
}
__device__ __forceinline__ uint32_t pk(float lo, float hi) {
    __nv_bfloat162 t = __floats2bfloat162_rn(lo, hi);
    return *(uint32_t*)&t;
}
__device__ __forceinline__ void split2(float v0, float v1, uint32_t& h, uint32_t& l) {
    __nv_bfloat16 h0 = __float2bfloat16(v0), h1 = __float2bfloat16(v1);
    h = pk(__bfloat162float(h0), __bfloat162float(h1));
    l = pk(v0 - __bfloat162float(h0), v1 - __bfloat162float(h1));
}
// 32-col bf16 tile (64B rows, 4x16B segs)
__device__ __forceinline__ uint32_t off32(int r, int s) {
    return (uint32_t)(r * 64 + ((s ^ ((r >> 1) & 3)) << 4));
}
// 64-col bf16 tile (128B rows, 8x16B segs)
__device__ __forceinline__ uint32_t off64(int r, int s) {
    return (uint32_t)(r * 128 + ((s ^ (r & 7)) << 4));
}

// ---------------- merged weight split (+ QKV bias concat, Q pre-scaled) ----------------
static constexpr int WS_QKV = NQKV * DIM / 4;
static constexpr int WS_W1  = DFF * DIM / 4;
static constexpr int WS_W2  = DIM * DFF / 4;
static constexpr int WS_B   = NQKV / 4;
static constexpr int WS_TOT = WS_QKV + WS_W1 + WS_W2 + WS_B;

__global__ __launch_bounds__(256)
void wsplit_all(const float* __restrict__ Wq, const float* __restrict__ Wk,
                const float* __restrict__ Wv, const float* __restrict__ W1,
                const float* __restrict__ W2, const float* __restrict__ bq,
                const float* __restrict__ bk, const float* __restrict__ bv,
                __nv_bfloat16* __restrict__ qkvh,
                __nv_bfloat16* __restrict__ w1h, __nv_bfloat16* __restrict__ w1l,
                __nv_bfloat16* __restrict__ w2h, __nv_bfloat16* __restrict__ w2l,
                float* __restrict__ bqkv)
{
    int i = blockIdx.x * 256 + threadIdx.x;
    if (i >= WS_TOT) return;
    if (i < WS_QKV) {
        int e = i * 4;
        int r = e >> 10;
        float sc = 1.0f;
        const float* src;
        if (r < 1024)      { src = Wq + e;                sc = QSCALE; }
        else if (r < 2048) { src = Wk + (e - 1024*1024); }
        else               { src = Wv + (e - 2048*1024); }
        float4 v = *(const float4*)src;
        uint2 uh;
        uh.x = pk(v.x * sc, v.y * sc);
        uh.y = pk(v.z * sc, v.w * sc);
        *(uint2*)(qkvh + e) = uh;
    } else if (i < WS_QKV + WS_W1) {
        int e = (i - WS_QKV) * 4;
        float4 v = *(const float4*)(W1 + e);
        uint2 uh, ul;
        split2(v.x, v.y, uh.x, ul.x);
        split2(v.z, v.w, uh.y, ul.y);
        *(uint2*)(w1h + e) = uh;
        *(uint2*)(w1l + e) = ul;
    } else if (i < WS_QKV + WS_W1 + WS_W2) {
        int e = (i - WS_QKV - WS_W1) * 4;
        float4 v = *(const float4*)(W2 + e);
        uint2 uh, ul;
        split2(v.x, v.y, uh.x, ul.x);
        split2(v.z, v.w, uh.y, ul.y);
        *(uint2*)(w2h + e) = uh;
        *(uint2*)(w2l + e) = ul;
    } else {
        int e = (i - WS_QKV - WS_W1 - WS_W2) * 4;
        #pragma unroll
        for (int j = 0; j < 4; j++) {
            int c = e + j;
            float b = (c < 1024) ? QSCALE * bq[c]
                    : (c < 2048) ? bk[c - 1024] : bv[c - 2048];
            bqkv[c] = b;
        }
    }
}

// ---------------- LayerNorm (optional residual; fp32 out + bf16 splits) ----------------
__global__ __launch_bounds__(256)
void ln_kernel(const float* __restrict__ x, const float* __restrict__ res,
               const float* __restrict__ gamma, const float* __restrict__ beta,
               float* __restrict__ out, __nv_bfloat16* __restrict__ ohi,
               __nv_bfloat16* __restrict__ olo)
{
    int row = blockIdx.x;
    int t = threadIdx.x;
    const float4* xr = (const float4*)(x + (size_t)row * DIM);
    float4 v = xr[t];
    if (res) {
        const float4* rr = (const float4*)(res + (size_t)row * DIM);
        float4 r = rr[t];
        v.x += r.x; v.y += r.y; v.z += r.z; v.w += r.w;
    }
    float s  = v.x + v.y + v.z + v.w;
    float s2 = v.x*v.x + v.y*v.y + v.z*v.z + v.w*v.w;
    #pragma unroll
    for (int o = 16; o > 0; o >>= 1) {
        s  += __shfl_down_sync(0xffffffffu, s,  o);
        s2 += __shfl_down_sync(0xffffffffu, s2, o);
    }
    __shared__ float ss[8], ss2[8];
    __shared__ float mean_s, rstd_s;
    if ((t & 31) == 0) { ss[t >> 5] = s; ss2[t >> 5] = s2; }
    __syncthreads();
    if (t == 0) {
        float a = 0.f, b = 0.f;
        #pragma unroll
        for (int i = 0; i < 8; i++) { a += ss[i]; b += ss2[i]; }
        float mean = a * (1.0f / DIM);
        float var  = b * (1.0f / DIM) - mean * mean;
        mean_s = mean;
        rstd_s = rsqrtf(var + 1e-5f);
    }
    __syncthreads();
    float mean = mean_s, rstd = rstd_s;
    float4 g = ((const float4*)gamma)[t];
    float4 bb = ((const float4*)beta)[t];
    float4 o4;
    o4.x = (v.x - mean) * rstd * g.x + bb.x;
    o4.y = (v.y - mean) * rstd * g.y + bb.y;
    o4.z = (v.z - mean) * rstd * g.z + bb.z;
    o4.w = (v.w - mean) * rstd * g.w + bb.w;
    size_t idx = (size_t)row * DIM + t * 4;
    if (out) *(float4*)(out + idx) = o4;
    if (ohi) {
        uint2 uh, ul;
        split2(o4.x, o4.y, uh.x, ul.x);
        split2(o4.z, o4.w, uh.y, ul.y);
        *(uint2*)(ohi + idx) = uh;
        *(uint2*)(olo + idx) = ul;
    }
}

// ---------------- 3-term split-bf16 GEMM (FF1/FF2): C = A @ W^T ----------------
// CTA 128x128, 8 warps, K-chunk 32, 3-stage cp.async, 2 CTAs/SM.
// EPI: 1 = bias+silu -> bf16 hi/lo ; 2 = bias+res -> fp32
static constexpr int G_STAGE = 32768;   // Ah(8K) Al(8K) Bh(8K) Bl(8K)
static constexpr int G_SMEM = 3 * G_STAGE;

template<int EPI>
__global__ void __launch_bounds__(256, 2)
gemm_mma(const __nv_bfloat16* __restrict__ Ah, const __nv_bfloat16* __restrict__ Al,
         const __nv_bfloat16* __restrict__ Bh, const __nv_bfloat16* __restrict__ Bl,
         const float* __restrict__ bias, const float* __restrict__ res,
         float* __restrict__ C, __nv_bfloat16* __restrict__ Chi,
         __nv_bfloat16* __restrict__ Clo, int N, int K)
{
    extern __shared__ char sm[];
    const int tid = threadIdx.x;
    const int wid = tid >> 5, lane = tid & 31;
    const int bm = blockIdx.y * 128, bn = blockIdx.x * 128;
    const int wm = (wid & 3) * 32, wn = (wid >> 2) * 64;
    const uint32_t sb = smem_u32(sm);

    float acc[2][8][4];
    #pragma unroll
    for (int i = 0; i < 2; i++)
        #pragma unroll
        for (int j = 0; j < 8; j++)
            #pragma unroll
            for (int d = 0; d < 4; d++) acc[i][j][d] = 0.f;

    const int r_ld = tid >> 1;
    const int s_ld = (tid & 1) * 2;
    const __nv_bfloat16* gA[2] = {Ah, Al};
    const __nv_bfloat16* gB[2] = {Bh, Bl};

    auto issue = [&](int c) {
        uint32_t st = sb + (uint32_t)(c % 3) * G_STAGE;
        int k0 = c * 32;
        #pragma unroll
        for (int t = 0; t < 2; t++) {
            const __nv_bfloat16* A = gA[t];
            const __nv_bfloat16* B = gB[t];
            uint32_t dA = st + t * 8192;
            uint32_t dB = st + 16384 + t * 8192;
            #pragma unroll
            for (int j = 0; j < 2; j++) {
                int s = s_ld + j;
                uint32_t o = off32(r_ld, s);
                cp16(dA + o, A + (size_t)(bm + r_ld) * K + k0 + s * 8);
                cp16(dB + o, B + (size_t)(bn + r_ld) * K + k0 + s * 8);
            }
        }
        cp_commit();
    };

    const int NC = K / 32;
    issue(0);
    issue(1);
    issue(2);

    for (int c = 0; c < NC; c++) {
        if (c + 2 < NC) cp_wait<2>(); else if (c + 1 < NC) cp_wait<1>(); else cp_wait<0>();
        __syncthreads();
        uint32_t st = sb + (uint32_t)(c % 3) * G_STAGE;
        #pragma unroll
        for (int ks = 0; ks < 2; ks++) {
            uint32_t a_h[8], a_l[8];
            #pragma unroll
            for (int mt = 0; mt < 2; mt++) {
                int row = wm + mt * 16 + (lane & 7) + ((lane >> 3) & 1) * 8;
                int seg = ks * 2 + (lane >> 4);
                uint32_t oa = off32(row, seg);
                ldm_x4(a_h + mt * 4, st + oa);
                ldm_x4(a_l + mt * 4, st + 8192 + oa);
            }
            #pragma unroll
            for (int np = 0; np < 2; np++) {
                uint32_t bh[8], bl[8];
                #pragma unroll
                for (int p = 0; p < 2; p++) {
                    int ntp = np * 2 + p;
                    int row = wn + ntp * 16 + (lane & 7) + ((lane >> 4) & 1) * 8;
                    int seg = ks * 2 + ((lane >> 3) & 1);
                    uint32_t ob = off32(row, seg);
                    ldm_x4(bh + p * 4, st + 16384 + ob);
                    ldm_x4(bl + p * 4, st + 24576 + ob);
                }
                #pragma unroll
                for (int p = 0; p < 2; p++)
                    #pragma unroll
                    for (int half = 0; half < 2; half++)
                        #pragma unroll
                        for (int mt = 0; mt < 2; mt++)
                            mma_bf16(acc[mt][(np*2+p)*2+half], a_h + mt*4, bh + p*4 + half*2);
                #pragma unroll
                for (int p = 0; p < 2; p++)
                    #pragma unroll
                    for (int half = 0; half < 2; half++)
                        #pragma unroll
                        for (int mt = 0; mt < 2; mt++)
                            mma_bf16(acc[mt][(np*2+p)*2+half], a_h + mt*4, bl + p*4 + half*2);
                #pragma unroll
                for (int p = 0; p < 2; p++)
                    #pragma unroll
                    for (int half = 0; half < 2; half++)
                        #pragma unroll
                        for (int mt = 0; mt < 2; mt++)
                            mma_bf16(acc[mt][(np*2+p)*2+half], a_l + mt*4, bh + p*4 + half*2);
            }
        }
        __syncthreads();
        if (c + 3 < NC) issue(c + 3);
    }

    #pragma unroll
    for (int mt = 0; mt < 2; mt++) {
        int r0 = bm + wm + mt * 16 + (lane >> 2);
        #pragma unroll
        for (int nt = 0; nt < 8; nt++) {
            int col = bn + wn + nt * 8 + (lane & 3) * 2;
            float b0 = bias[col], b1 = bias[col + 1];
            float* a = acc[mt][nt];
            if (EPI == 1) {
                float v0 = a[0] + b0, v1 = a[1] + b1, v2 = a[2] + b0, v3 = a[3] + b1;
                v0 = v0 / (1.f + __expf(-v0));
                v1 = v1 / (1.f + __expf(-v1));
                v2 = v2 / (1.f + __expf(-v2));
                v3 = v3 / (1.f + __expf(-v3));
                uint32_t h0, l0, h1, l1;
                split2(v0, v1, h0, l0);
                split2(v2, v3, h1, l1);
                *(uint32_t*)(Chi + (size_t)r0 * N + col) = h0;
                *(uint32_t*)(Clo + (size_t)r0 * N + col) = l0;
                *(uint32_t*)(Chi + (size_t)(r0 + 8) * N + col) = h1;
                *(uint32_t*)(Clo + (size_t)(r0 + 8) * N + col) = l1;
            } else {
                float2 p0, p1;
                float2 rr0 = *(const float2*)(res + (size_t)r0 * N + col);
                float2 rr1 = *(const float2*)(res + (size_t)(r0 + 8) * N + col);
                p0.x = a[0] + b0 + rr0.x; p0.y = a[1] + b1 + rr0.y;
                p1.x = a[2] + b0 + rr1.x; p1.y = a[3] + b1 + rr1.y;
                *(float2*)(C + (size_t)r0 * N + col) = p0;
                *(float2*)(C + (size_t)(r0 + 8) * N + col) = p1;
            }
        }
    }
}

// ---------------- 2-term QKV GEMM: C = A @ W^T + b -> bf16 hi only ----------------
// Terms: Ah*Bh + Al*Bh (weight-lo dropped; output consumed as bf16 anyway).
// Stage 24KB -> 3 stages = 72KB -> 3 CTAs/SM.
static constexpr int Q_STAGE = 24576;   // Ah(8K) Al(8K) Bh(8K)
static constexpr int Q_SMEM = 3 * Q_STAGE;

__global__ void __launch_bounds__(256, 3)
gemm_qkv(const __nv_bfloat16* __restrict__ Ah, const __nv_bfloat16* __restrict__ Al,
         const __nv_bfloat16* __restrict__ Bh, const float* __restrict__ bias,
         __nv_bfloat16* __restrict__ Chi, int N, int K)
{
    extern __shared__ char sm[];
    const int tid = threadIdx.x;
    const int wid = tid >> 5, lane = tid & 31;
    const int bm = blockIdx.y * 128, bn = blockIdx.x * 128;
    const int wm = (wid & 3) * 32, wn = (wid >> 2) * 64;
    const uint32_t sb = smem_u32(sm);

    float acc[2][8][4];
    #pragma unroll
    for (int i = 0; i < 2; i++)
        #pragma unroll
        for (int j = 0; j < 8; j++)
            #pragma unroll
            for (int d = 0; d < 4; d++) acc[i][j][d] = 0.f;

    const int r_ld = tid >> 1;
    const int s_ld = (tid & 1) * 2;

    auto issue = [&](int c) {
        uint32_t st = sb + (uint32_t)(c % 3) * Q_STAGE;
        int k0 = c * 32;
        #pragma unroll
        for (int j = 0; j < 2; j++) {
            int s = s_ld + j;
            uint32_t o = off32(r_ld, s);
            cp16(st + o,         Ah + (size_t)(bm + r_ld) * K + k0 + s * 8);
            cp16(st + 8192 + o,  Al + (size_t)(bm + r_ld) * K + k0 + s * 8);
            cp16(st + 16384 + o, Bh + (size_t)(bn + r_ld) * K + k0 + s * 8);
        }
        cp_commit();
    };

    const int NC = K / 32;
    issue(0);
    issue(1);
    issue(2);

    for (int c = 0; c < NC; c++) {
        if (c + 2 < NC) cp_wait<2>(); else if (c + 1 < NC) cp_wait<1>(); else cp_wait<0>();
        __syncthreads();
        uint32_t st = sb + (uint32_t)(c % 3) * Q_STAGE;
        #pragma unroll
        for (int ks = 0; ks < 2; ks++) {
            uint32_t a_h[8], a_l[8];
            #pragma unroll
            for (int mt = 0; mt < 2; mt++) {
                int row = wm + mt * 16 + (lane & 7) + ((lane >> 3) & 1) * 8;
                int seg = ks * 2 + (lane >> 4);
                uint32_t oa = off32(row, seg);
                ldm_x4(a_h + mt * 4, st + oa);
                ldm_x4(a_l + mt * 4, st + 8192 + oa);
            }
            #pragma unroll
            for (int np = 0; np < 2; np++) {
                uint32_t bh[8];
                #pragma unroll
                for (int p = 0; p < 2; p++) {
                    int ntp = np * 2 + p;
                    int row = wn + ntp * 16 + (lane & 7) + ((lane >> 4) & 1) * 8;
                    int seg = ks * 2 + ((lane >> 3) & 1);
                    ldm_x4(bh + p * 4, st + 16384 + off32(row, seg));
                }
                #pragma unroll
                for (int p = 0; p < 2; p++)
                    #pragma unroll
                    for (int half = 0; half < 2; half++)
                        #pragma unroll
                        for (int mt = 0; mt < 2; mt++)
                            mma_bf16(acc[mt][(np*2+p)*2+half], a_h + mt*4, bh + p*4 + half*2);
                #pragma unroll
                for (int p = 0; p < 2; p++)
                    #pragma unroll
                    for (int half = 0; half < 2; half++)
                        #pragma unroll
                        for (int mt = 0; mt < 2; mt++)
                            mma_bf16(acc[mt][(np*2+p)*2+half], a_l + mt*4, bh + p*4 + half*2);
            }
        }
        __syncthreads();
        if (c + 3 < NC) issue(c + 3);
    }

    #pragma unroll
    for (int mt = 0; mt < 2; mt++) {
        int r0 = bm + wm + mt * 16 + (lane >> 2);
        #pragma unroll
        for (int nt = 0; nt < 8; nt++) {
            int col = bn + wn + nt * 8 + (lane & 3) * 2;
            float b0 = bias[col], b1 = bias[col + 1];
            float* a = acc[mt][nt];
            *(uint32_t*)(Chi + (size_t)r0 * N + col)       = pk(a[0] + b0, a[1] + b1);
            *(uint32_t*)(Chi + (size_t)(r0 + 8) * N + col) = pk(a[2] + b0, a[3] + b1);
        }
    }
}

// ---------------- Flash attention via mma.sync (bf16-hi only) ----------------
// grid: (SEQ/64, NH, B); 128 thr (4 warps, 16 q-rows each), 4 CTAs/SM.
// Scores in log2 units -> exp2f softmax. Single-pass bf16 scores.
// smem: Qhi 8K @0; KV 3 stages @8192, stride 16384: Kh, Vh(+8192)
static constexpr int A_SMEM = 8192 + 3 * 16384;   // 57344

__global__ void __launch_bounds__(128, 4)
attn_mma(const __nv_bfloat16* __restrict__ qkvh, float* __restrict__ out)
{
    extern __shared__ char sm[];
    const int tid = threadIdx.x;
    const int wid = tid >> 5, lane = tid & 31;
    const int h = blockIdx.y, b = blockIdx.z;
    const int tok0 = b * SEQ + blockIdx.x * 64;
    const uint32_t sb = smem_u32(sm);

    // group 0: Q (64 rows x 128B, hi only)
    {
        int r = tid >> 1;
        size_t qrow = (size_t)(tok0 + r) * NQKV + h * HD;
        #pragma unroll
        for (int j = 0; j < 4; j++) {
            int s = (tid & 1) * 4 + j;
            cp16(sb + off64(r, s), qkvh + qrow + s * 8);
        }
        cp_commit();
    }
    auto issueKV = [&](int kb) {
        uint32_t st = sb + 8192 + (uint32_t)(kb % 3) * 16384;
        int r = tid >> 1;
        size_t kvrow = (size_t)(b * SEQ + kb * 64 + r) * NQKV + h * HD;
        #pragma unroll
        for (int j = 0; j < 4; j++) {
            int s = (tid & 1) * 4 + j;
            uint32_t o = off64(r, s);
            cp16(st + o, qkvh + kvrow + 1024 + s * 8);          // K hi
            cp16(st + 8192 + o, qkvh + kvrow + 2048 + s * 8);   // V hi
        }
        cp_commit();
    };
    issueKV(0);
    issueKV(1);
    issueKV(2);

    cp_wait<2>(); // Q + KV0 done
    __syncthreads();

    // Q fragments (registers, reused all blocks)
    uint32_t qf[4][4];
    {
        int row = wid * 16 + (lane & 7) + ((lane >> 3) & 1) * 8;
        #pragma unroll
        for (int ks = 0; ks < 4; ks++) {
            int seg = ks * 2 + (lane >> 4);
            ldm_x4(qf[ks], sb + off64(row, seg));
        }
    }

    float o_acc[8][4];
    #pragma unroll
    for (int i = 0; i < 8; i++)
        #pragma unroll
        for (int d = 0; d < 4; d++) o_acc[i][d] = 0.f;
    float runA = -INFINITY, runB = -INFINITY, lA = 0.f, lB = 0.f;

    const int NKB = SEQ / 64;
    for (int kb = 0; kb < NKB; kb++) {
        if (kb > 0) {
            if (kb + 2 < NKB) cp_wait<2>();
            else if (kb + 1 < NKB) cp_wait<1>();
            else cp_wait<0>();
            __syncthreads();
        }
        uint32_t st = sb + 8192 + (uint32_t)(kb % 3) * 16384;
        // ---- scores S[16,64] (log2 units), single bf16 pass ----
        float s[8][4];
        #pragma unroll
        for (int i = 0; i < 8; i++)
            #pragma unroll
            for (int d = 0; d < 4; d++) s[i][d] = 0.f;
        #pragma unroll
        for (int ks = 0; ks < 4; ks++) {
            uint32_t bh[16];
            #pragma unroll
            for (int ntp = 0; ntp < 4; ntp++) {
                int row = ntp * 16 + (lane & 7) + ((lane >> 4) & 1) * 8;
                int seg = ks * 2 + ((lane >> 3) & 1);
                ldm_x4(bh + ntp * 4, st + off64(row, seg));
            }
            #pragma unroll
            for (int ntp = 0; ntp < 4; ntp++)
                #pragma unroll
                for (int half = 0; half < 2; half++)
                    mma_bf16(s[ntp * 2 + half], qf[ks], bh + ntp * 4 + half * 2);
        }
        // ---- online softmax in base 2 (rows: A = lane>>2, B = +8) ----
        float mA = -INFINITY, mB = -INFINITY;
        #pragma unroll
        for (int nt = 0; nt < 8; nt++) {
            mA = fmaxf(mA, fmaxf(s[nt][0], s[nt][1]));
            mB = fmaxf(mB, fmaxf(s[nt][2], s[nt][3]));
        }
        mA = fmaxf(mA, __shfl_xor_sync(0xffffffffu, mA, 1));
        mA = fmaxf(mA, __shfl_xor_sync(0xffffffffu, mA, 2));
        mB = fmaxf(mB, __shfl_xor_sync(0xffffffffu, mB, 1));
        mB = fmaxf(mB, __shfl_xor_sync(0xffffffffu, mB, 2));
        float nA = fmaxf(runA, mA), nB = fmaxf(runB, mB);
        float cA = exp2f(runA - nA), cB = exp2f(runB - nB);
        runA = nA; runB = nB;
        lA *= cA; lB *= cB;
        #pragma unroll
        for (int nt = 0; nt < 8; nt++) {
            o_acc[nt][0] *= cA; o_acc[nt][1] *= cA;
            o_acc[nt][2] *= cB; o_acc[nt][3] *= cB;
        }
        float sumA = 0.f, sumB = 0.f;
        #pragma unroll
        for (int nt = 0; nt < 8; nt++) {
            s[nt][0] = exp2f(s[nt][0] - nA); sumA += s[nt][0];
            s[nt][1] = exp2f(s[nt][1] - nA); sumA += s[nt][1];
            s[nt][2] = exp2f(s[nt][2] - nB); sumB += s[nt][2];
            s[nt][3] = exp2f(s[nt][3] - nB); sumB += s[nt][3];
        }
        lA += sumA; lB += sumB;
        // ---- P (bf16 A-frags, pure register repack) ----
        uint32_t pf[4][4];
        #pragma unroll
        for (int j = 0; j < 4; j++) {
            pf[j][0] = pk(s[2*j][0],   s[2*j][1]);
            pf[j][1] = pk(s[2*j][2],   s[2*j][3]);
            pf[j][2] = pk(s[2*j+1][0], s[2*j+1][1]);
            pf[j][3] = pk(s[2*j+1][2], s[2*j+1][3]);
        }
        // ---- O += P @ V ----
        #pragma unroll
        for (int ks = 0; ks < 4; ks++) {
            #pragma unroll
            for (int ntp = 0; ntp < 4; ntp++) {
                int row = ks * 16 + (lane & 7) + ((lane >> 3) & 1) * 8;
                int seg = ntp * 2 + (lane >> 4);
                uint32_t vb[4];
                ldm_x4t(vb, st + 8192 + off64(row, seg));
                mma_bf16(o_acc[ntp * 2 + 0], pf[ks], vb + 0);
                mma_bf16(o_acc[ntp * 2 + 1], pf[ks], vb + 2);
            }
        }
        __syncthreads();
        if (kb + 3 < NKB) issueKV(kb + 3);
    }

    // finalize: row sums live in quads
    lA += __shfl_xor_sync(0xffffffffu, lA, 1);
    lA += __shfl_xor_sync(0xffffffffu, lA, 2);
    lB += __shfl_xor_sync(0xffffffffu, lB, 1);
    lB += __shfl_xor_sync(0xffffffffu, lB, 2);
    float iA = 1.f / lA, iB = 1.f / lB;
    int rowA = tok0 + wid * 16 + (lane >> 2);
    #pragma unroll
    for (int nt = 0; nt < 8; nt++) {
        int col = h * HD + nt * 8 + (lane & 3) * 2;
        float2 p0 = {o_acc[nt][0] * iA, o_acc[nt][1] * iA};
        float2 p1 = {o_acc[nt][2] * iB, o_acc[nt][3] * iB};
        *(float2*)(out + (size_t)rowA * DIM + col) = p0;
        *(float2*)(out + (size_t)(rowA + 8) * DIM + col) = p1;
    }
}

// ---------------- launch ----------------
extern "C" void kernel_launch(void* const* d_in, const int* in_sizes, int n_in,
                              void* d_out, int out_size)
{
    (void)in_sizes; (void)n_in; (void)out_size;
    const float* x   = (const float*)d_in[0];
    const float* Wq  = (const float*)d_in[1];
    const float* bq  = (const float*)d_in[2];
    const float* Wk  = (const float*)d_in[3];
    const float* bk  = (const float*)d_in[4];
    const float* Wv  = (const float*)d_in[5];
    const float* bv  = (const float*)d_in[6];
    const float* g1  = (const float*)d_in[7];
    const float* b1  = (const float*)d_in[8];
    const float* g2  = (const float*)d_in[9];
    const float* b2  = (const float*)d_in[10];
    const float* W1  = (const float*)d_in[11];
    const float* bf1 = (const float*)d_in[12];
    const float* W2  = (const float*)d_in[13];
    const float* bf2 = (const float*)d_in[14];

    float *xn, *attn, *bqkv;
    cudaGetSymbolAddress((void**)&xn,   g_xn);
    cudaGetSymbolAddress((void**)&attn, g_attn);
    cudaGetSymbolAddress((void**)&bqkv, g_bqkv);

    __nv_bfloat16 *xnh, *xnl, *qkvh, *hh, *hl, *f1h, *f1l;
    __nv_bfloat16 *wqkvh, *w1h, *w1l, *w2h, *w2l;
    cudaGetSymbolAddress((void**)&xnh,   g_xn_hi);   cudaGetSymbolAddress((void**)&xnl,   g_xn_lo);
    cudaGetSymbolAddress((void**)&qkvh,  g_qkv_hi);
    cudaGetSymbolAddress((void**)&hh,    g_h_hi);    cudaGetSymbolAddress((void**)&hl,    g_h_lo);
    cudaGetSymbolAddress((void**)&f1h,   g_ff1_hi);  cudaGetSymbolAddress((void**)&f1l,   g_ff1_lo);
    cudaGetSymbolAddress((void**)&wqkvh, g_wqkv_hi);
    cudaGetSymbolAddress((void**)&w1h,   g_w1_hi);   cudaGetSymbolAddress((void**)&w1l,   g_w1_lo);
    cudaGetSymbolAddress((void**)&w2h,   g_w2_hi);   cudaGetSymbolAddress((void**)&w2l,   g_w2_lo);

    cudaFuncSetAttribute(gemm_mma<1>, cudaFuncAttributeMaxDynamicSharedMemorySize, G_SMEM);
    cudaFuncSetAttribute(gemm_mma<2>, cudaFuncAttributeMaxDynamicSharedMemorySize, G_SMEM);
    cudaFuncSetAttribute(gemm_qkv,    cudaFuncAttributeMaxDynamicSharedMemorySize, Q_SMEM);
    cudaFuncSetAttribute(attn_mma,    cudaFuncAttributeMaxDynamicSharedMemorySize, A_SMEM);

    // launch 0: merged weight splits (+ bias concat, Q pre-scaled by 1/8*log2e)
    wsplit_all<<<(WS_TOT + 255)/256, 256>>>(Wq, Wk, Wv, W1, W2, bq, bk, bv,
                                            wqkvh, w1h, w1l, w2h, w2l, bqkv);

    // launch 1: xn = LN(x) : fp32 + splits
    ln_kernel<<<NTOK, 256>>>(x, nullptr, g1, b1, xn, xnh, xnl);

    // launch 2: fused QKV projection, 2-term -> bf16 hi [NTOK, 3072]
    dim3 gQKV(NQKV / 128, NTOK / 128);
    gemm_qkv<<<gQKV, 256, Q_SMEM>>>(xnh, xnl, wqkvh, bqkv, qkvh, NQKV, DIM);

    // launch 3: attention (tensor-core flash, single-pass bf16 scores, 4 CTAs/SM)
    attn_mma<<<dim3(SEQ / 64, NH, 2), 128, A_SMEM>>>(qkvh, attn);

    // launch 4: h = LN(attn + xn) -> splits
    ln_kernel<<<NTOK, 256>>>(attn, xn, g2, b2, nullptr, hh, hl);

    // launch 5: ff1 = silu(h @ W1^T + bf1) -> bf16 splits (3-term)
    dim3 gF1(DFF / 128, NTOK / 128);
    gemm_mma<1><<<gF1, 256, G_SMEM>>>(hh, hl, w1h, w1l, bf1, nullptr,
                                      nullptr, f1h, f1l, DFF, DIM);

    // launch 6: out = ff1 @ W2^T + bf2 + xn (3-term)
    dim3 gF2(DIM / 128, NTOK / 128);
    gemm_mma<2><<<gF2, 256, G_SMEM>>>(f1h, f1l, w2h, w2l, bf2, xn,
                                      (float*)d_out, nullptr, nullptr, DIM, DFF);
}

// round 13
// speedup vs baseline: 5.9573x; 1.0007x over previous
#include <cuda_runtime.h>
#include <cuda_bf16.h>
#include <math.h>
#include <stdint.h>

#define NTOK 4096          // B*S
#define SEQ  2048
#define DIM  1024
#define NH   16
#define HD   64
#define DFF  4096
#define NQKV 3072

#define QSCALE (0.125f * 1.44269504088896f)   // 1/sqrt(64) * log2(e)

// ---------------- scratch (device globals; no allocs allowed) ----------------
__device__ float g_xn[NTOK * DIM];
__device__ float g_attn[NTOK * DIM];
__device__ float g_bqkv[NQKV];

__device__ __nv_bfloat16 g_xn_hi[NTOK * DIM],   g_xn_lo[NTOK * DIM];
__device__ __nv_bfloat16 g_qkv_hi[NTOK * NQKV];
__device__ __nv_bfloat16 g_h_hi[NTOK * DIM],    g_h_lo[NTOK * DIM];
__device__ __nv_bfloat16 g_ff1_hi[NTOK * DFF],  g_ff1_lo[NTOK * DFF];
__device__ __nv_bfloat16 g_wqkv_hi[NQKV * DIM];
__device__ __nv_bfloat16 g_w1_hi[DFF * DIM],    g_w1_lo[DFF * DIM];
__device__ __nv_bfloat16 g_w2_hi[DIM * DFF],    g_w2_lo[DIM * DFF];

// ---------------- PTX helpers (family-portable sm_80-era ISA) ----------------
__device__ __forceinline__ uint32_t smem_u32(const void* p) {
    uint32_t a;
    asm("{ .reg .u64 t; cvta.to.shared.u64 t, %1; cvt.u32.u64 %0, t; }" : "=r"(a) : "l"(p));
    return a;
}
__device__ __forceinline__ void cp16(uint32_t dst, const void* src) {
    asm volatile("cp.async.cg.shared.global [%0], [%1], 16;" :: "r"(dst), "l"(src) : "memory");
}
__device__ __forceinline__ void cp_commit() {
    asm volatile("cp.async.commit_group;" ::: "memory");
}
template<int N> __device__ __forceinline__ void cp_wait() {
    asm volatile("cp.async.wait_group %0;" :: "n"(N) : "memory");
}
__device__ __forceinline__ void ldm_x4(uint32_t* r, uint32_t addr) {
    asm volatile("ldmatrix.sync.aligned.m8n8.x4.shared.b16 {%0,%1,%2,%3}, [%4];"
        : "=r"(r[0]), "=r"(r[1]), "=r"(r[2]), "=r"(r[3]) : "r"(addr));
}
__device__ __forceinline__ void ldm_x4t(uint32_t* r, uint32_t addr) {
    asm volatile("ldmatrix.sync.aligned.m8n8.x4.trans.shared.b16 {%0,%1,%2,%3}, [%4];"
        : "=r"(r[0]), "=r"(r[1]), "=r"(r[2]), "=r"(r[3]) : "r"(addr));
}
__device__ __forceinline__ void mma_bf16(float* d, const uint32_t* a, const uint32_t* b) {
    asm volatile(
        "mma.sync.aligned.m16n8k16.row.col.f32.bf16.bf16.f32 "
        "{%0,%1,%2,%3}, {%4,%5,%6,%7}, {%8,%9}, {%0,%1,%2,%3};"
        : "+f"(d[0]), "+f"(d[1]), "+f"(d[2]), "+f"(d[3])
        : "r"(a[0]), "r"(a[1]), "r"(a[2]), "r"(a[3]), "r"(b[0]), "r"(b[1]));
}
__device__ __forceinline__ uint32_t pk(float lo, float hi) {
    __nv_bfloat162 t = __floats2bfloat162_rn(lo, hi);
    return *(uint32_t*)&t;
}
__device__ __forceinline__ void split2(float v0, float v1, uint32_t& h, uint32_t& l) {
    __nv_bfloat16 h0 = __float2bfloat16(v0), h1 = __float2bfloat16(v1);
    h = pk(__bfloat162float(h0), __bfloat162float(h1));
    l = pk(v0 - __bfloat162float(h0), v1 - __bfloat162float(h1));
}
// 32-col bf16 tile (64B rows, 4x16B segs)
__device__ __forceinline__ uint32_t off32(int r, int s) {
    return (uint32_t)(r * 64 + ((s ^ ((r >> 1) & 3)) << 4));
}
// 64-col bf16 tile (128B rows, 8x16B segs)
__device__ __forceinline__ uint32_t off64(int r, int s) {
    return (uint32_t)(r * 128 + ((s ^ (r & 7)) << 4));
}

// ---------------- merged weight split (+ QKV bias concat, Q pre-scaled) ----------------
static constexpr int WS_QKV = NQKV * DIM / 4;
static constexpr int WS_W1  = DFF * DIM / 4;
static constexpr int WS_W2  = DIM * DFF / 4;
static constexpr int WS_B   = NQKV / 4;
static constexpr int WS_TOT = WS_QKV + WS_W1 + WS_W2 + WS_B;

__global__ __launch_bounds__(256)
void wsplit_all(const float* __restrict__ Wq, const float* __restrict__ Wk,
                const float* __restrict__ Wv, const float* __restrict__ W1,
                const float* __restrict__ W2, const float* __restrict__ bq,
                const float* __restrict__ bk, const float* __restrict__ bv,
                __nv_bfloat16* __restrict__ qkvh,
                __nv_bfloat16* __restrict__ w1h, __nv_bfloat16* __restrict__ w1l,
                __nv_bfloat16* __restrict__ w2h, __nv_bfloat16* __restrict__ w2l,
                float* __restrict__ bqkv)
{
    int i = blockIdx.x * 256 + threadIdx.x;
    if (i >= WS_TOT) return;
    if (i < WS_QKV) {
        int e = i * 4;
        int r = e >> 10;
        float sc = 1.0f;
        const float* src;
        if (r < 1024)      { src = Wq + e;                sc = QSCALE; }
        else if (r < 2048) { src = Wk + (e - 1024*1024); }
        else               { src = Wv + (e - 2048*1024); }
        float4 v = *(const float4*)src;
        uint2 uh;
        uh.x = pk(v.x * sc, v.y * sc);
        uh.y = pk(v.z * sc, v.w * sc);
        *(uint2*)(qkvh + e) = uh;
    } else if (i < WS_QKV + WS_W1) {
        int e = (i - WS_QKV) * 4;
        float4 v = *(const float4*)(W1 + e);
        uint2 uh, ul;
        split2(v.x, v.y, uh.x, ul.x);
        split2(v.z, v.w, uh.y, ul.y);
        *(uint2*)(w1h + e) = uh;
        *(uint2*)(w1l + e) = ul;
    } else if (i < WS_QKV + WS_W1 + WS_W2) {
        int e = (i - WS_QKV - WS_W1) * 4;
        float4 v = *(const float4*)(W2 + e);
        uint2 uh, ul;
        split2(v.x, v.y, uh.x, ul.x);
        split2(v.z, v.w, uh.y, ul.y);
        *(uint2*)(w2h + e) = uh;
        *(uint2*)(w2l + e) = ul;
    } else {
        int e = (i - WS_QKV - WS_W1 - WS_W2) * 4;
        #pragma unroll
        for (int j = 0; j < 4; j++) {
            int c = e + j;
            float b = (c < 1024) ? QSCALE * bq[c]
                    : (c < 2048) ? bk[c - 1024] : bv[c - 2048];
            bqkv[c] = b;
        }
    }
}

// ---------------- LayerNorm (optional residual; fp32 out + bf16 splits) ----------------
__global__ __launch_bounds__(256)
void ln_kernel(const float* __restrict__ x, const float* __restrict__ res,
               const float* __restrict__ gamma, const float* __restrict__ beta,
               float* __restrict__ out, __nv_bfloat16* __restrict__ ohi,
               __nv_bfloat16* __restrict__ olo)
{
    int row = blockIdx.x;
    int t = threadIdx.x;
    const float4* xr = (const float4*)(x + (size_t)row * DIM);
    float4 v = xr[t];
    if (res) {
        const float4* rr = (const float4*)(res + (size_t)row * DIM);
        float4 r = rr[t];
        v.x += r.x; v.y += r.y; v.z += r.z; v.w += r.w;
    }
    float s  = v.x + v.y + v.z + v.w;
    float s2 = v.x*v.x + v.y*v.y + v.z*v.z + v.w*v.w;
    #pragma unroll
    for (int o = 16; o > 0; o >>= 1) {
        s  += __shfl_down_sync(0xffffffffu, s,  o);
        s2 += __shfl_down_sync(0xffffffffu, s2, o);
    }
    __shared__ float ss[8], ss2[8];
    __shared__ float mean_s, rstd_s;
    if ((t & 31) == 0) { ss[t >> 5] = s; ss2[t >> 5] = s2; }
    __syncthreads();
    if (t == 0) {
        float a = 0.f, b = 0.f;
        #pragma unroll
        for (int i = 0; i < 8; i++) { a += ss[i]; b += ss2[i]; }
        float mean = a * (1.0f / DIM);
        float var  = b * (1.0f / DIM) - mean * mean;
        mean_s = mean;
        rstd_s = rsqrtf(var + 1e-5f);
    }
    __syncthreads();
    float mean = mean_s, rstd = rstd_s;
    float4 g = ((const float4*)gamma)[t];
    float4 bb = ((const float4*)beta)[t];
    float4 o4;
    o4.x = (v.x - mean) * rstd * g.x + bb.x;
    o4.y = (v.y - mean) * rstd * g.y + bb.y;
    o4.z = (v.z - mean) * rstd * g.z + bb.z;
    o4.w = (v.w - mean) * rstd * g.w + bb.w;
    size_t idx = (size_t)row * DIM + t * 4;
    if (out) *(float4*)(out + idx) = o4;
    if (ohi) {
        uint2 uh, ul;
        split2(o4.x, o4.y, uh.x, ul.x);
        split2(o4.z, o4.w, uh.y, ul.y);
        *(uint2*)(ohi + idx) = uh;
        *(uint2*)(olo + idx) = ul;
    }
}

// ---------------- 3-term split-bf16 GEMM (FF1/FF2): C = A @ W^T ----------------
// CTA 128x128, 8 warps, K-chunk 32, 3-stage cp.async, 2 CTAs/SM.
// Full-B preload: acc reuse distance = 16 MMAs (covers HMMA acc latency).
// EPI: 1 = bias+silu -> bf16 hi/lo ; 2 = bias+res -> fp32
static constexpr int G_STAGE = 32768;   // Ah(8K) Al(8K) Bh(8K) Bl(8K)
static constexpr int G_SMEM = 3 * G_STAGE;

template<int EPI>
__global__ void __launch_bounds__(256, 2)
gemm_mma(const __nv_bfloat16* __restrict__ Ah, const __nv_bfloat16* __restrict__ Al,
         const __nv_bfloat16* __restrict__ Bh, const __nv_bfloat16* __restrict__ Bl,
         const float* __restrict__ bias, const float* __restrict__ res,
         float* __restrict__ C, __nv_bfloat16* __restrict__ Chi,
         __nv_bfloat16* __restrict__ Clo, int N, int K)
{
    extern __shared__ char sm[];
    const int tid = threadIdx.x;
    const int wid = tid >> 5, lane = tid & 31;
    const int bm = blockIdx.y * 128, bn = blockIdx.x * 128;
    const int wm = (wid & 3) * 32, wn = (wid >> 2) * 64;
    const uint32_t sb = smem_u32(sm);

    float acc[2][8][4];
    #pragma unroll
    for (int i = 0; i < 2; i++)
        #pragma unroll
        for (int j = 0; j < 8; j++)
            #pragma unroll
            for (int d = 0; d < 4; d++) acc[i][j][d] = 0.f;

    const int r_ld = tid >> 1;
    const int s_ld = (tid & 1) * 2;
    const __nv_bfloat16* gA[2] = {Ah, Al};
    const __nv_bfloat16* gB[2] = {Bh, Bl};

    auto issue = [&](int c) {
        uint32_t st = sb + (uint32_t)(c % 3) * G_STAGE;
        int k0 = c * 32;
        #pragma unroll
        for (int t = 0; t < 2; t++) {
            const __nv_bfloat16* A = gA[t];
            const __nv_bfloat16* B = gB[t];
            uint32_t dA = st + t * 8192;
            uint32_t dB = st + 16384 + t * 8192;
            #pragma unroll
            for (int j = 0; j < 2; j++) {
                int s = s_ld + j;
                uint32_t o = off32(r_ld, s);
                cp16(dA + o, A + (size_t)(bm + r_ld) * K + k0 + s * 8);
                cp16(dB + o, B + (size_t)(bn + r_ld) * K + k0 + s * 8);
            }
        }
        cp_commit();
    };

    const int NC = K / 32;
    issue(0);
    issue(1);
    issue(2);

    for (int c = 0; c < NC; c++) {
        if (c + 2 < NC) cp_wait<2>(); else if (c + 1 < NC) cp_wait<1>(); else cp_wait<0>();
        __syncthreads();
        uint32_t st = sb + (uint32_t)(c % 3) * G_STAGE;
        #pragma unroll
        for (int ks = 0; ks < 2; ks++) {
            uint32_t a_h[8], a_l[8];
            #pragma unroll
            for (int mt = 0; mt < 2; mt++) {
                int row = wm + mt * 16 + (lane & 7) + ((lane >> 3) & 1) * 8;
                int seg = ks * 2 + (lane >> 4);
                uint32_t oa = off32(row, seg);
                ldm_x4(a_h + mt * 4, st + oa);
                ldm_x4(a_l + mt * 4, st + 8192 + oa);
            }
            uint32_t bh[16], bl[16];
            #pragma unroll
            for (int ntp = 0; ntp < 4; ntp++) {
                int row = wn + ntp * 16 + (lane & 7) + ((lane >> 4) & 1) * 8;
                int seg = ks * 2 + ((lane >> 3) & 1);
                uint32_t ob = off32(row, seg);
                ldm_x4(bh + ntp * 4, st + 16384 + ob);
                ldm_x4(bl + ntp * 4, st + 24576 + ob);
            }
            // pass hh: 16 distinct accumulators
            #pragma unroll
            for (int ntp = 0; ntp < 4; ntp++)
                #pragma unroll
                for (int half = 0; half < 2; half++)
                    #pragma unroll
                    for (int mt = 0; mt < 2; mt++)
                        mma_bf16(acc[mt][ntp*2+half], a_h + mt*4, bh + ntp*4 + half*2);
            // pass hl
            #pragma unroll
            for (int ntp = 0; ntp < 4; ntp++)
                #pragma unroll
                for (int half = 0; half < 2; half++)
                    #pragma unroll
                    for (int mt = 0; mt < 2; mt++)
                        mma_bf16(acc[mt][ntp*2+half], a_h + mt*4, bl + ntp*4 + half*2);
            // pass lh
            #pragma unroll
            for (int ntp = 0; ntp < 4; ntp++)
                #pragma unroll
                for (int half = 0; half < 2; half++)
                    #pragma unroll
                    for (int mt = 0; mt < 2; mt++)
                        mma_bf16(acc[mt][ntp*2+half], a_l + mt*4, bh + ntp*4 + half*2);
        }
        __syncthreads();
        if (c + 3 < NC) issue(c + 3);
    }

    #pragma unroll
    for (int mt = 0; mt < 2; mt++) {
        int r0 = bm + wm + mt * 16 + (lane >> 2);
        #pragma unroll
        for (int nt = 0; nt < 8; nt++) {
            int col = bn + wn + nt * 8 + (lane & 3) * 2;
            float b0 = bias[col], b1 = bias[col + 1];
            float* a = acc[mt][nt];
            if (EPI == 1) {
                float v0 = a[0] + b0, v1 = a[1] + b1, v2 = a[2] + b0, v3 = a[3] + b1;
                v0 = v0 / (1.f + __expf(-v0));
                v1 = v1 / (1.f + __expf(-v1));
                v2 = v2 / (1.f + __expf(-v2));
                v3 = v3 / (1.f + __expf(-v3));
                uint32_t h0, l0, h1, l1;
                split2(v0, v1, h0, l0);
                split2(v2, v3, h1, l1);
                *(uint32_t*)(Chi + (size_t)r0 * N + col) = h0;
                *(uint32_t*)(Clo + (size_t)r0 * N + col) = l0;
                *(uint32_t*)(Chi + (size_t)(r0 + 8) * N + col) = h1;
                *(uint32_t*)(Clo + (size_t)(r0 + 8) * N + col) = l1;
            } else {
                float2 p0, p1;
                float2 rr0 = *(const float2*)(res + (size_t)r0 * N + col);
                float2 rr1 = *(const float2*)(res + (size_t)(r0 + 8) * N + col);
                p0.x = a[0] + b0 + rr0.x; p0.y = a[1] + b1 + rr0.y;
                p1.x = a[2] + b0 + rr1.x; p1.y = a[3] + b1 + rr1.y;
                *(float2*)(C + (size_t)r0 * N + col) = p0;
                *(float2*)(C + (size_t)(r0 + 8) * N + col) = p1;
            }
        }
    }
}

// ---------------- 2-term QKV GEMM: C = A @ W^T + b -> bf16 hi only ----------------
static constexpr int Q_STAGE = 24576;   // Ah(8K) Al(8K) Bh(8K)
static constexpr int Q_SMEM = 3 * Q_STAGE;

__global__ void __launch_bounds__(256, 3)
gemm_qkv(const __nv_bfloat16* __restrict__ Ah, const __nv_bfloat16* __restrict__ Al,
         const __nv_bfloat16* __restrict__ Bh, const float* __restrict__ bias,
         __nv_bfloat16* __restrict__ Chi, int N, int K)
{
    extern __shared__ char sm[];
    const int tid = threadIdx.x;
    const int wid = tid >> 5, lane = tid & 31;
    const int bm = blockIdx.y * 128, bn = blockIdx.x * 128;
    const int wm = (wid & 3) * 32, wn = (wid >> 2) * 64;
    const uint32_t sb = smem_u32(sm);

    float acc[2][8][4];
    #pragma unroll
    for (int i = 0; i < 2; i++)
        #pragma unroll
        for (int j = 0; j < 8; j++)
            #pragma unroll
            for (int d = 0; d < 4; d++) acc[i][j][d] = 0.f;

    const int r_ld = tid >> 1;
    const int s_ld = (tid & 1) * 2;

    auto issue = [&](int c) {
        uint32_t st = sb + (uint32_t)(c % 3) * Q_STAGE;
        int k0 = c * 32;
        #pragma unroll
        for (int j = 0; j < 2; j++) {
            int s = s_ld + j;
            uint32_t o = off32(r_ld, s);
            cp16(st + o,         Ah + (size_t)(bm + r_ld) * K + k0 + s * 8);
            cp16(st + 8192 + o,  Al + (size_t)(bm + r_ld) * K + k0 + s * 8);
            cp16(st + 16384 + o, Bh + (size_t)(bn + r_ld) * K + k0 + s * 8);
        }
        cp_commit();
    };

    const int NC = K / 32;
    issue(0);
    issue(1);
    issue(2);

    for (int c = 0; c < NC; c++) {
        if (c + 2 < NC) cp_wait<2>(); else if (c + 1 < NC) cp_wait<1>(); else cp_wait<0>();
        __syncthreads();
        uint32_t st = sb + (uint32_t)(c % 3) * Q_STAGE;
        #pragma unroll
        for (int ks = 0; ks < 2; ks++) {
            uint32_t a_h[8], a_l[8];
            #pragma unroll
            for (int mt = 0; mt < 2; mt++) {
                int row = wm + mt * 16 + (lane & 7) + ((lane >> 3) & 1) * 8;
                int seg = ks * 2 + (lane >> 4);
                uint32_t oa = off32(row, seg);
                ldm_x4(a_h + mt * 4, st + oa);
                ldm_x4(a_l + mt * 4, st + 8192 + oa);
            }
            uint32_t bh[16];
            #pragma unroll
            for (int ntp = 0; ntp < 4; ntp++) {
                int row = wn + ntp * 16 + (lane & 7) + ((lane >> 4) & 1) * 8;
                int seg = ks * 2 + ((lane >> 3) & 1);
                ldm_x4(bh + ntp * 4, st + 16384 + off32(row, seg));
            }
            #pragma unroll
            for (int ntp = 0; ntp < 4; ntp++)
                #pragma unroll
                for (int half = 0; half < 2; half++)
                    #pragma unroll
                    for (int mt = 0; mt < 2; mt++)
                        mma_bf16(acc[mt][ntp*2+half], a_h + mt*4, bh + ntp*4 + half*2);
            #pragma unroll
            for (int ntp = 0; ntp < 4; ntp++)
                #pragma unroll
                for (int half = 0; half < 2; half++)
                    #pragma unroll
                    for (int mt = 0; mt < 2; mt++)
                        mma_bf16(acc[mt][ntp*2+half], a_l + mt*4, bh + ntp*4 + half*2);
        }
        __syncthreads();
        if (c + 3 < NC) issue(c + 3);
    }

    #pragma unroll
    for (int mt = 0; mt < 2; mt++) {
        int r0 = bm + wm + mt * 16 + (lane >> 2);
        #pragma unroll
        for (int nt = 0; nt < 8; nt++) {
            int col = bn + wn + nt * 8 + (lane & 3) * 2;
            float b0 = bias[col], b1 = bias[col + 1];
            float* a = acc[mt][nt];
            *(uint32_t*)(Chi + (size_t)r0 * N + col)       = pk(a[0] + b0, a[1] + b1);
            *(uint32_t*)(Chi + (size_t)(r0 + 8) * N + col) = pk(a[2] + b0, a[3] + b1);
        }
    }
}

// ---------------- Flash attention via mma.sync (bf16-hi only) ----------------
// grid: (SEQ/64, NH, B); 128 thr (4 warps, 16 q-rows each), 4 CTAs/SM.
// Scores in log2 units -> exp2f softmax; skip-rescale ballot.
// smem: Qhi 8K @0; KV 3 stages @8192, stride 16384: Kh, Vh(+8192)
static constexpr int A_SMEM = 8192 + 3 * 16384;   // 57344

__global__ void __launch_bounds__(128, 4)
attn_mma(const __nv_bfloat16* __restrict__ qkvh, float* __restrict__ out)
{
    extern __shared__ char sm[];
    const int tid = threadIdx.x;
    const int wid = tid >> 5, lane = tid & 31;
    const int h = blockIdx.y, b = blockIdx.z;
    const int tok0 = b * SEQ + blockIdx.x * 64;
    const uint32_t sb = smem_u32(sm);

    // group 0: Q (64 rows x 128B, hi only)
    {
        int r = tid >> 1;
        size_t qrow = (size_t)(tok0 + r) * NQKV + h * HD;
        #pragma unroll
        for (int j = 0; j < 4; j++) {
            int s = (tid & 1) * 4 + j;
            cp16(sb + off64(r, s), qkvh + qrow + s * 8);
        }
        cp_commit();
    }
    auto issueKV = [&](int kb) {
        uint32_t st = sb + 8192 + (uint32_t)(kb % 3) * 16384;
        int r = tid >> 1;
        size_t kvrow = (size_t)(b * SEQ + kb * 64 + r) * NQKV + h * HD;
        #pragma unroll
        for (int j = 0; j < 4; j++) {
            int s = (tid & 1) * 4 + j;
            uint32_t o = off64(r, s);
            cp16(st + o, qkvh + kvrow + 1024 + s * 8);          // K hi
            cp16(st + 8192 + o, qkvh + kvrow + 2048 + s * 8);   // V hi
        }
        cp_commit();
    };
    issueKV(0);
    issueKV(1);
    issueKV(2);

    cp_wait<2>(); // Q + KV0 done
    __syncthreads();

    // Q fragments (registers, reused all blocks)
    uint32_t qf[4][4];
    {
        int row = wid * 16 + (lane & 7) + ((lane >> 3) & 1) * 8;
        #pragma unroll
        for (int ks = 0; ks < 4; ks++) {
            int seg = ks * 2 + (lane >> 4);
            ldm_x4(qf[ks], sb + off64(row, seg));
        }
    }

    float o_acc[8][4];
    #pragma unroll
    for (int i = 0; i < 8; i++)
        #pragma unroll
        for (int d = 0; d < 4; d++) o_acc[i][d] = 0.f;
    float runA = -INFINITY, runB = -INFINITY, lA = 0.f, lB = 0.f;

    const int NKB = SEQ / 64;
    for (int kb = 0; kb < NKB; kb++) {
        if (kb > 0) {
            if (kb + 2 < NKB) cp_wait<2>();
            else if (kb + 1 < NKB) cp_wait<1>();
            else cp_wait<0>();
            __syncthreads();
        }
        uint32_t st = sb + 8192 + (uint32_t)(kb % 3) * 16384;
        // ---- scores S[16,64] (log2 units), single bf16 pass ----
        float s[8][4];
        #pragma unroll
        for (int i = 0; i < 8; i++)
            #pragma unroll
            for (int d = 0; d < 4; d++) s[i][d] = 0.f;
        #pragma unroll
        for (int ks = 0; ks < 4; ks++) {
            uint32_t bh[16];
            #pragma unroll
            for (int ntp = 0; ntp < 4; ntp++) {
                int row = ntp * 16 + (lane & 7) + ((lane >> 4) & 1) * 8;
                int seg = ks * 2 + ((lane >> 3) & 1);
                ldm_x4(bh + ntp * 4, st + off64(row, seg));
            }
            #pragma unroll
            for (int ntp = 0; ntp < 4; ntp++)
                #pragma unroll
                for (int half = 0; half < 2; half++)
                    mma_bf16(s[ntp * 2 + half], qf[ks], bh + ntp * 4 + half * 2);
        }
        // ---- online softmax in base 2 (rows: A = lane>>2, B = +8) ----
        float mA = -INFINITY, mB = -INFINITY;
        #pragma unroll
        for (int nt = 0; nt < 8; nt++) {
            mA = fmaxf(mA, fmaxf(s[nt][0], s[nt][1]));
            mB = fmaxf(mB, fmaxf(s[nt][2], s[nt][3]));
        }
        mA = fmaxf(mA, __shfl_xor_sync(0xffffffffu, mA, 1));
        mA = fmaxf(mA, __shfl_xor_sync(0xffffffffu, mA, 2));
        mB = fmaxf(mB, __shfl_xor_sync(0xffffffffu, mB, 1));
        mB = fmaxf(mB, __shfl_xor_sync(0xffffffffu, mB, 2));
        // skip the rescale entirely when no row's max moved (common after warmup)
        unsigned chg = __ballot_sync(0xffffffffu, (mA > runA) || (mB > runB));
        if (chg) {
            float nA = fmaxf(runA, mA), nB = fmaxf(runB, mB);
            float cA = exp2f(runA - nA), cB = exp2f(runB - nB);
            runA = nA; runB = nB;
            lA *= cA; lB *= cB;
            #pragma unroll
            for (int nt = 0; nt < 8; nt++) {
                o_acc[nt][0] *= cA; o_acc[nt][1] *= cA;
                o_acc[nt][2] *= cB; o_acc[nt][3] *= cB;
            }
        }
        float sumA = 0.f, sumB = 0.f;
        #pragma unroll
        for (int nt = 0; nt < 8; nt++) {
            s[nt][0] = exp2f(s[nt][0] - runA); sumA += s[nt][0];
            s[nt][1] = exp2f(s[nt][1] - runA); sumA += s[nt][1];
            s[nt][2] = exp2f(s[nt][2] - runB); sumB += s[nt][2];
            s[nt][3] = exp2f(s[nt][3] - runB); sumB += s[nt][3];
        }
        lA += sumA; lB += sumB;
        // ---- P (bf16 A-frags, pure register repack) ----
        uint32_t pf[4][4];
        #pragma unroll
        for (int j = 0; j < 4; j++) {
            pf[j][0] = pk(s[2*j][0],   s[2*j][1]);
            pf[j][1] = pk(s[2*j][2],   s[2*j][3]);
            pf[j][2] = pk(s[2*j+1][0], s[2*j+1][1]);
            pf[j][3] = pk(s[2*j+1][2], s[2*j+1][3]);
        }
        // ---- O += P @ V (batched V-frag loads) ----
        #pragma unroll
        for (int ks = 0; ks < 4; ks++) {
            uint32_t vb[16];
            #pragma unroll
            for (int ntp = 0; ntp < 4; ntp++) {
                int row = ks * 16 + (lane & 7) + ((lane >> 3) & 1) * 8;
                int seg = ntp * 2 + (lane >> 4);
                ldm_x4t(vb + ntp * 4, st + 8192 + off64(row, seg));
            }
            #pragma unroll
            for (int ntp = 0; ntp < 4; ntp++) {
                mma_bf16(o_acc[ntp * 2 + 0], pf[ks], vb + ntp * 4 + 0);
                mma_bf16(o_acc[ntp * 2 + 1], pf[ks], vb + ntp * 4 + 2);
            }
        }
        __syncthreads();
        if (kb + 3 < NKB) issueKV(kb + 3);
    }

    // finalize: row sums live in quads
    lA += __shfl_xor_sync(0xffffffffu, lA, 1);
    lA += __shfl_xor_sync(0xffffffffu, lA, 2);
    lB += __shfl_xor_sync(0xffffffffu, lB, 1);
    lB += __shfl_xor_sync(0xffffffffu, lB, 2);
    float iA = 1.f / lA, iB = 1.f / lB;
    int rowA = tok0 + wid * 16 + (lane >> 2);
    #pragma unroll
    for (int nt = 0; nt < 8; nt++) {
        int col = h * HD + nt * 8 + (lane & 3) * 2;
        float2 p0 = {o_acc[nt][0] * iA, o_acc[nt][1] * iA};
        float2 p1 = {o_acc[nt][2] * iB, o_acc[nt][3] * iB};
        *(float2*)(out + (size_t)rowA * DIM + col) = p0;
        *(float2*)(out + (size_t)(rowA + 8) * DIM + col) = p1;
    }
}

// ---------------- launch ----------------
extern "C" void kernel_launch(void* const* d_in, const int* in_sizes, int n_in,
                              void* d_out, int out_size)
{
    (void)in_sizes; (void)n_in; (void)out_size;
    const float* x   = (const float*)d_in[0];
    const float* Wq  = (const float*)d_in[1];
    const float* bq  = (const float*)d_in[2];
    const float* Wk  = (const float*)d_in[3];
    const float* bk  = (const float*)d_in[4];
    const float* Wv  = (const float*)d_in[5];
    const float* bv  = (const float*)d_in[6];
    const float* g1  = (const float*)d_in[7];
    const float* b1  = (const float*)d_in[8];
    const float* g2  = (const float*)d_in[9];
    const float* b2  = (const float*)d_in[10];
    const float* W1  = (const float*)d_in[11];
    const float* bf1 = (const float*)d_in[12];
    const float* W2  = (const float*)d_in[13];
    const float* bf2 = (const float*)d_in[14];

    float *xn, *attn, *bqkv;
    cudaGetSymbolAddress((void**)&xn,   g_xn);
    cudaGetSymbolAddress((void**)&attn, g_attn);
    cudaGetSymbolAddress((void**)&bqkv, g_bqkv);

    __nv_bfloat16 *xnh, *xnl, *qkvh, *hh, *hl, *f1h, *f1l;
    __nv_bfloat16 *wqkvh, *w1h, *w1l, *w2h, *w2l;
    cudaGetSymbolAddress((void**)&xnh,   g_xn_hi);   cudaGetSymbolAddress((void**)&xnl,   g_xn_lo);
    cudaGetSymbolAddress((void**)&qkvh,  g_qkv_hi);
    cudaGetSymbolAddress((void**)&hh,    g_h_hi);    cudaGetSymbolAddress((void**)&hl,    g_h_lo);
    cudaGetSymbolAddress((void**)&f1h,   g_ff1_hi);  cudaGetSymbolAddress((void**)&f1l,   g_ff1_lo);
    cudaGetSymbolAddress((void**)&wqkvh, g_wqkv_hi);
    cudaGetSymbolAddress((void**)&w1h,   g_w1_hi);   cudaGetSymbolAddress((void**)&w1l,   g_w1_lo);
    cudaGetSymbolAddress((void**)&w2h,   g_w2_hi);   cudaGetSymbolAddress((void**)&w2l,   g_w2_lo);

    cudaFuncSetAttribute(gemm_mma<1>, cudaFuncAttributeMaxDynamicSharedMemorySize, G_SMEM);
    cudaFuncSetAttribute(gemm_mma<2>, cudaFuncAttributeMaxDynamicSharedMemorySize, G_SMEM);
    cudaFuncSetAttribute(gemm_qkv,    cudaFuncAttributeMaxDynamicSharedMemorySize, Q_SMEM);
    cudaFuncSetAttribute(attn_mma,    cudaFuncAttributeMaxDynamicSharedMemorySize, A_SMEM);

    // launch 0: merged weight splits (+ bias concat, Q pre-scaled by 1/8*log2e)
    wsplit_all<<<(WS_TOT + 255)/256, 256>>>(Wq, Wk, Wv, W1, W2, bq, bk, bv,
                                            wqkvh, w1h, w1l, w2h, w2l, bqkv);

    // launch 1: xn = LN(x) : fp32 + splits
    ln_kernel<<<NTOK, 256>>>(x, nullptr, g1, b1, xn, xnh, xnl);

    // launch 2: fused QKV projection, 2-term -> bf16 hi [NTOK, 3072]
    dim3 gQKV(NQKV / 128, NTOK / 128);
    gemm_qkv<<<gQKV, 256, Q_SMEM>>>(xnh, xnl, wqkvh, bqkv, qkvh, NQKV, DIM);

    // launch 3: attention (tensor-core flash, single-pass bf16 scores, 4 CTAs/SM)
    attn_mma<<<dim3(SEQ / 64, NH, 2), 128, A_SMEM>>>(qkvh, attn);

    // launch 4: h = LN(attn + xn) -> splits
    ln_kernel<<<NTOK, 256>>>(attn, xn, g2, b2, nullptr, hh, hl);

    // launch 5: ff1 = silu(h @ W1^T + bf1) -> bf16 splits (3-term)
    dim3 gF1(DFF / 128, NTOK / 128);
    gemm_mma<1><<<gF1, 256, G_SMEM>>>(hh, hl, w1h, w1l, bf1, nullptr,
                                      nullptr, f1h, f1l, DFF, DIM);

    // launch 6: out = ff1 @ W2^T + bf2 + xn (3-term)
    dim3 gF2(DIM / 128, NTOK / 128);
    gemm_mma<2><<<gF2, 256, G_SMEM>>>(f1h, f1l, w2h, w2l, bf2, xn,
                                      (float*)d_out, nullptr, nullptr, DIM, DFF);
}

// round 14
// speedup vs baseline: 9.3259x; 1.5655x over previous
#include <cuda_runtime.h>
#include <cuda_fp16.h>
#include <math.h>
#include <stdint.h>

#define NTOK 4096          // B*S
#define SEQ  2048
#define DIM  1024
#define NH   16
#define HD   64
#define DFF  4096
#define NQKV 3072

#define QSCALE (0.125f * 1.44269504088896f)   // 1/sqrt(64) * log2(e)

// ---------------- scratch (device globals; no allocs allowed) ----------------
__device__ float g_xn[NTOK * DIM];
__device__ float g_attn[NTOK * DIM];
__device__ float g_bqkv[NQKV];

__device__ __half g_xn_h[NTOK * DIM];
__device__ __half g_qkv_h[NTOK * NQKV];
__device__ __half g_h_h[NTOK * DIM];
__device__ __half g_ff1_h[NTOK * DFF];
__device__ __half g_wqkv_h[NQKV * DIM], g_wqkv_l[NQKV * DIM];
__device__ __half g_w1_h[DFF * DIM],    g_w1_l[DFF * DIM];
__device__ __half g_w2_h[DIM * DFF],    g_w2_l[DIM * DFF];

// ---------------- PTX helpers (family-portable sm_80-era ISA) ----------------
__device__ __forceinline__ uint32_t smem_u32(const void* p) {
    uint32_t a;
    asm("{ .reg .u64 t; cvta.to.shared.u64 t, %1; cvt.u32.u64 %0, t; }" : "=r"(a) : "l"(p));
    return a;
}
__device__ __forceinline__ void cp16(uint32_t dst, const void* src) {
    asm volatile("cp.async.cg.shared.global [%0], [%1], 16;" :: "r"(dst), "l"(src) : "memory");
}
__device__ __forceinline__ void cp_commit() {
    asm volatile("cp.async.commit_group;" ::: "memory");
}
template<int N> __device__ __forceinline__ void cp_wait() {
    asm volatile("cp.async.wait_group %0;" :: "n"(N) : "memory");
}
__device__ __forceinline__ void ldm_x4(uint32_t* r, uint32_t addr) {
    asm volatile("ldmatrix.sync.aligned.m8n8.x4.shared.b16 {%0,%1,%2,%3}, [%4];"
        : "=r"(r[0]), "=r"(r[1]), "=r"(r[2]), "=r"(r[3]) : "r"(addr));
}
__device__ __forceinline__ void ldm_x4t(uint32_t* r, uint32_t addr) {
    asm volatile("ldmatrix.sync.aligned.m8n8.x4.trans.shared.b16 {%0,%1,%2,%3}, [%4];"
        : "=r"(r[0]), "=r"(r[1]), "=r"(r[2]), "=r"(r[3]) : "r"(addr));
}
__device__ __forceinline__ void mma_f16(float* d, const uint32_t* a, const uint32_t* b) {
    asm volatile(
        "mma.sync.aligned.m16n8k16.row.col.f32.f16.f16.f32 "
        "{%0,%1,%2,%3}, {%4,%5,%6,%7}, {%8,%9}, {%0,%1,%2,%3};"
        : "+f"(d[0]), "+f"(d[1]), "+f"(d[2]), "+f"(d[3])
        : "r"(a[0]), "r"(a[1]), "r"(a[2]), "r"(a[3]), "r"(b[0]), "r"(b[1]));
}
__device__ __forceinline__ uint32_t pkh(float lo, float hi) {
    __half2 t = __floats2half2_rn(lo, hi);
    return *(uint32_t*)&t;
}
// split fp32 -> (hi, lo) fp16 pair
__device__ __forceinline__ void splith2(float v0, float v1, uint32_t& h, uint32_t& l) {
    __half h0 = __float2half_rn(v0), h1 = __float2half_rn(v1);
    h = pkh(__half2float(h0), __half2float(h1));
    l = pkh(v0 - __half2float(h0), v1 - __half2float(h1));
}
// 32-col fp16 tile (64B rows, 4x16B segs)
__device__ __forceinline__ uint32_t off32(int r, int s) {
    return (uint32_t)(r * 64 + ((s ^ ((r >> 1) & 3)) << 4));
}
// 64-col fp16 tile (128B rows, 8x16B segs)
__device__ __forceinline__ uint32_t off64(int r, int s) {
    return (uint32_t)(r * 128 + ((s ^ (r & 7)) << 4));
}

// ---------------- weight splits: QKV (+ bias concat, Q pre-scaled) ----------------
static constexpr int WSA_QKV = NQKV * DIM / 4;
static constexpr int WSA_B   = NQKV / 4;
static constexpr int WSA_TOT = WSA_QKV + WSA_B;

__global__ __launch_bounds__(256)
void wsplit_a(const float* __restrict__ Wq, const float* __restrict__ Wk,
              const float* __restrict__ Wv, const float* __restrict__ bq,
              const float* __restrict__ bk, const float* __restrict__ bv,
              __half* __restrict__ wh, __half* __restrict__ wl,
              float* __restrict__ bqkv)
{
    int i = blockIdx.x * 256 + threadIdx.x;
    if (i >= WSA_TOT) return;
    if (i < WSA_QKV) {
        int e = i * 4;
        int r = e >> 10;
        float sc = 1.0f;
        const float* src;
        if (r < 1024)      { src = Wq + e;                sc = QSCALE; }
        else if (r < 2048) { src = Wk + (e - 1024*1024); }
        else               { src = Wv + (e - 2048*1024); }
        float4 v = *(const float4*)src;
        uint2 uh, ul;
        splith2(v.x * sc, v.y * sc, uh.x, ul.x);
        splith2(v.z * sc, v.w * sc, uh.y, ul.y);
        *(uint2*)(wh + e) = uh;
        *(uint2*)(wl + e) = ul;
    } else {
        int e = (i - WSA_QKV) * 4;
        #pragma unroll
        for (int j = 0; j < 4; j++) {
            int c = e + j;
            float b = (c < 1024) ? QSCALE * bq[c]
                    : (c < 2048) ? bk[c - 1024] : bv[c - 2048];
            bqkv[c] = b;
        }
    }
}

// ---------------- weight splits: W1, W2 ----------------
static constexpr int WSB_W1  = DFF * DIM / 4;
static constexpr int WSB_W2  = DIM * DFF / 4;
static constexpr int WSB_TOT = WSB_W1 + WSB_W2;

__global__ __launch_bounds__(256)
void wsplit_b(const float* __restrict__ W1, const float* __restrict__ W2,
              __half* __restrict__ w1h, __half* __restrict__ w1l,
              __half* __restrict__ w2h, __half* __restrict__ w2l)
{
    int i = blockIdx.x * 256 + threadIdx.x;
    if (i >= WSB_TOT) return;
    if (i < WSB_W1) {
        int e = i * 4;
        float4 v = *(const float4*)(W1 + e);
        uint2 uh, ul;
        splith2(v.x, v.y, uh.x, ul.x);
        splith2(v.z, v.w, uh.y, ul.y);
        *(uint2*)(w1h + e) = uh;
        *(uint2*)(w1l + e) = ul;
    } else {
        int e = (i - WSB_W1) * 4;
        float4 v = *(const float4*)(W2 + e);
        uint2 uh, ul;
        splith2(v.x, v.y, uh.x, ul.x);
        splith2(v.z, v.w, uh.y, ul.y);
        *(uint2*)(w2h + e) = uh;
        *(uint2*)(w2l + e) = ul;
    }
}

// ---------------- LayerNorm (optional residual; fp32 out + fp16 out) ----------------
__global__ __launch_bounds__(256)
void ln_kernel(const float* __restrict__ x, const float* __restrict__ res,
               const float* __restrict__ gamma, const float* __restrict__ beta,
               float* __restrict__ out, __half* __restrict__ oh)
{
    int row = blockIdx.x;
    int t = threadIdx.x;
    const float4* xr = (const float4*)(x + (size_t)row * DIM);
    float4 v = xr[t];
    if (res) {
        const float4* rr = (const float4*)(res + (size_t)row * DIM);
        float4 r = rr[t];
        v.x += r.x; v.y += r.y; v.z += r.z; v.w += r.w;
    }
    float s  = v.x + v.y + v.z + v.w;
    float s2 = v.x*v.x + v.y*v.y + v.z*v.z + v.w*v.w;
    #pragma unroll
    for (int o = 16; o > 0; o >>= 1) {
        s  += __shfl_down_sync(0xffffffffu, s,  o);
        s2 += __shfl_down_sync(0xffffffffu, s2, o);
    }
    __shared__ float ss[8], ss2[8];
    __shared__ float mean_s, rstd_s;
    if ((t & 31) == 0) { ss[t >> 5] = s; ss2[t >> 5] = s2; }
    __syncthreads();
    if (t == 0) {
        float a = 0.f, b = 0.f;
        #pragma unroll
        for (int i = 0; i < 8; i++) { a += ss[i]; b += ss2[i]; }
        float mean = a * (1.0f / DIM);
        float var  = b * (1.0f / DIM) - mean * mean;
        mean_s = mean;
        rstd_s = rsqrtf(var + 1e-5f);
    }
    __syncthreads();
    float mean = mean_s, rstd = rstd_s;
    float4 g = ((const float4*)gamma)[t];
    float4 bb = ((const float4*)beta)[t];
    float4 o4;
    o4.x = (v.x - mean) * rstd * g.x + bb.x;
    o4.y = (v.y - mean) * rstd * g.y + bb.y;
    o4.z = (v.z - mean) * rstd * g.z + bb.z;
    o4.w = (v.w - mean) * rstd * g.w + bb.w;
    size_t idx = (size_t)row * DIM + t * 4;
    if (out) *(float4*)(out + idx) = o4;
    uint2 uh;
    uh.x = pkh(o4.x, o4.y);
    uh.y = pkh(o4.z, o4.w);
    *(uint2*)(oh + idx) = uh;
}

// ---------------- unified 2-term fp16 GEMM: C = A @ (Wh+Wl)^T ----------------
// A fp16 single; weights split. CTA 128x128, 8 warps (32x64), K-chunk 32,
// 3-stage / lookahead-2 cp.async (single sync per chunk), 2 CTAs/SM.
// EPI: 0 = bias -> fp16 ; 1 = bias+silu -> fp16 ; 2 = bias+res -> fp32
static constexpr int G_STAGE = 24576;   // A(8K) Bh(8K) Bl(8K)
static constexpr int G_SMEM = 3 * G_STAGE;

template<int EPI>
__global__ void __launch_bounds__(256, 2)
gemm_h(const __half* __restrict__ A, const __half* __restrict__ Bh,
       const __half* __restrict__ Bl, const float* __restrict__ bias,
       const float* __restrict__ res, float* __restrict__ C,
       __half* __restrict__ Ch, int N, int K)
{
    extern __shared__ char sm[];
    const int tid = threadIdx.x;
    const int wid = tid >> 5, lane = tid & 31;
    const int bm = blockIdx.y * 128, bn = blockIdx.x * 128;
    const int wm = (wid & 3) * 32, wn = (wid >> 2) * 64;
    const uint32_t sb = smem_u32(sm);

    float acc[2][8][4];
    #pragma unroll
    for (int i = 0; i < 2; i++)
        #pragma unroll
        for (int j = 0; j < 8; j++)
            #pragma unroll
            for (int d = 0; d < 4; d++) acc[i][j][d] = 0.f;

    const int r_ld = tid >> 1;
    const int s_ld = (tid & 1) * 2;

    auto issue = [&](int c) {
        uint32_t st = sb + (uint32_t)(c % 3) * G_STAGE;
        int k0 = c * 32;
        #pragma unroll
        for (int j = 0; j < 2; j++) {
            int s = s_ld + j;
            uint32_t o = off32(r_ld, s);
            cp16(st + o,         A  + (size_t)(bm + r_ld) * K + k0 + s * 8);
            cp16(st + 8192 + o,  Bh + (size_t)(bn + r_ld) * K + k0 + s * 8);
            cp16(st + 16384 + o, Bl + (size_t)(bn + r_ld) * K + k0 + s * 8);
        }
        cp_commit();
    };

    const int NC = K / 32;
    issue(0);
    issue(1);

    for (int c = 0; c < NC; c++) {
        if (c + 1 < NC) cp_wait<1>(); else cp_wait<0>();
        __syncthreads();
        uint32_t st = sb + (uint32_t)(c % 3) * G_STAGE;
        #pragma unroll
        for (int ks = 0; ks < 2; ks++) {
            uint32_t a[8];
            #pragma unroll
            for (int mt = 0; mt < 2; mt++) {
                int row = wm + mt * 16 + (lane & 7) + ((lane >> 3) & 1) * 8;
                int seg = ks * 2 + (lane >> 4);
                ldm_x4(a + mt * 4, st + off32(row, seg));
            }
            uint32_t bh[16], bl[16];
            #pragma unroll
            for (int ntp = 0; ntp < 4; ntp++) {
                int row = wn + ntp * 16 + (lane & 7) + ((lane >> 4) & 1) * 8;
                int seg = ks * 2 + ((lane >> 3) & 1);
                uint32_t ob = off32(row, seg);
                ldm_x4(bh + ntp * 4, st + 8192 + ob);
                ldm_x4(bl + ntp * 4, st + 16384 + ob);
            }
            #pragma unroll
            for (int ntp = 0; ntp < 4; ntp++)
                #pragma unroll
                for (int half = 0; half < 2; half++)
                    #pragma unroll
                    for (int mt = 0; mt < 2; mt++)
                        mma_f16(acc[mt][ntp*2+half], a + mt*4, bh + ntp*4 + half*2);
            #pragma unroll
            for (int ntp = 0; ntp < 4; ntp++)
                #pragma unroll
                for (int half = 0; half < 2; half++)
                    #pragma unroll
                    for (int mt = 0; mt < 2; mt++)
                        mma_f16(acc[mt][ntp*2+half], a + mt*4, bl + ntp*4 + half*2);
        }
        if (c + 2 < NC) issue(c + 2);   // writes stage (c+2)%3 != c%3 : no sync needed
    }

    #pragma unroll
    for (int mt = 0; mt < 2; mt++) {
        int r0 = bm + wm + mt * 16 + (lane >> 2);
        #pragma unroll
        for (int nt = 0; nt < 8; nt++) {
            int col = bn + wn + nt * 8 + (lane & 3) * 2;
            float b0 = bias[col], b1 = bias[col + 1];
            float* a = acc[mt][nt];
            if (EPI == 0) {
                *(uint32_t*)(Ch + (size_t)r0 * N + col)       = pkh(a[0] + b0, a[1] + b1);
                *(uint32_t*)(Ch + (size_t)(r0 + 8) * N + col) = pkh(a[2] + b0, a[3] + b1);
            } else if (EPI == 1) {
                float v0 = a[0] + b0, v1 = a[1] + b1, v2 = a[2] + b0, v3 = a[3] + b1;
                v0 = v0 / (1.f + __expf(-v0));
                v1 = v1 / (1.f + __expf(-v1));
                v2 = v2 / (1.f + __expf(-v2));
                v3 = v3 / (1.f + __expf(-v3));
                *(uint32_t*)(Ch + (size_t)r0 * N + col)       = pkh(v0, v1);
                *(uint32_t*)(Ch + (size_t)(r0 + 8) * N + col) = pkh(v2, v3);
            } else {
                float2 p0, p1;
                float2 rr0 = *(const float2*)(res + (size_t)r0 * N + col);
                float2 rr1 = *(const float2*)(res + (size_t)(r0 + 8) * N + col);
                p0.x = a[0] + b0 + rr0.x; p0.y = a[1] + b1 + rr0.y;
                p1.x = a[2] + b0 + rr1.x; p1.y = a[3] + b1 + rr1.y;
                *(float2*)(C + (size_t)r0 * N + col) = p0;
                *(float2*)(C + (size_t)(r0 + 8) * N + col) = p1;
            }
        }
    }
}

// ---------------- Flash attention via mma.sync (fp16) ----------------
// grid: (SEQ/64, NH, B); 128 thr (4 warps, 16 q-rows each), 4 CTAs/SM.
// Scores in log2 units -> exp2f softmax; skip-rescale ballot.
// smem: Q 8K @0; KV 3 stages @8192 stride 16384 (lookahead-2, single sync): K, V(+8192)
static constexpr int A_SMEM = 8192 + 3 * 16384;   // 57344

__global__ void __launch_bounds__(128, 4)
attn_mma(const __half* __restrict__ qkvh, float* __restrict__ out)
{
    extern __shared__ char sm[];
    const int tid = threadIdx.x;
    const int wid = tid >> 5, lane = tid & 31;
    const int h = blockIdx.y, b = blockIdx.z;
    const int tok0 = b * SEQ + blockIdx.x * 64;
    const uint32_t sb = smem_u32(sm);

    // group 0: Q (64 rows x 128B)
    {
        int r = tid >> 1;
        size_t qrow = (size_t)(tok0 + r) * NQKV + h * HD;
        #pragma unroll
        for (int j = 0; j < 4; j++) {
            int s = (tid & 1) * 4 + j;
            cp16(sb + off64(r, s), qkvh + qrow + s * 8);
        }
        cp_commit();
    }
    auto issueKV = [&](int kb) {
        uint32_t st = sb + 8192 + (uint32_t)(kb % 3) * 16384;
        int r = tid >> 1;
        size_t kvrow = (size_t)(b * SEQ + kb * 64 + r) * NQKV + h * HD;
        #pragma unroll
        for (int j = 0; j < 4; j++) {
            int s = (tid & 1) * 4 + j;
            uint32_t o = off64(r, s);
            cp16(st + o, qkvh + kvrow + 1024 + s * 8);          // K
            cp16(st + 8192 + o, qkvh + kvrow + 2048 + s * 8);   // V
        }
        cp_commit();
    };
    issueKV(0);
    issueKV(1);

    cp_wait<1>(); // Q + KV0 done
    __syncthreads();

    // Q fragments (registers, reused all blocks)
    uint32_t qf[4][4];
    {
        int row = wid * 16 + (lane & 7) + ((lane >> 3) & 1) * 8;
        #pragma unroll
        for (int ks = 0; ks < 4; ks++) {
            int seg = ks * 2 + (lane >> 4);
            ldm_x4(qf[ks], sb + off64(row, seg));
        }
    }

    float o_acc[8][4];
    #pragma unroll
    for (int i = 0; i < 8; i++)
        #pragma unroll
        for (int d = 0; d < 4; d++) o_acc[i][d] = 0.f;
    float runA = -INFINITY, runB = -INFINITY, lA = 0.f, lB = 0.f;

    const int NKB = SEQ / 64;
    for (int kb = 0; kb < NKB; kb++) {
        if (kb > 0) {
            if (kb + 1 < NKB) cp_wait<1>(); else cp_wait<0>();
            __syncthreads();
        }
        uint32_t st = sb + 8192 + (uint32_t)(kb % 3) * 16384;
        // ---- scores S[16,64] (log2 units) ----
        float s[8][4];
        #pragma unroll
        for (int i = 0; i < 8; i++)
            #pragma unroll
            for (int d = 0; d < 4; d++) s[i][d] = 0.f;
        #pragma unroll
        for (int ks = 0; ks < 4; ks++) {
            uint32_t bh[16];
            #pragma unroll
            for (int ntp = 0; ntp < 4; ntp++) {
                int row = ntp * 16 + (lane & 7) + ((lane >> 4) & 1) * 8;
                int seg = ks * 2 + ((lane >> 3) & 1);
                ldm_x4(bh + ntp * 4, st + off64(row, seg));
            }
            #pragma unroll
            for (int ntp = 0; ntp < 4; ntp++)
                #pragma unroll
                for (int half = 0; half < 2; half++)
                    mma_f16(s[ntp * 2 + half], qf[ks], bh + ntp * 4 + half * 2);
        }
        // ---- online softmax in base 2 (rows: A = lane>>2, B = +8) ----
        float mA = -INFINITY, mB = -INFINITY;
        #pragma unroll
        for (int nt = 0; nt < 8; nt++) {
            mA = fmaxf(mA, fmaxf(s[nt][0], s[nt][1]));
            mB = fmaxf(mB, fmaxf(s[nt][2], s[nt][3]));
        }
        mA = fmaxf(mA, __shfl_xor_sync(0xffffffffu, mA, 1));
        mA = fmaxf(mA, __shfl_xor_sync(0xffffffffu, mA, 2));
        mB = fmaxf(mB, __shfl_xor_sync(0xffffffffu, mB, 1));
        mB = fmaxf(mB, __shfl_xor_sync(0xffffffffu, mB, 2));
        unsigned chg = __ballot_sync(0xffffffffu, (mA > runA) || (mB > runB));
        if (chg) {
            float nA = fmaxf(runA, mA), nB = fmaxf(runB, mB);
            float cA = exp2f(runA - nA), cB = exp2f(runB - nB);
            runA = nA; runB = nB;
            lA *= cA; lB *= cB;
            #pragma unroll
            for (int nt = 0; nt < 8; nt++) {
                o_acc[nt][0] *= cA; o_acc[nt][1] *= cA;
                o_acc[nt][2] *= cB; o_acc[nt][3] *= cB;
            }
        }
        float sumA = 0.f, sumB = 0.f;
        #pragma unroll
        for (int nt = 0; nt < 8; nt++) {
            s[nt][0] = exp2f(s[nt][0] - runA); sumA += s[nt][0];
            s[nt][1] = exp2f(s[nt][1] - runA); sumA += s[nt][1];
            s[nt][2] = exp2f(s[nt][2] - runB); sumB += s[nt][2];
            s[nt][3] = exp2f(s[nt][3] - runB); sumB += s[nt][3];
        }
        lA += sumA; lB += sumB;
        // ---- P (fp16 A-frags, pure register repack) ----
        uint32_t pf[4][4];
        #pragma unroll
        for (int j = 0; j < 4; j++) {
            pf[j][0] = pkh(s[2*j][0],   s[2*j][1]);
            pf[j][1] = pkh(s[2*j][2],   s[2*j][3]);
            pf[j][2] = pkh(s[2*j+1][0], s[2*j+1][1]);
            pf[j][3] = pkh(s[2*j+1][2], s[2*j+1][3]);
        }
        // ---- O += P @ V ----
        #pragma unroll
        for (int ks = 0; ks < 4; ks++) {
            uint32_t vb[16];
            #pragma unroll
            for (int ntp = 0; ntp < 4; ntp++) {
                int row = ks * 16 + (lane & 7) + ((lane >> 3) & 1) * 8;
                int seg = ntp * 2 + (lane >> 4);
                ldm_x4t(vb + ntp * 4, st + 8192 + off64(row, seg));
            }
            #pragma unroll
            for (int ntp = 0; ntp < 4; ntp++) {
                mma_f16(o_acc[ntp * 2 + 0], pf[ks], vb + ntp * 4 + 0);
                mma_f16(o_acc[ntp * 2 + 1], pf[ks], vb + ntp * 4 + 2);
            }
        }
        if (kb + 2 < NKB) issueKV(kb + 2);   // writes stage (kb+2)%3 != kb%3
    }

    // finalize
    lA += __shfl_xor_sync(0xffffffffu, lA, 1);
    lA += __shfl_xor_sync(0xffffffffu, lA, 2);
    lB += __shfl_xor_sync(0xffffffffu, lB, 1);
    lB += __shfl_xor_sync(0xffffffffu, lB, 2);
    float iA = 1.f / lA, iB = 1.f / lB;
    int rowA = tok0 + wid * 16 + (lane >> 2);
    #pragma unroll
    for (int nt = 0; nt < 8; nt++) {
        int col = h * HD + nt * 8 + (lane & 3) * 2;
        float2 p0 = {o_acc[nt][0] * iA, o_acc[nt][1] * iA};
        float2 p1 = {o_acc[nt][2] * iB, o_acc[nt][3] * iB};
        *(float2*)(out + (size_t)rowA * DIM + col) = p0;
        *(float2*)(out + (size_t)(rowA + 8) * DIM + col) = p1;
    }
}

// ---------------- launch ----------------
extern "C" void kernel_launch(void* const* d_in, const int* in_sizes, int n_in,
                              void* d_out, int out_size)
{
    (void)in_sizes; (void)n_in; (void)out_size;
    const float* x   = (const float*)d_in[0];
    const float* Wq  = (const float*)d_in[1];
    const float* bq  = (const float*)d_in[2];
    const float* Wk  = (const float*)d_in[3];
    const float* bk  = (const float*)d_in[4];
    const float* Wv  = (const float*)d_in[5];
    const float* bv  = (const float*)d_in[6];
    const float* g1  = (const float*)d_in[7];
    const float* b1  = (const float*)d_in[8];
    const float* g2  = (const float*)d_in[9];
    const float* b2  = (const float*)d_in[10];
    const float* W1  = (const float*)d_in[11];
    const float* bf1 = (const float*)d_in[12];
    const float* W2  = (const float*)d_in[13];
    const float* bf2 = (const float*)d_in[14];

    float *xn, *attn, *bqkv;
    cudaGetSymbolAddress((void**)&xn,   g_xn);
    cudaGetSymbolAddress((void**)&attn, g_attn);
    cudaGetSymbolAddress((void**)&bqkv, g_bqkv);

    __half *xnh, *qkvh, *hh, *f1h;
    __half *wqh, *wql, *w1h, *w1l, *w2h, *w2l;
    cudaGetSymbolAddress((void**)&xnh,  g_xn_h);
    cudaGetSymbolAddress((void**)&qkvh, g_qkv_h);
    cudaGetSymbolAddress((void**)&hh,   g_h_h);
    cudaGetSymbolAddress((void**)&f1h,  g_ff1_h);
    cudaGetSymbolAddress((void**)&wqh,  g_wqkv_h);  cudaGetSymbolAddress((void**)&wql, g_wqkv_l);
    cudaGetSymbolAddress((void**)&w1h,  g_w1_h);    cudaGetSymbolAddress((void**)&w1l, g_w1_l);
    cudaGetSymbolAddress((void**)&w2h,  g_w2_h);    cudaGetSymbolAddress((void**)&w2l, g_w2_l);

    cudaFuncSetAttribute(gemm_h<0>, cudaFuncAttributeMaxDynamicSharedMemorySize, G_SMEM);
    cudaFuncSetAttribute(gemm_h<1>, cudaFuncAttributeMaxDynamicSharedMemorySize, G_SMEM);
    cudaFuncSetAttribute(gemm_h<2>, cudaFuncAttributeMaxDynamicSharedMemorySize, G_SMEM);
    cudaFuncSetAttribute(attn_mma,  cudaFuncAttributeMaxDynamicSharedMemorySize, A_SMEM);

    // launch 0: QKV weight split (+ bias concat, Q pre-scaled by 1/8*log2e)
    wsplit_a<<<(WSA_TOT + 255)/256, 256>>>(Wq, Wk, Wv, bq, bk, bv, wqh, wql, bqkv);

    // launch 1: W1/W2 weight split
    wsplit_b<<<(WSB_TOT + 255)/256, 256>>>(W1, W2, w1h, w1l, w2h, w2l);

    // launch 2: xn = LN(x) : fp32 + fp16
    ln_kernel<<<NTOK, 256>>>(x, nullptr, g1, b1, xn, xnh);

    // launch 3 (profiled): fused QKV projection, 2-term -> fp16 [NTOK, 3072]
    dim3 gQKV(NQKV / 128, NTOK / 128);
    gemm_h<0><<<gQKV, 256, G_SMEM>>>(xnh, wqh, wql, bqkv, nullptr, nullptr, qkvh, NQKV, DIM);

    // launch 4: attention (fp16 tensor-core flash, 4 CTAs/SM)
    attn_mma<<<dim3(SEQ / 64, NH, 2), 128, A_SMEM>>>(qkvh, attn);

    // launch 5: h = LN(attn + xn) -> fp16
    ln_kernel<<<NTOK, 256>>>(attn, xn, g2, b2, nullptr, hh);

    // launch 6: ff1 = silu(h @ W1^T + bf1) -> fp16
    dim3 gF1(DFF / 128, NTOK / 128);
    gemm_h<1><<<gF1, 256, G_SMEM>>>(hh, w1h, w1l, bf1, nullptr, nullptr, f1h, DFF, DIM);

    // launch 7: out = ff1 @ W2^T + bf2 + xn
    dim3 gF2(DIM / 128, NTOK / 128);
    gemm_h<2><<<gF2, 256, G_SMEM>>>(f1h, w2h, w2l, bf2, xn, (float*)d_out, nullptr, DIM, DFF);
}

// round 15
// speedup vs baseline: 9.3394x; 1.0015x over previous
#include <cuda_runtime.h>
#include <cuda_fp16.h>
#include <math.h>
#include <stdint.h>

#define NTOK 4096          // B*S
#define SEQ  2048
#define DIM  1024
#define NH   16
#define HD   64
#define DFF  4096
#define NQKV 3072

#define QSCALE (0.125f * 1.44269504088896f)   // 1/sqrt(64) * log2(e)

// ---------------- scratch (device globals; no allocs allowed) ----------------
__device__ float g_xn[NTOK * DIM];
__device__ float g_attn[NTOK * DIM];
__device__ float g_bqkv[NQKV];

__device__ __half g_xn_h[NTOK * DIM];
__device__ __half g_qkv_h[NTOK * NQKV];
__device__ __half g_h_h[NTOK * DIM];
__device__ __half g_ff1_h[NTOK * DFF];
__device__ __half g_wqkv_h[NQKV * DIM];
__device__ __half g_w1_h[DFF * DIM],  g_w1_l[DFF * DIM];
__device__ __half g_w2_h[DIM * DFF],  g_w2_l[DIM * DFF];

// ---------------- PTX helpers (family-portable sm_80-era ISA) ----------------
__device__ __forceinline__ uint32_t smem_u32(const void* p) {
    uint32_t a;
    asm("{ .reg .u64 t; cvta.to.shared.u64 t, %1; cvt.u32.u64 %0, t; }" : "=r"(a) : "l"(p));
    return a;
}
__device__ __forceinline__ void cp16(uint32_t dst, const void* src) {
    asm volatile("cp.async.cg.shared.global [%0], [%1], 16;" :: "r"(dst), "l"(src) : "memory");
}
__device__ __forceinline__ void cp_commit() {
    asm volatile("cp.async.commit_group;" ::: "memory");
}
template<int N> __device__ __forceinline__ void cp_wait() {
    asm volatile("cp.async.wait_group %0;" :: "n"(N) : "memory");
}
__device__ __forceinline__ void ldm_x4(uint32_t* r, uint32_t addr) {
    asm volatile("ldmatrix.sync.aligned.m8n8.x4.shared.b16 {%0,%1,%2,%3}, [%4];"
        : "=r"(r[0]), "=r"(r[1]), "=r"(r[2]), "=r"(r[3]) : "r"(addr));
}
__device__ __forceinline__ void ldm_x4t(uint32_t* r, uint32_t addr) {
    asm volatile("ldmatrix.sync.aligned.m8n8.x4.trans.shared.b16 {%0,%1,%2,%3}, [%4];"
        : "=r"(r[0]), "=r"(r[1]), "=r"(r[2]), "=r"(r[3]) : "r"(addr));
}
__device__ __forceinline__ void mma_f16(float* d, const uint32_t* a, const uint32_t* b) {
    asm volatile(
        "mma.sync.aligned.m16n8k16.row.col.f32.f16.f16.f32 "
        "{%0,%1,%2,%3}, {%4,%5,%6,%7}, {%8,%9}, {%0,%1,%2,%3};"
        : "+f"(d[0]), "+f"(d[1]), "+f"(d[2]), "+f"(d[3])
        : "r"(a[0]), "r"(a[1]), "r"(a[2]), "r"(a[3]), "r"(b[0]), "r"(b[1]));
}
__device__ __forceinline__ uint32_t pkh(float lo, float hi) {
    __half2 t = __floats2half2_rn(lo, hi);
    return *(uint32_t*)&t;
}
__device__ __forceinline__ void splith2(float v0, float v1, uint32_t& h, uint32_t& l) {
    __half h0 = __float2half_rn(v0), h1 = __float2half_rn(v1);
    h = pkh(__half2float(h0), __half2float(h1));
    l = pkh(v0 - __half2float(h0), v1 - __half2float(h1));
}
// 64-col fp16 tile (128B rows, 8x16B segs)
__device__ __forceinline__ uint32_t off64(int r, int s) {
    return (uint32_t)(r * 128 + ((s ^ (r & 7)) << 4));
}

// ---------------- weight prep: QKV hi-only (+ bias concat, Q pre-scaled) ----------------
static constexpr int WSA_QKV = NQKV * DIM / 4;
static constexpr int WSA_B   = NQKV / 4;
static constexpr int WSA_TOT = WSA_QKV + WSA_B;

__global__ __launch_bounds__(256)
void wsplit_a(const float* __restrict__ Wq, const float* __restrict__ Wk,
              const float* __restrict__ Wv, const float* __restrict__ bq,
              const float* __restrict__ bk, const float* __restrict__ bv,
              __half* __restrict__ wh, float* __restrict__ bqkv)
{
    int i = blockIdx.x * 256 + threadIdx.x;
    if (i >= WSA_TOT) return;
    if (i < WSA_QKV) {
        int e = i * 4;
        int r = e >> 10;
        float sc = 1.0f;
        const float* src;
        if (r < 1024)      { src = Wq + e;                sc = QSCALE; }
        else if (r < 2048) { src = Wk + (e - 1024*1024); }
        else               { src = Wv + (e - 2048*1024); }
        float4 v = *(const float4*)src;
        uint2 uh;
        uh.x = pkh(v.x * sc, v.y * sc);
        uh.y = pkh(v.z * sc, v.w * sc);
        *(uint2*)(wh + e) = uh;
    } else {
        int e = (i - WSA_QKV) * 4;
        #pragma unroll
        for (int j = 0; j < 4; j++) {
            int c = e + j;
            float b = (c < 1024) ? QSCALE * bq[c]
                    : (c < 2048) ? bk[c - 1024] : bv[c - 2048];
            bqkv[c] = b;
        }
    }
}

// ---------------- weight splits: W1, W2 (hi + lo fp16) ----------------
static constexpr int WSB_W1  = DFF * DIM / 4;
static constexpr int WSB_W2  = DIM * DFF / 4;
static constexpr int WSB_TOT = WSB_W1 + WSB_W2;

__global__ __launch_bounds__(256)
void wsplit_b(const float* __restrict__ W1, const float* __restrict__ W2,
              __half* __restrict__ w1h, __half* __restrict__ w1l,
              __half* __restrict__ w2h, __half* __restrict__ w2l)
{
    int i = blockIdx.x * 256 + threadIdx.x;
    if (i >= WSB_TOT) return;
    if (i < WSB_W1) {
        int e = i * 4;
        float4 v = *(const float4*)(W1 + e);
        uint2 uh, ul;
        splith2(v.x, v.y, uh.x, ul.x);
        splith2(v.z, v.w, uh.y, ul.y);
        *(uint2*)(w1h + e) = uh;
        *(uint2*)(w1l + e) = ul;
    } else {
        int e = (i - WSB_W1) * 4;
        float4 v = *(const float4*)(W2 + e);
        uint2 uh, ul;
        splith2(v.x, v.y, uh.x, ul.x);
        splith2(v.z, v.w, uh.y, ul.y);
        *(uint2*)(w2h + e) = uh;
        *(uint2*)(w2l + e) = ul;
    }
}

// ---------------- LayerNorm (optional residual; fp32 out + fp16 out) ----------------
__global__ __launch_bounds__(256)
void ln_kernel(const float* __restrict__ x, const float* __restrict__ res,
               const float* __restrict__ gamma, const float* __restrict__ beta,
               float* __restrict__ out, __half* __restrict__ oh)
{
    int row = blockIdx.x;
    int t = threadIdx.x;
    const float4* xr = (const float4*)(x + (size_t)row * DIM);
    float4 v = xr[t];
    if (res) {
        const float4* rr = (const float4*)(res + (size_t)row * DIM);
        float4 r = rr[t];
        v.x += r.x; v.y += r.y; v.z += r.z; v.w += r.w;
    }
    float s  = v.x + v.y + v.z + v.w;
    float s2 = v.x*v.x + v.y*v.y + v.z*v.z + v.w*v.w;
    #pragma unroll
    for (int o = 16; o > 0; o >>= 1) {
        s  += __shfl_down_sync(0xffffffffu, s,  o);
        s2 += __shfl_down_sync(0xffffffffu, s2, o);
    }
    __shared__ float ss[8], ss2[8];
    __shared__ float mean_s, rstd_s;
    if ((t & 31) == 0) { ss[t >> 5] = s; ss2[t >> 5] = s2; }
    __syncthreads();
    if (t == 0) {
        float a = 0.f, b = 0.f;
        #pragma unroll
        for (int i = 0; i < 8; i++) { a += ss[i]; b += ss2[i]; }
        float mean = a * (1.0f / DIM);
        float var  = b * (1.0f / DIM) - mean * mean;
        mean_s = mean;
        rstd_s = rsqrtf(var + 1e-5f);
    }
    __syncthreads();
    float mean = mean_s, rstd = rstd_s;
    float4 g = ((const float4*)gamma)[t];
    float4 bb = ((const float4*)beta)[t];
    float4 o4;
    o4.x = (v.x - mean) * rstd * g.x + bb.x;
    o4.y = (v.y - mean) * rstd * g.y + bb.y;
    o4.z = (v.z - mean) * rstd * g.z + bb.z;
    o4.w = (v.w - mean) * rstd * g.w + bb.w;
    size_t idx = (size_t)row * DIM + t * 4;
    if (out) *(float4*)(out + idx) = o4;
    uint2 uh;
    uh.x = pkh(o4.x, o4.y);
    uh.y = pkh(o4.z, o4.w);
    *(uint2*)(oh + idx) = uh;
}

// ---------------- unified fp16 GEMM: C = A @ (Wh[+Wl])^T ----------------
// CTA 128x128, 8 warps (32x64), K-chunk 64, 2 CTAs/SM.
// TERMS=1: 3 stages (A+Bh, 32KB each); TERMS=2: 2 stages (A+Bh+Bl, 48KB each).
// EPI: 0 = bias -> fp16 ; 1 = bias+silu -> fp16 ; 2 = bias+res -> fp32
template<int EPI, int TERMS, int NSTAGE>
__global__ void __launch_bounds__(256, 2)
gemm_h(const __half* __restrict__ A, const __half* __restrict__ Bh,
       const __half* __restrict__ Bl, const float* __restrict__ bias,
       const float* __restrict__ res, float* __restrict__ C,
       __half* __restrict__ Ch, int N, int K)
{
    constexpr uint32_t STAGE = (1 + TERMS) * 16384;
    extern __shared__ char sm[];
    const int tid = threadIdx.x;
    const int wid = tid >> 5, lane = tid & 31;
    const int bm = blockIdx.y * 128, bn = blockIdx.x * 128;
    const int wm = (wid & 3) * 32, wn = (wid >> 2) * 64;
    const uint32_t sb = smem_u32(sm);

    float acc[2][8][4];
    #pragma unroll
    for (int i = 0; i < 2; i++)
        #pragma unroll
        for (int j = 0; j < 8; j++)
            #pragma unroll
            for (int d = 0; d < 4; d++) acc[i][j][d] = 0.f;

    const int r_ld = tid >> 1;          // 0..127
    const int s_ld = (tid & 1) * 4;     // seg base 0 or 4

    auto issue = [&](int c) {
        uint32_t st = sb + (uint32_t)(c % NSTAGE) * STAGE;
        int k0 = c * 64;
        #pragma unroll
        for (int j = 0; j < 4; j++) {
            int s = s_ld + j;
            uint32_t o = off64(r_ld, s);
            cp16(st + o,        A  + (size_t)(bm + r_ld) * K + k0 + s * 8);
            cp16(st + 16384 + o, Bh + (size_t)(bn + r_ld) * K + k0 + s * 8);
            if (TERMS == 2)
                cp16(st + 32768 + o, Bl + (size_t)(bn + r_ld) * K + k0 + s * 8);
        }
        cp_commit();
    };

    const int NC = K / 64;
    issue(0);
    if (NSTAGE == 3) issue(1);

    for (int c = 0; c < NC; c++) {
        if (NSTAGE == 3) {
            if (c + 1 < NC) cp_wait<1>(); else cp_wait<0>();
        } else {
            cp_wait<0>();
        }
        __syncthreads();
        if (NSTAGE == 2) { if (c + 1 < NC) issue(c + 1); }
        uint32_t st = sb + (uint32_t)(c % NSTAGE) * STAGE;
        #pragma unroll
        for (int ks = 0; ks < 4; ks++) {
            uint32_t a[8];
            #pragma unroll
            for (int mt = 0; mt < 2; mt++) {
                int row = wm + mt * 16 + (lane & 7) + ((lane >> 3) & 1) * 8;
                int seg = ks * 2 + (lane >> 4);
                ldm_x4(a + mt * 4, st + off64(row, seg));
            }
            uint32_t bh[16], bl[16];
            #pragma unroll
            for (int ntp = 0; ntp < 4; ntp++) {
                int row = wn + ntp * 16 + (lane & 7) + ((lane >> 4) & 1) * 8;
                int seg = ks * 2 + ((lane >> 3) & 1);
                uint32_t ob = off64(row, seg);
                ldm_x4(bh + ntp * 4, st + 16384 + ob);
                if (TERMS == 2) ldm_x4(bl + ntp * 4, st + 32768 + ob);
            }
            #pragma unroll
            for (int ntp = 0; ntp < 4; ntp++)
                #pragma unroll
                for (int half = 0; half < 2; half++)
                    #pragma unroll
                    for (int mt = 0; mt < 2; mt++)
                        mma_f16(acc[mt][ntp*2+half], a + mt*4, bh + ntp*4 + half*2);
            if (TERMS == 2) {
                #pragma unroll
                for (int ntp = 0; ntp < 4; ntp++)
                    #pragma unroll
                    for (int half = 0; half < 2; half++)
                        #pragma unroll
                        for (int mt = 0; mt < 2; mt++)
                            mma_f16(acc[mt][ntp*2+half], a + mt*4, bl + ntp*4 + half*2);
            }
        }
        if (NSTAGE == 3) { if (c + 2 < NC) issue(c + 2); }  // writes (c+2)%3 != c%3
    }

    #pragma unroll
    for (int mt = 0; mt < 2; mt++) {
        int r0 = bm + wm + mt * 16 + (lane >> 2);
        #pragma unroll
        for (int nt = 0; nt < 8; nt++) {
            int col = bn + wn + nt * 8 + (lane & 3) * 2;
            float b0 = bias[col], b1 = bias[col + 1];
            float* a = acc[mt][nt];
            if (EPI == 0) {
                *(uint32_t*)(Ch + (size_t)r0 * N + col)       = pkh(a[0] + b0, a[1] + b1);
                *(uint32_t*)(Ch + (size_t)(r0 + 8) * N + col) = pkh(a[2] + b0, a[3] + b1);
            } else if (EPI == 1) {
                float v0 = a[0] + b0, v1 = a[1] + b1, v2 = a[2] + b0, v3 = a[3] + b1;
                v0 = v0 / (1.f + __expf(-v0));
                v1 = v1 / (1.f + __expf(-v1));
                v2 = v2 / (1.f + __expf(-v2));
                v3 = v3 / (1.f + __expf(-v3));
                *(uint32_t*)(Ch + (size_t)r0 * N + col)       = pkh(v0, v1);
                *(uint32_t*)(Ch + (size_t)(r0 + 8) * N + col) = pkh(v2, v3);
            } else {
                float2 p0, p1;
                float2 rr0 = *(const float2*)(res + (size_t)r0 * N + col);
                float2 rr1 = *(const float2*)(res + (size_t)(r0 + 8) * N + col);
                p0.x = a[0] + b0 + rr0.x; p0.y = a[1] + b1 + rr0.y;
                p1.x = a[2] + b0 + rr1.x; p1.y = a[3] + b1 + rr1.y;
                *(float2*)(C + (size_t)r0 * N + col) = p0;
                *(float2*)(C + (size_t)(r0 + 8) * N + col) = p1;
            }
        }
    }
}

static constexpr int G_SMEM1 = 3 * 2 * 16384;   // TERMS=1, 3 stages = 96KB
static constexpr int G_SMEM2 = 2 * 3 * 16384;   // TERMS=2, 2 stages = 96KB

// ---------------- Flash attention via mma.sync (fp16) ----------------
// grid: (SEQ/64, NH, B); 128 thr (4 warps, 16 q-rows each), 4 CTAs/SM.
// Scores in log2 units -> exp2f softmax; skip-rescale ballot.
// smem: Q 8K @0; KV 3 stages @8192 stride 16384 (lookahead-2, single sync): K, V(+8192)
static constexpr int A_SMEM = 8192 + 3 * 16384;   // 57344

__global__ void __launch_bounds__(128, 4)
attn_mma(const __half* __restrict__ qkvh, float* __restrict__ out)
{
    extern __shared__ char sm[];
    const int tid = threadIdx.x;
    const int wid = tid >> 5, lane = tid & 31;
    const int h = blockIdx.y, b = blockIdx.z;
    const int tok0 = b * SEQ + blockIdx.x * 64;
    const uint32_t sb = smem_u32(sm);

    // group 0: Q (64 rows x 128B)
    {
        int r = tid >> 1;
        size_t qrow = (size_t)(tok0 + r) * NQKV + h * HD;
        #pragma unroll
        for (int j = 0; j < 4; j++) {
            int s = (tid & 1) * 4 + j;
            cp16(sb + off64(r, s), qkvh + qrow + s * 8);
        }
        cp_commit();
    }
    auto issueKV = [&](int kb) {
        uint32_t st = sb + 8192 + (uint32_t)(kb % 3) * 16384;
        int r = tid >> 1;
        size_t kvrow = (size_t)(b * SEQ + kb * 64 + r) * NQKV + h * HD;
        #pragma unroll
        for (int j = 0; j < 4; j++) {
            int s = (tid & 1) * 4 + j;
            uint32_t o = off64(r, s);
            cp16(st + o, qkvh + kvrow + 1024 + s * 8);          // K
            cp16(st + 8192 + o, qkvh + kvrow + 2048 + s * 8);   // V
        }
        cp_commit();
    };
    issueKV(0);
    issueKV(1);

    cp_wait<1>(); // Q + KV0 done
    __syncthreads();

    uint32_t qf[4][4];
    {
        int row = wid * 16 + (lane & 7) + ((lane >> 3) & 1) * 8;
        #pragma unroll
        for (int ks = 0; ks < 4; ks++) {
            int seg = ks * 2 + (lane >> 4);
            ldm_x4(qf[ks], sb + off64(row, seg));
        }
    }

    float o_acc[8][4];
    #pragma unroll
    for (int i = 0; i < 8; i++)
        #pragma unroll
        for (int d = 0; d < 4; d++) o_acc[i][d] = 0.f;
    float runA = -INFINITY, runB = -INFINITY, lA = 0.f, lB = 0.f;

    const int NKB = SEQ / 64;
    for (int kb = 0; kb < NKB; kb++) {
        if (kb > 0) {
            if (kb + 1 < NKB) cp_wait<1>(); else cp_wait<0>();
            __syncthreads();
        }
        uint32_t st = sb + 8192 + (uint32_t)(kb % 3) * 16384;
        float s[8][4];
        #pragma unroll
        for (int i = 0; i < 8; i++)
            #pragma unroll
            for (int d = 0; d < 4; d++) s[i][d] = 0.f;
        #pragma unroll
        for (int ks = 0; ks < 4; ks++) {
            uint32_t bh[16];
            #pragma unroll
            for (int ntp = 0; ntp < 4; ntp++) {
                int row = ntp * 16 + (lane & 7) + ((lane >> 4) & 1) * 8;
                int seg = ks * 2 + ((lane >> 3) & 1);
                ldm_x4(bh + ntp * 4, st + off64(row, seg));
            }
            #pragma unroll
            for (int ntp = 0; ntp < 4; ntp++)
                #pragma unroll
                for (int half = 0; half < 2; half++)
                    mma_f16(s[ntp * 2 + half], qf[ks], bh + ntp * 4 + half * 2);
        }
        float mA = -INFINITY, mB = -INFINITY;
        #pragma unroll
        for (int nt = 0; nt < 8; nt++) {
            mA = fmaxf(mA, fmaxf(s[nt][0], s[nt][1]));
            mB = fmaxf(mB, fmaxf(s[nt][2], s[nt][3]));
        }
        mA = fmaxf(mA, __shfl_xor_sync(0xffffffffu, mA, 1));
        mA = fmaxf(mA, __shfl_xor_sync(0xffffffffu, mA, 2));
        mB = fmaxf(mB, __shfl_xor_sync(0xffffffffu, mB, 1));
        mB = fmaxf(mB, __shfl_xor_sync(0xffffffffu, mB, 2));
        unsigned chg = __ballot_sync(0xffffffffu, (mA > runA) || (mB > runB));
        if (chg) {
            float nA = fmaxf(runA, mA), nB = fmaxf(runB, mB);
            float cA = exp2f(runA - nA), cB = exp2f(runB - nB);
            runA = nA; runB = nB;
            lA *= cA; lB *= cB;
            #pragma unroll
            for (int nt = 0; nt < 8; nt++) {
                o_acc[nt][0] *= cA; o_acc[nt][1] *= cA;
                o_acc[nt][2] *= cB; o_acc[nt][3] *= cB;
            }
        }
        float sumA = 0.f, sumB = 0.f;
        #pragma unroll
        for (int nt = 0; nt < 8; nt++) {
            s[nt][0] = exp2f(s[nt][0] - runA); sumA += s[nt][0];
            s[nt][1] = exp2f(s[nt][1] - runA); sumA += s[nt][1];
            s[nt][2] = exp2f(s[nt][2] - runB); sumB += s[nt][2];
            s[nt][3] = exp2f(s[nt][3] - runB); sumB += s[nt][3];
        }
        lA += sumA; lB += sumB;
        uint32_t pf[4][4];
        #pragma unroll
        for (int j = 0; j < 4; j++) {
            pf[j][0] = pkh(s[2*j][0],   s[2*j][1]);
            pf[j][1] = pkh(s[2*j][2],   s[2*j][3]);
            pf[j][2] = pkh(s[2*j+1][0], s[2*j+1][1]);
            pf[j][3] = pkh(s[2*j+1][2], s[2*j+1][3]);
        }
        #pragma unroll
        for (int ks = 0; ks < 4; ks++) {
            uint32_t vb[16];
            #pragma unroll
            for (int ntp = 0; ntp < 4; ntp++) {
                int row = ks * 16 + (lane & 7) + ((lane >> 3) & 1) * 8;
                int seg = ntp * 2 + (lane >> 4);
                ldm_x4t(vb + ntp * 4, st + 8192 + off64(row, seg));
            }
            #pragma unroll
            for (int ntp = 0; ntp < 4; ntp++) {
                mma_f16(o_acc[ntp * 2 + 0], pf[ks], vb + ntp * 4 + 0);
                mma_f16(o_acc[ntp * 2 + 1], pf[ks], vb + ntp * 4 + 2);
            }
        }
        if (kb + 2 < NKB) issueKV(kb + 2);   // writes (kb+2)%3 != kb%3
    }

    lA += __shfl_xor_sync(0xffffffffu, lA, 1);
    lA += __shfl_xor_sync(0xffffffffu, lA, 2);
    lB += __shfl_xor_sync(0xffffffffu, lB, 1);
    lB += __shfl_xor_sync(0xffffffffu, lB, 2);
    float iA = 1.f / lA, iB = 1.f / lB;
    int rowA = tok0 + wid * 16 + (lane >> 2);
    #pragma unroll
    for (int nt = 0; nt < 8; nt++) {
        int col = h * HD + nt * 8 + (lane & 3) * 2;
        float2 p0 = {o_acc[nt][0] * iA, o_acc[nt][1] * iA};
        float2 p1 = {o_acc[nt][2] * iB, o_acc[nt][3] * iB};
        *(float2*)(out + (size_t)rowA * DIM + col) = p0;
        *(float2*)(out + (size_t)(rowA + 8) * DIM + col) = p1;
    }
}

// ---------------- launch ----------------
extern "C" void kernel_launch(void* const* d_in, const int* in_sizes, int n_in,
                              void* d_out, int out_size)
{
    (void)in_sizes; (void)n_in; (void)out_size;
    const float* x   = (const float*)d_in[0];
    const float* Wq  = (const float*)d_in[1];
    const float* bq  = (const float*)d_in[2];
    const float* Wk  = (const float*)d_in[3];
    const float* bk  = (const float*)d_in[4];
    const float* Wv  = (const float*)d_in[5];
    const float* bv  = (const float*)d_in[6];
    const float* g1  = (const float*)d_in[7];
    const float* b1  = (const float*)d_in[8];
    const float* g2  = (const float*)d_in[9];
    const float* b2  = (const float*)d_in[10];
    const float* W1  = (const float*)d_in[11];
    const float* bf1 = (const float*)d_in[12];
    const float* W2  = (const float*)d_in[13];
    const float* bf2 = (const float*)d_in[14];

    float *xn, *attn, *bqkv;
    cudaGetSymbolAddress((void**)&xn,   g_xn);
    cudaGetSymbolAddress((void**)&attn, g_attn);
    cudaGetSymbolAddress((void**)&bqkv, g_bqkv);

    __half *xnh, *qkvh, *hh, *f1h;
    __half *wqh, *w1h, *w1l, *w2h, *w2l;
    cudaGetSymbolAddress((void**)&xnh,  g_xn_h);
    cudaGetSymbolAddress((void**)&qkvh, g_qkv_h);
    cudaGetSymbolAddress((void**)&hh,   g_h_h);
    cudaGetSymbolAddress((void**)&f1h,  g_ff1_h);
    cudaGetSymbolAddress((void**)&wqh,  g_wqkv_h);
    cudaGetSymbolAddress((void**)&w1h,  g_w1_h);   cudaGetSymbolAddress((void**)&w1l, g_w1_l);
    cudaGetSymbolAddress((void**)&w2h,  g_w2_h);   cudaGetSymbolAddress((void**)&w2l, g_w2_l);

    cudaFuncSetAttribute((const void*)gemm_h<0,1,3>, cudaFuncAttributeMaxDynamicSharedMemorySize, G_SMEM1);
    cudaFuncSetAttribute((const void*)gemm_h<1,2,2>, cudaFuncAttributeMaxDynamicSharedMemorySize, G_SMEM2);
    cudaFuncSetAttribute((const void*)gemm_h<2,2,2>, cudaFuncAttributeMaxDynamicSharedMemorySize, G_SMEM2);
    cudaFuncSetAttribute((const void*)attn_mma,      cudaFuncAttributeMaxDynamicSharedMemorySize, A_SMEM);

    // launch 0: QKV weight -> fp16 hi (+ bias concat, Q pre-scaled)
    wsplit_a<<<(WSA_TOT + 255)/256, 256>>>(Wq, Wk, Wv, bq, bk, bv, wqh, bqkv);

    // launch 1: W1/W2 split hi+lo
    wsplit_b<<<(WSB_TOT + 255)/256, 256>>>(W1, W2, w1h, w1l, w2h, w2l);

    // launch 2: xn = LN(x) : fp32 + fp16
    ln_kernel<<<NTOK, 256>>>(x, nullptr, g1, b1, xn, xnh);

    // launch 3 (profiled): fused QKV projection, 1-term -> fp16 [NTOK, 3072]
    dim3 gQKV(NQKV / 128, NTOK / 128);
    gemm_h<0,1,3><<<gQKV, 256, G_SMEM1>>>(xnh, wqh, nullptr, bqkv, nullptr, nullptr, qkvh, NQKV, DIM);

    // launch 4: attention (fp16 tensor-core flash, 4 CTAs/SM)
    attn_mma<<<dim3(SEQ / 64, NH, 2), 128, A_SMEM>>>(qkvh, attn);

    // launch 5: h = LN(attn + xn) -> fp16
    ln_kernel<<<NTOK, 256>>>(attn, xn, g2, b2, nullptr, hh);

    // launch 6: ff1 = silu(h @ W1^T + bf1) -> fp16 (2-term)
    dim3 gF1(DFF / 128, NTOK / 128);
    gemm_h<1,2,2><<<gF1, 256, G_SMEM2>>>(hh, w1h, w1l, bf1, nullptr, nullptr, f1h, DFF, DIM);

    // launch 7: out = ff1 @ W2^T + bf2 + xn (2-term)
    dim3 gF2(DIM / 128, NTOK / 128);
    gemm_h<2,2,2><<<gF2, 256, G_SMEM2>>>(f1h, w2h, w2l, bf2, xn, (float*)d_out, nullptr, DIM, DFF);
}

// round 16
// speedup vs baseline: 13.1325x; 1.4061x over previous
#include <cuda_runtime.h>
#include <cuda_fp16.h>
#include <math.h>
#include <stdint.h>

#define NTOK 4096          // B*S
#define SEQ  2048
#define DIM  1024
#define NH   16
#define HD   64
#define DFF  4096
#define NQKV 3072

#define QSCALE (0.125f * 1.44269504088896f)   // 1/sqrt(64) * log2(e)

// ---------------- scratch (device globals; no allocs allowed) ----------------
__device__ float g_xn[NTOK * DIM];
__device__ float g_attn[NTOK * DIM];
__device__ float g_bqkv[NQKV];

__device__ __half g_xn_h[NTOK * DIM];
__device__ __half g_qkv_h[NTOK * NQKV];
__device__ __half g_h_h[NTOK * DIM];
__device__ __half g_ff1_h[NTOK * DFF];
__device__ __half g_wqkv_h[NQKV * DIM];
__device__ __half g_w1_h[DFF * DIM];
__device__ __half g_w2_h[DIM * DFF];

// ---------------- PTX helpers (family-portable sm_80-era ISA) ----------------
__device__ __forceinline__ uint32_t smem_u32(const void* p) {
    uint32_t a;
    asm("{ .reg .u64 t; cvta.to.shared.u64 t, %1; cvt.u32.u64 %0, t; }" : "=r"(a) : "l"(p));
    return a;
}
__device__ __forceinline__ void cp16(uint32_t dst, const void* src) {
    asm volatile("cp.async.cg.shared.global [%0], [%1], 16;" :: "r"(dst), "l"(src) : "memory");
}
__device__ __forceinline__ void cp_commit() {
    asm volatile("cp.async.commit_group;" ::: "memory");
}
template<int N> __device__ __forceinline__ void cp_wait() {
    asm volatile("cp.async.wait_group %0;" :: "n"(N) : "memory");
}
__device__ __forceinline__ void ldm_x4(uint32_t* r, uint32_t addr) {
    asm volatile("ldmatrix.sync.aligned.m8n8.x4.shared.b16 {%0,%1,%2,%3}, [%4];"
        : "=r"(r[0]), "=r"(r[1]), "=r"(r[2]), "=r"(r[3]) : "r"(addr));
}
__device__ __forceinline__ void ldm_x4t(uint32_t* r, uint32_t addr) {
    asm volatile("ldmatrix.sync.aligned.m8n8.x4.trans.shared.b16 {%0,%1,%2,%3}, [%4];"
        : "=r"(r[0]), "=r"(r[1]), "=r"(r[2]), "=r"(r[3]) : "r"(addr));
}
__device__ __forceinline__ void mma_f16(float* d, const uint32_t* a, const uint32_t* b) {
    asm volatile(
        "mma.sync.aligned.m16n8k16.row.col.f32.f16.f16.f32 "
        "{%0,%1,%2,%3}, {%4,%5,%6,%7}, {%8,%9}, {%0,%1,%2,%3};"
        : "+f"(d[0]), "+f"(d[1]), "+f"(d[2]), "+f"(d[3])
        : "r"(a[0]), "r"(a[1]), "r"(a[2]), "r"(a[3]), "r"(b[0]), "r"(b[1]));
}
__device__ __forceinline__ uint32_t pkh(float lo, float hi) {
    __half2 t = __floats2half2_rn(lo, hi);
    return *(uint32_t*)&t;
}
// 64-col fp16 tile (128B rows, 8x16B segs)
__device__ __forceinline__ uint32_t off64(int r, int s) {
    return (uint32_t)(r * 128 + ((s ^ (r & 7)) << 4));
}

// ---------------- weight prep: QKV hi (+ bias concat, Q pre-scaled) ----------------
static constexpr int WSA_QKV = NQKV * DIM / 4;
static constexpr int WSA_B   = NQKV / 4;
static constexpr int WSA_TOT = WSA_QKV + WSA_B;

__global__ __launch_bounds__(256)
void wsplit_a(const float* __restrict__ Wq, const float* __restrict__ Wk,
              const float* __restrict__ Wv, const float* __restrict__ bq,
              const float* __restrict__ bk, const float* __restrict__ bv,
              __half* __restrict__ wh, float* __restrict__ bqkv)
{
    int i = blockIdx.x * 256 + threadIdx.x;
    if (i >= WSA_TOT) return;
    if (i < WSA_QKV) {
        int e = i * 4;
        int r = e >> 10;
        float sc = 1.0f;
        const float* src;
        if (r < 1024)      { src = Wq + e;                sc = QSCALE; }
        else if (r < 2048) { src = Wk + (e - 1024*1024); }
        else               { src = Wv + (e - 2048*1024); }
        float4 v = *(const float4*)src;
        uint2 uh;
        uh.x = pkh(v.x * sc, v.y * sc);
        uh.y = pkh(v.z * sc, v.w * sc);
        *(uint2*)(wh + e) = uh;
    } else {
        int e = (i - WSA_QKV) * 4;
        #pragma unroll
        for (int j = 0; j < 4; j++) {
            int c = e + j;
            float b = (c < 1024) ? QSCALE * bq[c]
                    : (c < 2048) ? bk[c - 1024] : bv[c - 2048];
            bqkv[c] = b;
        }
    }
}

// ---------------- weight prep: W1, W2 -> fp16 ----------------
static constexpr int WSB_W1  = DFF * DIM / 4;
static constexpr int WSB_W2  = DIM * DFF / 4;
static constexpr int WSB_TOT = WSB_W1 + WSB_W2;

__global__ __launch_bounds__(256)
void wsplit_b(const float* __restrict__ W1, const float* __restrict__ W2,
              __half* __restrict__ w1h, __half* __restrict__ w2h)
{
    int i = blockIdx.x * 256 + threadIdx.x;
    if (i >= WSB_TOT) return;
    if (i < WSB_W1) {
        int e = i * 4;
        float4 v = *(const float4*)(W1 + e);
        uint2 uh;
        uh.x = pkh(v.x, v.y);
        uh.y = pkh(v.z, v.w);
        *(uint2*)(w1h + e) = uh;
    } else {
        int e = (i - WSB_W1) * 4;
        float4 v = *(const float4*)(W2 + e);
        uint2 uh;
        uh.x = pkh(v.x, v.y);
        uh.y = pkh(v.z, v.w);
        *(uint2*)(w2h + e) = uh;
    }
}

// ---------------- LayerNorm (optional residual; fp32 out + fp16 out) ----------------
__global__ __launch_bounds__(256)
void ln_kernel(const float* __restrict__ x, const float* __restrict__ res,
               const float* __restrict__ gamma, const float* __restrict__ beta,
               float* __restrict__ out, __half* __restrict__ oh)
{
    int row = blockIdx.x;
    int t = threadIdx.x;
    const float4* xr = (const float4*)(x + (size_t)row * DIM);
    float4 v = xr[t];
    if (res) {
        const float4* rr = (const float4*)(res + (size_t)row * DIM);
        float4 r = rr[t];
        v.x += r.x; v.y += r.y; v.z += r.z; v.w += r.w;
    }
    float s  = v.x + v.y + v.z + v.w;
    float s2 = v.x*v.x + v.y*v.y + v.z*v.z + v.w*v.w;
    #pragma unroll
    for (int o = 16; o > 0; o >>= 1) {
        s  += __shfl_down_sync(0xffffffffu, s,  o);
        s2 += __shfl_down_sync(0xffffffffu, s2, o);
    }
    __shared__ float ss[8], ss2[8];
    __shared__ float mean_s, rstd_s;
    if ((t & 31) == 0) { ss[t >> 5] = s; ss2[t >> 5] = s2; }
    __syncthreads();
    if (t == 0) {
        float a = 0.f, b = 0.f;
        #pragma unroll
        for (int i = 0; i < 8; i++) { a += ss[i]; b += ss2[i]; }
        float mean = a * (1.0f / DIM);
        float var  = b * (1.0f / DIM) - mean * mean;
        mean_s = mean;
        rstd_s = rsqrtf(var + 1e-5f);
    }
    __syncthreads();
    float mean = mean_s, rstd = rstd_s;
    float4 g = ((const float4*)gamma)[t];
    float4 bb = ((const float4*)beta)[t];
    float4 o4;
    o4.x = (v.x - mean) * rstd * g.x + bb.x;
    o4.y = (v.y - mean) * rstd * g.y + bb.y;
    o4.z = (v.z - mean) * rstd * g.z + bb.z;
    o4.w = (v.w - mean) * rstd * g.w + bb.w;
    size_t idx = (size_t)row * DIM + t * 4;
    if (out) *(float4*)(out + idx) = o4;
    uint2 uh;
    uh.x = pkh(o4.x, o4.y);
    uh.y = pkh(o4.z, o4.w);
    *(uint2*)(oh + idx) = uh;
}

// ---------------- 1-term fp16 GEMM: C = A @ Wh^T ----------------
// CTA 128x128, 8 warps (32x64), K-chunk 64, 3 stages @32KB (lookahead-2,
// single sync/chunk), 2 CTAs/SM.
// EPI: 0 = bias -> fp16 ; 1 = bias+silu -> fp16 ; 2 = bias+res -> fp32
static constexpr uint32_t G_STAGE = 32768;    // A(16K) Bh(16K)
static constexpr int G_SMEM = 3 * G_STAGE;    // 96KB

template<int EPI>
__global__ void __launch_bounds__(256, 2)
gemm_h(const __half* __restrict__ A, const __half* __restrict__ Bh,
       const float* __restrict__ bias, const float* __restrict__ res,
       float* __restrict__ C, __half* __restrict__ Ch, int N, int K)
{
    extern __shared__ char sm[];
    const int tid = threadIdx.x;
    const int wid = tid >> 5, lane = tid & 31;
    const int bm = blockIdx.y * 128, bn = blockIdx.x * 128;
    const int wm = (wid & 3) * 32, wn = (wid >> 2) * 64;
    const uint32_t sb = smem_u32(sm);

    float acc[2][8][4];
    #pragma unroll
    for (int i = 0; i < 2; i++)
        #pragma unroll
        for (int j = 0; j < 8; j++)
            #pragma unroll
            for (int d = 0; d < 4; d++) acc[i][j][d] = 0.f;

    const int r_ld = tid >> 1;          // 0..127
    const int s_ld = (tid & 1) * 4;     // seg base 0 or 4

    auto issue = [&](int c) {
        uint32_t st = sb + (uint32_t)(c % 3) * G_STAGE;
        int k0 = c * 64;
        #pragma unroll
        for (int j = 0; j < 4; j++) {
            int s = s_ld + j;
            uint32_t o = off64(r_ld, s);
            cp16(st + o,         A  + (size_t)(bm + r_ld) * K + k0 + s * 8);
            cp16(st + 16384 + o, Bh + (size_t)(bn + r_ld) * K + k0 + s * 8);
        }
        cp_commit();
    };

    const int NC = K / 64;
    issue(0);
    issue(1);

    for (int c = 0; c < NC; c++) {
        if (c + 1 < NC) cp_wait<1>(); else cp_wait<0>();
        __syncthreads();
        uint32_t st = sb + (uint32_t)(c % 3) * G_STAGE;
        #pragma unroll
        for (int ks = 0; ks < 4; ks++) {
            uint32_t a[8];
            #pragma unroll
            for (int mt = 0; mt < 2; mt++) {
                int row = wm + mt * 16 + (lane & 7) + ((lane >> 3) & 1) * 8;
                int seg = ks * 2 + (lane >> 4);
                ldm_x4(a + mt * 4, st + off64(row, seg));
            }
            uint32_t bh[16];
            #pragma unroll
            for (int ntp = 0; ntp < 4; ntp++) {
                int row = wn + ntp * 16 + (lane & 7) + ((lane >> 4) & 1) * 8;
                int seg = ks * 2 + ((lane >> 3) & 1);
                ldm_x4(bh + ntp * 4, st + 16384 + off64(row, seg));
            }
            #pragma unroll
            for (int ntp = 0; ntp < 4; ntp++)
                #pragma unroll
                for (int half = 0; half < 2; half++)
                    #pragma unroll
                    for (int mt = 0; mt < 2; mt++)
                        mma_f16(acc[mt][ntp*2+half], a + mt*4, bh + ntp*4 + half*2);
        }
        if (c + 2 < NC) issue(c + 2);   // writes (c+2)%3 != c%3 : safe without sync
    }

    #pragma unroll
    for (int mt = 0; mt < 2; mt++) {
        int r0 = bm + wm + mt * 16 + (lane >> 2);
        #pragma unroll
        for (int nt = 0; nt < 8; nt++) {
            int col = bn + wn + nt * 8 + (lane & 3) * 2;
            float b0 = bias[col], b1 = bias[col + 1];
            float* a = acc[mt][nt];
            if (EPI == 0) {
                *(uint32_t*)(Ch + (size_t)r0 * N + col)       = pkh(a[0] + b0, a[1] + b1);
                *(uint32_t*)(Ch + (size_t)(r0 + 8) * N + col) = pkh(a[2] + b0, a[3] + b1);
            } else if (EPI == 1) {
                float v0 = a[0] + b0, v1 = a[1] + b1, v2 = a[2] + b0, v3 = a[3] + b1;
                v0 = v0 / (1.f + __expf(-v0));
                v1 = v1 / (1.f + __expf(-v1));
                v2 = v2 / (1.f + __expf(-v2));
                v3 = v3 / (1.f + __expf(-v3));
                *(uint32_t*)(Ch + (size_t)r0 * N + col)       = pkh(v0, v1);
                *(uint32_t*)(Ch + (size_t)(r0 + 8) * N + col) = pkh(v2, v3);
            } else {
                float2 p0, p1;
                float2 rr0 = *(const float2*)(res + (size_t)r0 * N + col);
                float2 rr1 = *(const float2*)(res + (size_t)(r0 + 8) * N + col);
                p0.x = a[0] + b0 + rr0.x; p0.y = a[1] + b1 + rr0.y;
                p1.x = a[2] + b0 + rr1.x; p1.y = a[3] + b1 + rr1.y;
                *(float2*)(C + (size_t)r0 * N + col) = p0;
                *(float2*)(C + (size_t)(r0 + 8) * N + col) = p1;
            }
        }
    }
}

// ---------------- Flash attention via mma.sync (fp16) ----------------
// grid: (SEQ/64, NH, B); 128 thr (4 warps, 16 q-rows each), 4 CTAs/SM.
// Scores in log2 units -> exp2f softmax; skip-rescale ballot.
// smem: Q 8K @0; KV 3 stages @8192 stride 16384 (lookahead-2, single sync): K, V(+8192)
static constexpr int A_SMEM = 8192 + 3 * 16384;   // 57344

__global__ void __launch_bounds__(128, 4)
attn_mma(const __half* __restrict__ qkvh, float* __restrict__ out)
{
    extern __shared__ char sm[];
    const int tid = threadIdx.x;
    const int wid = tid >> 5, lane = tid & 31;
    const int h = blockIdx.y, b = blockIdx.z;
    const int tok0 = b * SEQ + blockIdx.x * 64;
    const uint32_t sb = smem_u32(sm);

    // group 0: Q (64 rows x 128B)
    {
        int r = tid >> 1;
        size_t qrow = (size_t)(tok0 + r) * NQKV + h * HD;
        #pragma unroll
        for (int j = 0; j < 4; j++) {
            int s = (tid & 1) * 4 + j;
            cp16(sb + off64(r, s), qkvh + qrow + s * 8);
        }
        cp_commit();
    }
    auto issueKV = [&](int kb) {
        uint32_t st = sb + 8192 + (uint32_t)(kb % 3) * 16384;
        int r = tid >> 1;
        size_t kvrow = (size_t)(b * SEQ + kb * 64 + r) * NQKV + h * HD;
        #pragma unroll
        for (int j = 0; j < 4; j++) {
            int s = (tid & 1) * 4 + j;
            uint32_t o = off64(r, s);
            cp16(st + o, qkvh + kvrow + 1024 + s * 8);          // K
            cp16(st + 8192 + o, qkvh + kvrow + 2048 + s * 8);   // V
        }
        cp_commit();
    };
    issueKV(0);
    issueKV(1);

    cp_wait<1>(); // Q + KV0 done
    __syncthreads();

    uint32_t qf[4][4];
    {
        int row = wid * 16 + (lane & 7) + ((lane >> 3) & 1) * 8;
        #pragma unroll
        for (int ks = 0; ks < 4; ks++) {
            int seg = ks * 2 + (lane >> 4);
            ldm_x4(qf[ks], sb + off64(row, seg));
        }
    }

    float o_acc[8][4];
    #pragma unroll
    for (int i = 0; i < 8; i++)
        #pragma unroll
        for (int d = 0; d < 4; d++) o_acc[i][d] = 0.f;
    float runA = -INFINITY, runB = -INFINITY, lA = 0.f, lB = 0.f;

    const int NKB = SEQ / 64;
    for (int kb = 0; kb < NKB; kb++) {
        if (kb > 0) {
            if (kb + 1 < NKB) cp_wait<1>(); else cp_wait<0>();
            __syncthreads();
        }
        uint32_t st = sb + 8192 + (uint32_t)(kb % 3) * 16384;
        float s[8][4];
        #pragma unroll
        for (int i = 0; i < 8; i++)
            #pragma unroll
            for (int d = 0; d < 4; d++) s[i][d] = 0.f;
        #pragma unroll
        for (int ks = 0; ks < 4; ks++) {
            uint32_t bh[16];
            #pragma unroll
            for (int ntp = 0; ntp < 4; ntp++) {
                int row = ntp * 16 + (lane & 7) + ((lane >> 4) & 1) * 8;
                int seg = ks * 2 + ((lane >> 3) & 1);
                ldm_x4(bh + ntp * 4, st + off64(row, seg));
            }
            #pragma unroll
            for (int ntp = 0; ntp < 4; ntp++)
                #pragma unroll
                for (int half = 0; half < 2; half++)
                    mma_f16(s[ntp * 2 + half], qf[ks], bh + ntp * 4 + half * 2);
        }
        float mA = -INFINITY, mB = -INFINITY;
        #pragma unroll
        for (int nt = 0; nt < 8; nt++) {
            mA = fmaxf(mA, fmaxf(s[nt][0], s[nt][1]));
            mB = fmaxf(mB, fmaxf(s[nt][2], s[nt][3]));
        }
        mA = fmaxf(mA, __shfl_xor_sync(0xffffffffu, mA, 1));
        mA = fmaxf(mA, __shfl_xor_sync(0xffffffffu, mA, 2));
        mB = fmaxf(mB, __shfl_xor_sync(0xffffffffu, mB, 1));
        mB = fmaxf(mB, __shfl_xor_sync(0xffffffffu, mB, 2));
        unsigned chg = __ballot_sync(0xffffffffu, (mA > runA) || (mB > runB));
        if (chg) {
            float nA = fmaxf(runA, mA), nB = fmaxf(runB, mB);
            float cA = exp2f(runA - nA), cB = exp2f(runB - nB);
            runA = nA; runB = nB;
            lA *= cA; lB *= cB;
            #pragma unroll
            for (int nt = 0; nt < 8; nt++) {
                o_acc[nt][0] *= cA; o_acc[nt][1] *= cA;
                o_acc[nt][2] *= cB; o_acc[nt][3] *= cB;
            }
        }
        float sumA = 0.f, sumB = 0.f;
        #pragma unroll
        for (int nt = 0; nt < 8; nt++) {
            s[nt][0] = exp2f(s[nt][0] - runA); sumA += s[nt][0];
            s[nt][1] = exp2f(s[nt][1] - runA); sumA += s[nt][1];
            s[nt][2] = exp2f(s[nt][2] - runB); sumB += s[nt][2];
            s[nt][3] = exp2f(s[nt][3] - runB); sumB += s[nt][3];
        }
        lA += sumA; lB += sumB;
        uint32_t pf[4][4];
        #pragma unroll
        for (int j = 0; j < 4; j++) {
            pf[j][0] = pkh(s[2*j][0],   s[2*j][1]);
            pf[j][1] = pkh(s[2*j][2],   s[2*j][3]);
            pf[j][2] = pkh(s[2*j+1][0], s[2*j+1][1]);
            pf[j][3] = pkh(s[2*j+1][2], s[2*j+1][3]);
        }
        #pragma unroll
        for (int ks = 0; ks < 4; ks++) {
            uint32_t vb[16];
            #pragma unroll
            for (int ntp = 0; ntp < 4; ntp++) {
                int row = ks * 16 + (lane & 7) + ((lane >> 3) & 1) * 8;
                int seg = ntp * 2 + (lane >> 4);
                ldm_x4t(vb + ntp * 4, st + 8192 + off64(row, seg));
            }
            #pragma unroll
            for (int ntp = 0; ntp < 4; ntp++) {
                mma_f16(o_acc[ntp * 2 + 0], pf[ks], vb + ntp * 4 + 0);
                mma_f16(o_acc[ntp * 2 + 1], pf[ks], vb + ntp * 4 + 2);
            }
        }
        if (kb + 2 < NKB) issueKV(kb + 2);   // writes (kb+2)%3 != kb%3
    }

    lA += __shfl_xor_sync(0xffffffffu, lA, 1);
    lA += __shfl_xor_sync(0xffffffffu, lA, 2);
    lB += __shfl_xor_sync(0xffffffffu, lB, 1);
    lB += __shfl_xor_sync(0xffffffffu, lB, 2);
    float iA = 1.f / lA, iB = 1.f / lB;
    int rowA = tok0 + wid * 16 + (lane >> 2);
    #pragma unroll
    for (int nt = 0; nt < 8; nt++) {
        int col = h * HD + nt * 8 + (lane & 3) * 2;
        float2 p0 = {o_acc[nt][0] * iA, o_acc[nt][1] * iA};
        float2 p1 = {o_acc[nt][2] * iB, o_acc[nt][3] * iB};
        *(float2*)(out + (size_t)rowA * DIM + col) = p0;
        *(float2*)(out + (size_t)(rowA + 8) * DIM + col) = p1;
    }
}

// ---------------- launch ----------------
extern "C" void kernel_launch(void* const* d_in, const int* in_sizes, int n_in,
                              void* d_out, int out_size)
{
    (void)in_sizes; (void)n_in; (void)out_size;
    const float* x   = (const float*)d_in[0];
    const float* Wq  = (const float*)d_in[1];
    const float* bq  = (const float*)d_in[2];
    const float* Wk  = (const float*)d_in[3];
    const float* bk  = (const float*)d_in[4];
    const float* Wv  = (const float*)d_in[5];
    const float* bv  = (const float*)d_in[6];
    const float* g1  = (const float*)d_in[7];
    const float* b1  = (const float*)d_in[8];
    const float* g2  = (const float*)d_in[9];
    const float* b2  = (const float*)d_in[10];
    const float* W1  = (const float*)d_in[11];
    const float* bf1 = (const float*)d_in[12];
    const float* W2  = (const float*)d_in[13];
    const float* bf2 = (const float*)d_in[14];

    float *xn, *attn, *bqkv;
    cudaGetSymbolAddress((void**)&xn,   g_xn);
    cudaGetSymbolAddress((void**)&attn, g_attn);
    cudaGetSymbolAddress((void**)&bqkv, g_bqkv);

    __half *xnh, *qkvh, *hh, *f1h;
    __half *wqh, *w1h, *w2h;
    cudaGetSymbolAddress((void**)&xnh,  g_xn_h);
    cudaGetSymbolAddress((void**)&qkvh, g_qkv_h);
    cudaGetSymbolAddress((void**)&hh,   g_h_h);
    cudaGetSymbolAddress((void**)&f1h,  g_ff1_h);
    cudaGetSymbolAddress((void**)&wqh,  g_wqkv_h);
    cudaGetSymbolAddress((void**)&w1h,  g_w1_h);
    cudaGetSymbolAddress((void**)&w2h,  g_w2_h);

    cudaFuncSetAttribute((const void*)gemm_h<0>, cudaFuncAttributeMaxDynamicSharedMemorySize, G_SMEM);
    cudaFuncSetAttribute((const void*)gemm_h<1>, cudaFuncAttributeMaxDynamicSharedMemorySize, G_SMEM);
    cudaFuncSetAttribute((const void*)gemm_h<2>, cudaFuncAttributeMaxDynamicSharedMemorySize, G_SMEM);
    cudaFuncSetAttribute((const void*)attn_mma,  cudaFuncAttributeMaxDynamicSharedMemorySize, A_SMEM);

    // launch 0: QKV weight -> fp16 (+ bias concat, Q pre-scaled)
    wsplit_a<<<(WSA_TOT + 255)/256, 256>>>(Wq, Wk, Wv, bq, bk, bv, wqh, bqkv);

    // launch 1: W1/W2 -> fp16
    wsplit_b<<<(WSB_TOT + 255)/256, 256>>>(W1, W2, w1h, w2h);

    // launch 2: xn = LN(x) : fp32 + fp16
    ln_kernel<<<NTOK, 256>>>(x, nullptr, g1, b1, xn, xnh);

    // launch 3 (profiled): fused QKV projection -> fp16 [NTOK, 3072]
    dim3 gQKV(NQKV / 128, NTOK / 128);
    gemm_h<0><<<gQKV, 256, G_SMEM>>>(xnh, wqh, bqkv, nullptr, nullptr, qkvh, NQKV, DIM);

    // launch 4: attention (fp16 tensor-core flash, 4 CTAs/SM)
    attn_mma<<<dim3(SEQ / 64, NH, 2), 128, A_SMEM>>>(qkvh, attn);

    // launch 5: h = LN(attn + xn) -> fp16
    ln_kernel<<<NTOK, 256>>>(attn, xn, g2, b2, nullptr, hh);

    // launch 6: ff1 = silu(h @ W1^T + bf1) -> fp16
    dim3 gF1(DFF / 128, NTOK / 128);
    gemm_h<1><<<gF1, 256, G_SMEM>>>(hh, w1h, bf1, nullptr, nullptr, f1h, DFF, DIM);

    // launch 7: out = ff1 @ W2^T + bf2 + xn
    dim3 gF2(DIM / 128, NTOK / 128);
    gemm_h<2><<<gF2, 256, G_SMEM>>>(f1h, w2h, bf2, xn, (float*)d_out, nullptr, DIM, DFF);
}